// round 9
// baseline (speedup 1.0000x reference)
#include <cuda_runtime.h>
#include <cuda_fp16.h>
#include <stdint.h>
#include <math.h>

#define N_NODES 10000
#define N_EDGES 320000

// ---------------- scratch (static device allocations) ----------------
__device__ __half g_C1[N_NODES * 512];   // fp16: x@(W1top-W1bot) + b1
__device__ __half g_D1[N_NODES * 512];   // fp16: x@W1bot
__device__ float  g_H1[N_NODES * 256];
__device__ __half g_C2[N_NODES * 256];
__device__ __half g_D2[N_NODES * 256];
__device__ float  g_H2[N_NODES * 128];
__device__ int    g_hist[N_NODES + 1];
__device__ int    g_cursor[N_NODES];
__device__ int    g_src_s[N_EDGES];
__device__ int    g_dst_s[N_EDGES];
// transposed fp16 weights (K-major [NOUT, K]) for edge second-layer GEMMs
__device__ __half g_WT1[256 * 512];
__device__ __half g_WT2[128 * 256];
// dual first-layer weights: rows [0,NOUT) = (Wtop-Wbot)^T, rows [NOUT,2NOUT) = Wbot^T
__device__ __half g_WTD1[1024 * 128];
__device__ __half g_WTD2[512 * 256];

// ---------------- helpers ----------------
__device__ __forceinline__ uint32_t smem_u32(const void* p) {
    uint32_t a;
    asm("{ .reg .u64 t; cvta.to.shared.u64 t, %1; cvt.u32.u64 %0, t; }" : "=r"(a) : "l"(p));
    return a;
}
__device__ __forceinline__ void mma_f16(float* c,
    uint32_t a0, uint32_t a1, uint32_t a2, uint32_t a3,
    uint32_t b0, uint32_t b1) {
    asm volatile(
        "mma.sync.aligned.m16n8k16.row.col.f32.f16.f16.f32 "
        "{%0,%1,%2,%3}, {%4,%5,%6,%7}, {%8,%9}, {%0,%1,%2,%3};"
        : "+f"(c[0]), "+f"(c[1]), "+f"(c[2]), "+f"(c[3])
        : "r"(a0), "r"(a1), "r"(a2), "r"(a3), "r"(b0), "r"(b1));
}
__device__ __forceinline__ uint32_t haddrelu2(uint32_t a, uint32_t b) {
    __half2 av = *reinterpret_cast<__half2*>(&a);
    __half2 bv = *reinterpret_cast<__half2*>(&b);
    __half2 r = __hmax2(__hadd2(av, bv), __float2half2_rn(0.f));
    return *reinterpret_cast<uint32_t*>(&r);
}
__device__ __forceinline__ void cp16(uint32_t dst, const void* src) {
    asm volatile("cp.async.ca.shared.global [%0], [%1], 16;" :: "r"(dst), "l"(src) : "memory");
}
__device__ __forceinline__ void cp_commit() {
    asm volatile("cp.async.commit_group;" ::: "memory");
}
__device__ __forceinline__ void cp_wait_all() {
    asm volatile("cp.async.wait_group 0;" ::: "memory");
}

// ---------------- init ----------------
__global__ void k_zero() {
    int stride = gridDim.x * blockDim.x;
    int i0 = blockIdx.x * blockDim.x + threadIdx.x;
    for (int j = i0; j < N_NODES * 256; j += stride) g_H1[j] = 0.f;
    for (int j = i0; j < N_NODES * 128; j += stride) g_H2[j] = 0.f;
    for (int j = i0; j <= N_NODES;      j += stride) g_hist[j] = 0;
    for (int j = i0; j < N_NODES;       j += stride) g_cursor[j] = 0;
}

// ---------------- counting sort by dst ----------------
__global__ void k_hist(const int* __restrict__ dst) {
    int e = blockIdx.x * blockDim.x + threadIdx.x;
    if (e < N_EDGES) atomicAdd(&g_hist[dst[e] + 1], 1);
}
__global__ void k_scan() {
    __shared__ int s[1024];
    __shared__ int carry;
    int tid = threadIdx.x;
    if (tid == 0) carry = 0;
    __syncthreads();
    for (int base = 0; base < N_NODES + 1; base += 1024) {
        int i = base + tid;
        int v = (i < N_NODES + 1) ? g_hist[i] : 0;
        s[tid] = v;
        __syncthreads();
        for (int off = 1; off < 1024; off <<= 1) {
            int t = (tid >= off) ? s[tid - off] : 0;
            __syncthreads();
            s[tid] += t;
            __syncthreads();
        }
        int out = s[tid] + carry;
        if (i < N_NODES + 1) g_hist[i] = out;
        __syncthreads();
        if (tid == 1023) carry = out;
        __syncthreads();
    }
}
__global__ void k_scatter(const int* __restrict__ src, const int* __restrict__ dst) {
    int e = blockIdx.x * blockDim.x + threadIdx.x;
    if (e < N_EDGES) {
        int d = dst[e];
        int pos = g_hist[d] + atomicAdd(&g_cursor[d], 1);
        g_src_s[pos] = src[e];
        g_dst_s[pos] = d;
    }
}

// ---------------- weight prep ----------------
template <int KW, int NOUT>
__global__ void k_prep(const float* __restrict__ W2, __half* __restrict__ WT) {
    int i = blockIdx.x * blockDim.x + threadIdx.x;
    if (i < KW * NOUT) {
        int n = i / KW, k = i % KW;
        WT[i] = __float2half_rn(W2[k * NOUT + n]);
    }
}
template <int K, int NOUT>
__global__ void k_prep_dual(const float* __restrict__ W1, __half* __restrict__ WT) {
    int i = blockIdx.x * blockDim.x + threadIdx.x;
    if (i < NOUT * K) {
        int n = i / K, k = i % K;
        float top = W1[k * NOUT + n];
        float bot = W1[(K + k) * NOUT + n];
        WT[(size_t)n * K + k] = __float2half_rn(top - bot);
        WT[(size_t)(NOUT + n) * K + k] = __float2half_rn(bot);
    }
}

// ---------------- node fp16 MMA GEMM: [C | D] = fp16(X) @ WTdual^T ----------------
#define NODE_SMEM 36864   // A@0 (128x144), B@18432 (128x144)

template <int K, int NOUT>
__global__ void __launch_bounds__(256, 2) k_node_mma(
    const float* __restrict__ X, const __half* __restrict__ WT,
    const float* __restrict__ b1, __half* __restrict__ C, __half* __restrict__ D)
{
    extern __shared__ char smem[];
    const int tid = threadIdx.x;
    const int wid = tid >> 5, lid = tid & 31;
    const int warp_m = wid & 3, warp_n = wid >> 2;
    const int gid = lid >> 2, tig = lid & 3;

    const int m0 = blockIdx.x * 128;
    const int n0 = blockIdx.y * 128;

    const int fm = tid >> 1;
    const int fk = (tid & 1) * 32;
    const int gm = m0 + fm;
    const bool valid = gm < N_NODES;
    const float* rowX = X + (size_t)(valid ? gm : 0) * K + fk;
    const __half* rowW = WT + (size_t)(n0 + fm) * K + fk;

    float acc[2][8][4];
#pragma unroll
    for (int a = 0; a < 2; ++a)
#pragma unroll
        for (int b = 0; b < 8; ++b)
#pragma unroll
            for (int c = 0; c < 4; ++c) acc[a][b][c] = 0.f;

    constexpr int NCH = K / 64;
#pragma unroll 1
    for (int ch = 0; ch < NCH; ++ch) {
        {
            const uint4* wp = (const uint4*)(rowW + ch * 64);
            uint4 w0 = wp[0], w1 = wp[1], w2 = wp[2], w3 = wp[3];
            char* pb = smem + 18432 + fm * 144 + fk * 2;
            *(uint4*)pb        = w0;
            *(uint4*)(pb + 16) = w1;
            *(uint4*)(pb + 32) = w2;
            *(uint4*)(pb + 48) = w3;
        }
        {
            char* pa = smem + fm * 144 + fk * 2;
#pragma unroll
            for (int q = 0; q < 4; ++q) {
                float4 x0 = make_float4(0.f, 0.f, 0.f, 0.f);
                float4 x1 = make_float4(0.f, 0.f, 0.f, 0.f);
                if (valid) {
                    x0 = *(const float4*)(rowX + ch * 64 + q * 8);
                    x1 = *(const float4*)(rowX + ch * 64 + q * 8 + 4);
                }
                __half2 h0 = __floats2half2_rn(x0.x, x0.y);
                __half2 h1 = __floats2half2_rn(x0.z, x0.w);
                __half2 h2 = __floats2half2_rn(x1.x, x1.y);
                __half2 h3 = __floats2half2_rn(x1.z, x1.w);
                *(uint4*)(pa + q * 16) = make_uint4(
                    *(uint32_t*)&h0, *(uint32_t*)&h1, *(uint32_t*)&h2, *(uint32_t*)&h3);
            }
        }
        __syncthreads();
#pragma unroll
        for (int ks = 0; ks < 4; ++ks) {
            const int koff = ks * 32 + tig * 4;
            uint32_t a[2][4];
#pragma unroll
            for (int mt = 0; mt < 2; ++mt) {
                int r = warp_m * 32 + mt * 16 + gid;
                const char* base = smem + r * 144;
                a[mt][0] = *(const uint32_t*)(base + koff);
                a[mt][1] = *(const uint32_t*)(base + 8 * 144 + koff);
                a[mt][2] = *(const uint32_t*)(base + koff + 16);
                a[mt][3] = *(const uint32_t*)(base + 8 * 144 + koff + 16);
            }
#pragma unroll
            for (int j = 0; j < 8; ++j) {
                int n = warp_n * 64 + j * 8 + gid;
                const char* bb = smem + 18432 + n * 144;
                uint32_t b0 = *(const uint32_t*)(bb + koff);
                uint32_t b1v = *(const uint32_t*)(bb + koff + 16);
                mma_f16(acc[0][j], a[0][0], a[0][1], a[0][2], a[0][3], b0, b1v);
                mma_f16(acc[1][j], a[1][0], a[1][1], a[1][2], a[1][3], b0, b1v);
            }
        }
        __syncthreads();
    }

    const bool isC = (n0 < NOUT);
    __half* OUT = isC ? C : D;
    const int cb = isC ? n0 : n0 - NOUT;
#pragma unroll
    for (int mt = 0; mt < 2; ++mt)
#pragma unroll
        for (int j = 0; j < 8; ++j) {
            int r = m0 + warp_m * 32 + mt * 16 + gid;
            int c = cb + warp_n * 64 + j * 8 + tig * 2;
            float bb0 = 0.f, bb1 = 0.f;
            if (isC) { bb0 = __ldg(b1 + c); bb1 = __ldg(b1 + c + 1); }
            if (r < N_NODES) {
                __half2 h = __floats2half2_rn(acc[mt][j][0] + bb0, acc[mt][j][1] + bb1);
                *(__half2*)&OUT[(size_t)r * NOUT + c] = h;
            }
            if (r + 8 < N_NODES) {
                __half2 h = __floats2half2_rn(acc[mt][j][2] + bb0, acc[mt][j][3] + bb1);
                *(__half2*)&OUT[(size_t)(r + 8) * NOUT + c] = h;
            }
        }
}

// ---------------- fp16 edge GEMM + segmented max (512 thr, 16 warps 4Mx4N) ----------------
// Tile 128 edges x 128 cols, K chunk 64. Warp tile 32x32 -> acc 32 regs/thread.
// A = relu(C16[dst]+D16[src]) from reg-prefetched gathers; B via cp.async double buffer.
#define SM_SDST 0
#define SM_SSRC 512
#define SM_A    1024
#define SM_B0   19456
#define SM_B1   37888
#define SM_STG  1024
#define EDGE_SMEM 56320

template <int KW, int NOUT>
__global__ void __launch_bounds__(512, 2) k_edge_mma(
    const __half* __restrict__ C, const __half* __restrict__ D,
    const __half* __restrict__ WT, const float* __restrict__ b2, float* __restrict__ AGG)
{
    extern __shared__ char smem[];
    const uint32_t sb = smem_u32(smem);
    const int tid = threadIdx.x;
    const int wid = tid >> 5, lid = tid & 31;
    const int warp_m = wid & 3, warp_n = wid >> 2;     // 4 x 4 warp grid
    const int gid = lid >> 2, tig = lid & 3;

    int* sdst = (int*)(smem + SM_SDST);
    int* ssrc = (int*)(smem + SM_SSRC);

    const int e0 = blockIdx.x * 128;
    const int n0 = blockIdx.y * 128;
    if (tid < 128) {
        sdst[tid] = g_dst_s[e0 + tid];
        ssrc[tid] = g_src_s[e0 + tid];
    }
    __syncthreads();

    // fill assignment: 4 threads per row, 16 halves (32B) each
    const int fm = tid >> 2;
    const int fq = (tid & 3) * 16;      // half-element offset within 64-chunk
    const __half* rowC = C + (size_t)sdst[fm] * KW + fq;
    const __half* rowD = D + (size_t)ssrc[fm] * KW + fq;
    const __half* rowW = WT + (size_t)(n0 + fm) * KW + fq;
    const uint32_t bdst0 = sb + SM_B0 + fm * 144 + fq * 2;
    const uint32_t bdst1 = sb + SM_B1 + fm * 144 + fq * 2;

    float acc[2][4][4];
#pragma unroll
    for (int a = 0; a < 2; ++a)
#pragma unroll
        for (int b = 0; b < 4; ++b)
#pragma unroll
            for (int c = 0; c < 4; ++c) acc[a][b][c] = 0.f;

    constexpr int NCH = KW / 64;
    uint4 pc[2], pd[2];
    {   // prologue: prefetch chunk-0 gathers + async B(0)
        const uint4* cp = (const uint4*)rowC;
        const uint4* dp = (const uint4*)rowD;
        pc[0] = cp[0]; pc[1] = cp[1];
        pd[0] = dp[0]; pd[1] = dp[1];
        cp16(bdst0,      rowW);
        cp16(bdst0 + 16, rowW + 8);
        cp_commit();
    }

#pragma unroll 1
    for (int ch = 0; ch < NCH; ++ch) {
        // ---- A tile: relu(C+D) from prefetched registers
        {
            uint4 ao[2];
#pragma unroll
            for (int q = 0; q < 2; ++q) {
                ao[q].x = haddrelu2(pc[q].x, pd[q].x);
                ao[q].y = haddrelu2(pc[q].y, pd[q].y);
                ao[q].z = haddrelu2(pc[q].z, pd[q].z);
                ao[q].w = haddrelu2(pc[q].w, pd[q].w);
            }
            char* pa = smem + SM_A + fm * 144 + fq * 2;
            *(uint4*)pa        = ao[0];
            *(uint4*)(pa + 16) = ao[1];
        }
        cp_wait_all();
        __syncthreads();

        // ---- prefetch next chunk: C/D -> regs, B -> other SMEM buffer (async)
        if (ch + 1 < NCH) {
            const uint4* cp = (const uint4*)(rowC + (ch + 1) * 64);
            const uint4* dp = (const uint4*)(rowD + (ch + 1) * 64);
            pc[0] = cp[0]; pc[1] = cp[1];
            pd[0] = dp[0]; pd[1] = dp[1];
            const __half* ws = rowW + (ch + 1) * 64;
            uint32_t bd = ((ch + 1) & 1) ? bdst1 : bdst0;
            cp16(bd,      ws);
            cp16(bd + 16, ws + 8);
            cp_commit();
        }

        // ---- 4 k-steps of 16 from A + B[ch&1]
        const char* Bbuf = smem + ((ch & 1) ? SM_B1 : SM_B0);
#pragma unroll
        for (int ks = 0; ks < 4; ++ks) {
            const int koff = ks * 32 + tig * 4;
            uint32_t a[2][4];
#pragma unroll
            for (int mt = 0; mt < 2; ++mt) {
                int r = warp_m * 32 + mt * 16 + gid;
                const char* base = smem + SM_A + r * 144;
                a[mt][0] = *(const uint32_t*)(base + koff);
                a[mt][1] = *(const uint32_t*)(base + 8 * 144 + koff);
                a[mt][2] = *(const uint32_t*)(base + koff + 16);
                a[mt][3] = *(const uint32_t*)(base + 8 * 144 + koff + 16);
            }
#pragma unroll
            for (int j = 0; j < 4; ++j) {
                int n = warp_n * 32 + j * 8 + gid;
                const char* bb = Bbuf + n * 144;
                uint32_t b0 = *(const uint32_t*)(bb + koff);
                uint32_t b1 = *(const uint32_t*)(bb + koff + 16);
                mma_f16(acc[0][j], a[0][0], a[0][1], a[0][2], a[0][3], b0, b1);
                mma_f16(acc[1][j], a[1][0], a[1][1], a[1][2], a[1][3], b0, b1);
            }
        }
        __syncthreads();
    }

    // ---- epilogue: stage 64 cols per pass, bias+relu, segmented max over sorted dst
    float* stage = (float*)(smem + SM_STG);
#pragma unroll 1
    for (int p = 0; p < 2; ++p) {
        if ((warp_n >> 1) == p) {
#pragma unroll
            for (int mt = 0; mt < 2; ++mt)
#pragma unroll
                for (int j = 0; j < 4; ++j) {
                    int r0 = warp_m * 32 + mt * 16 + gid;
                    int cw = (warp_n & 1) * 32 + j * 8 + tig * 2;
                    float* st = stage + r0 * 66 + cw;
                    st[0] = acc[mt][j][0];
                    st[1] = acc[mt][j][1];
                    st[66 * 8] = acc[mt][j][2];
                    st[66 * 8 + 1] = acc[mt][j][3];
                }
        }
        __syncthreads();
        {
            int colw = tid & 63;            // 64 cols
            int grp = tid >> 6;             // 8 groups x 16 rows
            int gcol = n0 + p * 64 + colw;
            float bias = b2[gcol];
            int prev = -1;
            float mx = 0.f;
#pragma unroll 4
            for (int r = grp * 16; r < grp * 16 + 16; ++r) {
                int d = sdst[r];
                float v = fmaxf(stage[r * 66 + colw] + bias, 0.f);
                if (d == prev) {
                    mx = fmaxf(mx, v);
                } else {
                    if (prev >= 0)
                        atomicMax((int*)&AGG[(size_t)prev * NOUT + gcol], __float_as_int(mx));
                    prev = d;
                    mx = v;
                }
            }
            atomicMax((int*)&AGG[(size_t)prev * NOUT + gcol], __float_as_int(mx));
        }
        __syncthreads();
    }
}

// ---------------- dense head ----------------
__global__ void k_head(const float* __restrict__ W3, const float* __restrict__ b3,
                       const float* __restrict__ W4, const float* __restrict__ b4,
                       float* __restrict__ out) {
    __shared__ float sh[128];
    __shared__ float red[2];
    int n = blockIdx.x;
    int t = threadIdx.x;   // 64 threads
    sh[t]      = g_H2[n * 128 + t];
    sh[t + 64] = g_H2[n * 128 + 64 + t];
    __syncthreads();
    float s = b3[t];
#pragma unroll 8
    for (int k = 0; k < 128; k++) s += sh[k] * W3[k * 64 + t];
    s = fmaxf(s, 0.f);
    float p = s * W4[t];
#pragma unroll
    for (int off = 16; off > 0; off >>= 1) p += __shfl_down_sync(0xffffffffu, p, off);
    if ((t & 31) == 0) red[t >> 5] = p;
    __syncthreads();
    if (t == 0) {
        float z = red[0] + red[1] + b4[0];
        out[n] = 1.f / (1.f + expf(-z));
    }
}

// ---------------- launch ----------------
extern "C" void kernel_launch(void* const* d_in, const int* in_sizes, int n_in,
                              void* d_out, int out_size) {
    const float* x   = (const float*)d_in[0];
    const int*   ei  = (const int*)d_in[1];
    const int*   src = ei;
    const int*   dst = ei + N_EDGES;
    const float* W1a = (const float*)d_in[2];
    const float* b1a = (const float*)d_in[3];
    const float* W2a = (const float*)d_in[4];
    const float* b2a = (const float*)d_in[5];
    const float* W1b = (const float*)d_in[6];
    const float* b1b = (const float*)d_in[7];
    const float* W2b = (const float*)d_in[8];
    const float* b2b = (const float*)d_in[9];
    const float* W3  = (const float*)d_in[10];
    const float* b3  = (const float*)d_in[11];
    const float* W4  = (const float*)d_in[12];
    const float* b4  = (const float*)d_in[13];
    float* out = (float*)d_out;

    void *pC1, *pD1, *pH1, *pC2, *pD2, *pH2, *pWT1, *pWT2, *pWTD1, *pWTD2;
    cudaGetSymbolAddress(&pC1, g_C1);
    cudaGetSymbolAddress(&pD1, g_D1);
    cudaGetSymbolAddress(&pH1, g_H1);
    cudaGetSymbolAddress(&pC2, g_C2);
    cudaGetSymbolAddress(&pD2, g_D2);
    cudaGetSymbolAddress(&pH2, g_H2);
    cudaGetSymbolAddress(&pWT1, g_WT1);
    cudaGetSymbolAddress(&pWT2, g_WT2);
    cudaGetSymbolAddress(&pWTD1, g_WTD1);
    cudaGetSymbolAddress(&pWTD2, g_WTD2);

    cudaFuncSetAttribute(k_edge_mma<512, 256>, cudaFuncAttributeMaxDynamicSharedMemorySize, EDGE_SMEM);
    cudaFuncSetAttribute(k_edge_mma<256, 128>, cudaFuncAttributeMaxDynamicSharedMemorySize, EDGE_SMEM);
    cudaFuncSetAttribute(k_node_mma<128, 512>, cudaFuncAttributeMaxDynamicSharedMemorySize, NODE_SMEM);
    cudaFuncSetAttribute(k_node_mma<256, 256>, cudaFuncAttributeMaxDynamicSharedMemorySize, NODE_SMEM);

    // init + counting sort
    k_zero<<<512, 256>>>();
    k_hist<<<(N_EDGES + 255) / 256, 256>>>(dst);
    k_scan<<<1, 1024>>>();
    k_scatter<<<(N_EDGES + 255) / 256, 256>>>(src, dst);

    // weight prep
    k_prep<512, 256><<<(512 * 256 + 255) / 256, 256>>>(W2a, (__half*)pWT1);
    k_prep<256, 128><<<(256 * 128 + 255) / 256, 256>>>(W2b, (__half*)pWT2);
    k_prep_dual<128, 512><<<(512 * 128 + 255) / 256, 256>>>(W1a, (__half*)pWTD1);
    k_prep_dual<256, 256><<<(256 * 256 + 255) / 256, 256>>>(W1b, (__half*)pWTD2);

    // layer 1
    {
        dim3 g((N_NODES + 127) / 128, 1024 / 128);
        k_node_mma<128, 512><<<g, 256, NODE_SMEM>>>(x, (const __half*)pWTD1, b1a,
                                                    (__half*)pC1, (__half*)pD1);
    }
    {
        dim3 g(N_EDGES / 128, 256 / 128);
        k_edge_mma<512, 256><<<g, 512, EDGE_SMEM>>>(
            (const __half*)pC1, (const __half*)pD1,
            (const __half*)pWT1, b2a, (float*)pH1);
    }

    // layer 2
    {
        dim3 g((N_NODES + 127) / 128, 512 / 128);
        k_node_mma<256, 256><<<g, 256, NODE_SMEM>>>((const float*)pH1, (const __half*)pWTD2, b1b,
                                                    (__half*)pC2, (__half*)pD2);
    }
    {
        dim3 g(N_EDGES / 128, 128 / 128);
        k_edge_mma<256, 128><<<g, 512, EDGE_SMEM>>>(
            (const __half*)pC2, (const __half*)pD2,
            (const __half*)pWT2, b2b, (float*)pH2);
    }

    // head
    k_head<<<N_NODES, 64>>>(W3, b3, W4, b4, out);
}

// round 10
// speedup vs baseline: 1.0820x; 1.0820x over previous
#include <cuda_runtime.h>
#include <cuda_fp16.h>
#include <stdint.h>
#include <math.h>

#define N_NODES 10000
#define N_EDGES 320000

// ---------------- scratch (static device allocations) ----------------
__device__ __half g_C1[N_NODES * 512];   // fp16: x@(W1top-W1bot) + b1
__device__ __half g_D1[N_NODES * 512];   // fp16: x@W1bot
__device__ float  g_H1[N_NODES * 256];
__device__ __half g_C2[N_NODES * 256];
__device__ __half g_D2[N_NODES * 256];
__device__ float  g_H2[N_NODES * 128];
__device__ int    g_hist[N_NODES + 1];
__device__ int    g_bsum[32];
__device__ int    g_cursor[N_NODES];
__device__ int    g_src_s[N_EDGES];
__device__ int    g_dst_s[N_EDGES];
__device__ __half g_WT1[256 * 512];
__device__ __half g_WT2[128 * 256];
__device__ __half g_WTD1[1024 * 128];
__device__ __half g_WTD2[512 * 256];

// ---------------- helpers ----------------
__device__ __forceinline__ uint32_t smem_u32(const void* p) {
    uint32_t a;
    asm("{ .reg .u64 t; cvta.to.shared.u64 t, %1; cvt.u32.u64 %0, t; }" : "=r"(a) : "l"(p));
    return a;
}
__device__ __forceinline__ void mma_f16(float* c,
    uint32_t a0, uint32_t a1, uint32_t a2, uint32_t a3,
    uint32_t b0, uint32_t b1) {
    asm volatile(
        "mma.sync.aligned.m16n8k16.row.col.f32.f16.f16.f32 "
        "{%0,%1,%2,%3}, {%4,%5,%6,%7}, {%8,%9}, {%0,%1,%2,%3};"
        : "+f"(c[0]), "+f"(c[1]), "+f"(c[2]), "+f"(c[3])
        : "r"(a0), "r"(a1), "r"(a2), "r"(a3), "r"(b0), "r"(b1));
}
__device__ __forceinline__ uint32_t haddrelu2(uint32_t a, uint32_t b) {
    __half2 av = *reinterpret_cast<__half2*>(&a);
    __half2 bv = *reinterpret_cast<__half2*>(&b);
    __half2 r = __hmax2(__hadd2(av, bv), __float2half2_rn(0.f));
    return *reinterpret_cast<uint32_t*>(&r);
}
__device__ __forceinline__ void cp16(uint32_t dst, const void* src) {
    asm volatile("cp.async.ca.shared.global [%0], [%1], 16;" :: "r"(dst), "l"(src) : "memory");
}
__device__ __forceinline__ void cp_commit() {
    asm volatile("cp.async.commit_group;" ::: "memory");
}
__device__ __forceinline__ void cp_wait_all() {
    asm volatile("cp.async.wait_group 0;" ::: "memory");
}

// ---------------- init ----------------
__global__ void k_zero() {
    int stride = gridDim.x * blockDim.x;
    int i0 = blockIdx.x * blockDim.x + threadIdx.x;
    for (int j = i0; j < N_NODES * 256; j += stride) g_H1[j] = 0.f;
    for (int j = i0; j < N_NODES * 128; j += stride) g_H2[j] = 0.f;
    for (int j = i0; j <= N_NODES;      j += stride) g_hist[j] = 0;
    for (int j = i0; j < N_NODES;       j += stride) g_cursor[j] = 0;
}

// ---------------- counting sort by dst (parallel scan) ----------------
__global__ void k_hist(const int* __restrict__ dst) {
    int e = blockIdx.x * blockDim.x + threadIdx.x;
    if (e < N_EDGES) atomicAdd(&g_hist[dst[e] + 1], 1);
}
__global__ void k_scan1() {   // grid 20 x 512: per-block inclusive scan
    __shared__ int s[512];
    int b = blockIdx.x, t = threadIdx.x;
    int i = b * 512 + t;
    int v = (i < N_NODES + 1) ? g_hist[i] : 0;
    s[t] = v;
    __syncthreads();
    for (int off = 1; off < 512; off <<= 1) {
        int u = (t >= off) ? s[t - off] : 0;
        __syncthreads();
        s[t] += u;
        __syncthreads();
    }
    if (i < N_NODES + 1) g_hist[i] = s[t];
    if (t == 511) g_bsum[b] = s[511];
}
__global__ void k_scan2() {   // 1 warp: scan block sums
    int t = threadIdx.x;
    int v = (t < 20) ? g_bsum[t] : 0;
    for (int off = 1; off < 32; off <<= 1) {
        int u = __shfl_up_sync(0xffffffffu, v, off);
        if (t >= off) v += u;
    }
    if (t < 20) g_bsum[t] = v;
}
__global__ void k_scan3() {   // grid 19 x 512: add offsets to blocks 1..19
    int b = blockIdx.x + 1, t = threadIdx.x;
    int i = b * 512 + t;
    if (i < N_NODES + 1) g_hist[i] += g_bsum[b - 1];
}
__global__ void k_scatter(const int* __restrict__ src, const int* __restrict__ dst) {
    int e = blockIdx.x * blockDim.x + threadIdx.x;
    if (e < N_EDGES) {
        int d = dst[e];
        int pos = g_hist[d] + atomicAdd(&g_cursor[d], 1);
        g_src_s[pos] = src[e];
        g_dst_s[pos] = d;
    }
}

// ---------------- weight prep ----------------
template <int KW, int NOUT>
__global__ void k_prep(const float* __restrict__ W2, __half* __restrict__ WT) {
    int i = blockIdx.x * blockDim.x + threadIdx.x;
    if (i < KW * NOUT) {
        int n = i / KW, k = i % KW;
        WT[i] = __float2half_rn(W2[k * NOUT + n]);
    }
}
template <int K, int NOUT>
__global__ void k_prep_dual(const float* __restrict__ W1, __half* __restrict__ WT) {
    int i = blockIdx.x * blockDim.x + threadIdx.x;
    if (i < NOUT * K) {
        int n = i / K, k = i % K;
        float top = W1[k * NOUT + n];
        float bot = W1[(K + k) * NOUT + n];
        WT[(size_t)n * K + k] = __float2half_rn(top - bot);
        WT[(size_t)(NOUT + n) * K + k] = __float2half_rn(bot);
    }
}

// ---------------- node fp16 MMA GEMM: [C | D] = fp16(X) @ WTdual^T ----------------
#define NODE_SMEM 36864

template <int K, int NOUT>
__global__ void __launch_bounds__(256, 2) k_node_mma(
    const float* __restrict__ X, const __half* __restrict__ WT,
    const float* __restrict__ b1, __half* __restrict__ C, __half* __restrict__ D)
{
    extern __shared__ char smem[];
    const int tid = threadIdx.x;
    const int wid = tid >> 5, lid = tid & 31;
    const int warp_m = wid & 3, warp_n = wid >> 2;
    const int gid = lid >> 2, tig = lid & 3;

    const int m0 = blockIdx.x * 128;
    const int n0 = blockIdx.y * 128;

    const int fm = tid >> 1;
    const int fk = (tid & 1) * 32;
    const int gm = m0 + fm;
    const bool valid = gm < N_NODES;
    const float* rowX = X + (size_t)(valid ? gm : 0) * K + fk;
    const __half* rowW = WT + (size_t)(n0 + fm) * K + fk;

    float acc[2][8][4];
#pragma unroll
    for (int a = 0; a < 2; ++a)
#pragma unroll
        for (int b = 0; b < 8; ++b)
#pragma unroll
            for (int c = 0; c < 4; ++c) acc[a][b][c] = 0.f;

    constexpr int NCH = K / 64;
#pragma unroll 1
    for (int ch = 0; ch < NCH; ++ch) {
        {
            const uint4* wp = (const uint4*)(rowW + ch * 64);
            uint4 w0 = wp[0], w1 = wp[1], w2 = wp[2], w3 = wp[3];
            char* pb = smem + 18432 + fm * 144 + fk * 2;
            *(uint4*)pb        = w0;
            *(uint4*)(pb + 16) = w1;
            *(uint4*)(pb + 32) = w2;
            *(uint4*)(pb + 48) = w3;
        }
        {
            char* pa = smem + fm * 144 + fk * 2;
#pragma unroll
            for (int q = 0; q < 4; ++q) {
                float4 x0 = make_float4(0.f, 0.f, 0.f, 0.f);
                float4 x1 = make_float4(0.f, 0.f, 0.f, 0.f);
                if (valid) {
                    x0 = *(const float4*)(rowX + ch * 64 + q * 8);
                    x1 = *(const float4*)(rowX + ch * 64 + q * 8 + 4);
                }
                __half2 h0 = __floats2half2_rn(x0.x, x0.y);
                __half2 h1 = __floats2half2_rn(x0.z, x0.w);
                __half2 h2 = __floats2half2_rn(x1.x, x1.y);
                __half2 h3 = __floats2half2_rn(x1.z, x1.w);
                *(uint4*)(pa + q * 16) = make_uint4(
                    *(uint32_t*)&h0, *(uint32_t*)&h1, *(uint32_t*)&h2, *(uint32_t*)&h3);
            }
        }
        __syncthreads();
#pragma unroll
        for (int ks = 0; ks < 4; ++ks) {
            const int koff = ks * 32 + tig * 4;
            uint32_t a[2][4];
#pragma unroll
            for (int mt = 0; mt < 2; ++mt) {
                int r = warp_m * 32 + mt * 16 + gid;
                const char* base = smem + r * 144;
                a[mt][0] = *(const uint32_t*)(base + koff);
                a[mt][1] = *(const uint32_t*)(base + 8 * 144 + koff);
                a[mt][2] = *(const uint32_t*)(base + koff + 16);
                a[mt][3] = *(const uint32_t*)(base + 8 * 144 + koff + 16);
            }
#pragma unroll
            for (int j = 0; j < 8; ++j) {
                int n = warp_n * 64 + j * 8 + gid;
                const char* bb = smem + 18432 + n * 144;
                uint32_t b0 = *(const uint32_t*)(bb + koff);
                uint32_t b1v = *(const uint32_t*)(bb + koff + 16);
                mma_f16(acc[0][j], a[0][0], a[0][1], a[0][2], a[0][3], b0, b1v);
                mma_f16(acc[1][j], a[1][0], a[1][1], a[1][2], a[1][3], b0, b1v);
            }
        }
        __syncthreads();
    }

    const bool isC = (n0 < NOUT);
    __half* OUT = isC ? C : D;
    const int cb = isC ? n0 : n0 - NOUT;
#pragma unroll
    for (int mt = 0; mt < 2; ++mt)
#pragma unroll
        for (int j = 0; j < 8; ++j) {
            int r = m0 + warp_m * 32 + mt * 16 + gid;
            int c = cb + warp_n * 64 + j * 8 + tig * 2;
            float bb0 = 0.f, bb1 = 0.f;
            if (isC) { bb0 = __ldg(b1 + c); bb1 = __ldg(b1 + c + 1); }
            if (r < N_NODES) {
                __half2 h = __floats2half2_rn(acc[mt][j][0] + bb0, acc[mt][j][1] + bb1);
                *(__half2*)&OUT[(size_t)r * NOUT + c] = h;
            }
            if (r + 8 < N_NODES) {
                __half2 h = __floats2half2_rn(acc[mt][j][2] + bb0, acc[mt][j][3] + bb1);
                *(__half2*)&OUT[(size_t)(r + 8) * NOUT + c] = h;
            }
        }
}

// ---------------- layer-2 edge GEMM (R8 config: 256 thr, tile 128x128) ----------------
#define SM_SDST 0
#define SM_SSRC 512
#define SM_A    1024
#define SM_B0   19456
#define SM_B1   37888
#define SM_STG  1024
#define EDGE_SMEM 56320

template <int KW, int NOUT>
__global__ void __launch_bounds__(256, 2) k_edge_mma(
    const __half* __restrict__ C, const __half* __restrict__ D,
    const __half* __restrict__ WT, const float* __restrict__ b2, float* __restrict__ AGG)
{
    extern __shared__ char smem[];
    const uint32_t sb = smem_u32(smem);
    const int tid = threadIdx.x;
    const int wid = tid >> 5, lid = tid & 31;
    const int warp_m = wid & 3, warp_n = wid >> 2;
    const int gid = lid >> 2, tig = lid & 3;

    int* sdst = (int*)(smem + SM_SDST);
    int* ssrc = (int*)(smem + SM_SSRC);

    const int e0 = blockIdx.x * 128;
    const int n0 = blockIdx.y * 128;
    if (tid < 128) {
        sdst[tid] = g_dst_s[e0 + tid];
        ssrc[tid] = g_src_s[e0 + tid];
    }
    __syncthreads();

    const int fm = tid >> 1;
    const int fk = (tid & 1) * 32;
    const __half* rowC = C + (size_t)sdst[fm] * KW + fk;
    const __half* rowD = D + (size_t)ssrc[fm] * KW + fk;
    const __half* rowW = WT + (size_t)(n0 + fm) * KW + fk;
    const uint32_t bdst0 = sb + SM_B0 + fm * 144 + fk * 2;
    const uint32_t bdst1 = sb + SM_B1 + fm * 144 + fk * 2;

    float acc[2][8][4];
#pragma unroll
    for (int a = 0; a < 2; ++a)
#pragma unroll
        for (int b = 0; b < 8; ++b)
#pragma unroll
            for (int c = 0; c < 4; ++c) acc[a][b][c] = 0.f;

    constexpr int NCH = KW / 64;
    uint4 pc[4], pd[4];
    {
        const uint4* cp = (const uint4*)rowC;
        const uint4* dp = (const uint4*)rowD;
#pragma unroll
        for (int q = 0; q < 4; ++q) { pc[q] = cp[q]; pd[q] = dp[q]; }
        cp16(bdst0,      rowW);
        cp16(bdst0 + 16, rowW + 8);
        cp16(bdst0 + 32, rowW + 16);
        cp16(bdst0 + 48, rowW + 24);
        cp_commit();
    }

#pragma unroll 1
    for (int ch = 0; ch < NCH; ++ch) {
        {
            uint4 ao[4];
#pragma unroll
            for (int q = 0; q < 4; ++q) {
                ao[q].x = haddrelu2(pc[q].x, pd[q].x);
                ao[q].y = haddrelu2(pc[q].y, pd[q].y);
                ao[q].z = haddrelu2(pc[q].z, pd[q].z);
                ao[q].w = haddrelu2(pc[q].w, pd[q].w);
            }
            char* pa = smem + SM_A + fm * 144 + fk * 2;
            *(uint4*)pa        = ao[0];
            *(uint4*)(pa + 16) = ao[1];
            *(uint4*)(pa + 32) = ao[2];
            *(uint4*)(pa + 48) = ao[3];
        }
        cp_wait_all();
        __syncthreads();

        if (ch + 1 < NCH) {
            const uint4* cp = (const uint4*)(rowC + (ch + 1) * 64);
            const uint4* dp = (const uint4*)(rowD + (ch + 1) * 64);
#pragma unroll
            for (int q = 0; q < 4; ++q) { pc[q] = cp[q]; pd[q] = dp[q]; }
            const __half* ws = rowW + (ch + 1) * 64;
            uint32_t bd = ((ch + 1) & 1) ? bdst1 : bdst0;
            cp16(bd,      ws);
            cp16(bd + 16, ws + 8);
            cp16(bd + 32, ws + 16);
            cp16(bd + 48, ws + 24);
            cp_commit();
        }

        const char* Bbuf = smem + ((ch & 1) ? SM_B1 : SM_B0);
#pragma unroll
        for (int ks = 0; ks < 4; ++ks) {
            const int koff = ks * 32 + tig * 4;
            uint32_t a[2][4];
#pragma unroll
            for (int mt = 0; mt < 2; ++mt) {
                int r = warp_m * 32 + mt * 16 + gid;
                const char* base = smem + SM_A + r * 144;
                a[mt][0] = *(const uint32_t*)(base + koff);
                a[mt][1] = *(const uint32_t*)(base + 8 * 144 + koff);
                a[mt][2] = *(const uint32_t*)(base + koff + 16);
                a[mt][3] = *(const uint32_t*)(base + 8 * 144 + koff + 16);
            }
#pragma unroll
            for (int j = 0; j < 8; ++j) {
                int n = warp_n * 64 + j * 8 + gid;
                const char* bb = Bbuf + n * 144;
                uint32_t b0 = *(const uint32_t*)(bb + koff);
                uint32_t b1 = *(const uint32_t*)(bb + koff + 16);
                mma_f16(acc[0][j], a[0][0], a[0][1], a[0][2], a[0][3], b0, b1);
                mma_f16(acc[1][j], a[1][0], a[1][1], a[1][2], a[1][3], b0, b1);
            }
        }
        __syncthreads();
    }

    float* stage = (float*)(smem + SM_STG);
#pragma unroll 1
    for (int p = 0; p < 2; ++p) {
        if (warp_n == p) {
#pragma unroll
            for (int mt = 0; mt < 2; ++mt)
#pragma unroll
                for (int j = 0; j < 8; ++j) {
                    int r0 = warp_m * 32 + mt * 16 + gid;
                    int cw = j * 8 + tig * 2;
                    float* st = stage + r0 * 66 + cw;
                    st[0] = acc[mt][j][0];
                    st[1] = acc[mt][j][1];
                    st[66 * 8] = acc[mt][j][2];
                    st[66 * 8 + 1] = acc[mt][j][3];
                }
        }
        __syncthreads();
        {
            int colw = tid & 63;
            int grp = tid >> 6;
            int gcol = n0 + p * 64 + colw;
            float bias = b2[gcol];
            int prev = -1;
            float mx = 0.f;
#pragma unroll 4
            for (int r = grp * 32; r < grp * 32 + 32; ++r) {
                int d = sdst[r];
                float v = fmaxf(stage[r * 66 + colw] + bias, 0.f);
                if (d == prev) {
                    mx = fmaxf(mx, v);
                } else {
                    if (prev >= 0)
                        atomicMax((int*)&AGG[(size_t)prev * NOUT + gcol], __float_as_int(mx));
                    prev = d;
                    mx = v;
                }
            }
            atomicMax((int*)&AGG[(size_t)prev * NOUT + gcol], __float_as_int(mx));
        }
        __syncthreads();
    }
}

// ---------------- layer-1 edge GEMM: 512 thr, tile 128 edges x 256 cols ----------------
// Warp grid 4M x 4N, warp tile 32x64 (same MMA:LDS density as R8).
// Single pass over N=256 -> C/D gathered once per edge tile.
// SMEM: sdst@0, ssrc@512, A@1024 (128x144=18432), B0@19456 (256x144=36864), B1@56320.
#define WEDGE_SMEM 93184

template <int KW, int NOUT>
__global__ void __launch_bounds__(512, 1) k_edge_wide(
    const __half* __restrict__ C, const __half* __restrict__ D,
    const __half* __restrict__ WT, const float* __restrict__ b2, float* __restrict__ AGG)
{
    extern __shared__ char smem[];
    const uint32_t sb = smem_u32(smem);
    const int tid = threadIdx.x;
    const int wid = tid >> 5, lid = tid & 31;
    const int warp_m = wid & 3, warp_n = wid >> 2;   // 4 x 4
    const int gid = lid >> 2, tig = lid & 3;

    int* sdst = (int*)(smem + SM_SDST);
    int* ssrc = (int*)(smem + SM_SSRC);

    const int e0 = blockIdx.x * 128;
    if (tid < 128) {
        sdst[tid] = g_dst_s[e0 + tid];
        ssrc[tid] = g_src_s[e0 + tid];
    }
    __syncthreads();

    // A fill: 4 threads/row, 16 halves each.  B fill: 2 threads/row (256 rows), 32 halves each.
    const int fm = tid >> 2;
    const int fq = (tid & 3) * 16;
    const int wm = tid >> 1;
    const int wq = (tid & 1) * 32;
    const __half* rowC = C + (size_t)sdst[fm] * KW + fq;
    const __half* rowD = D + (size_t)ssrc[fm] * KW + fq;
    const __half* rowW = WT + (size_t)wm * KW + wq;
    const uint32_t bdst0 = sb + SM_B0 + wm * 144 + wq * 2;
    const uint32_t bdst1 = sb + SM_B0 + 36864 + wm * 144 + wq * 2;

    float acc[2][8][4];
#pragma unroll
    for (int a = 0; a < 2; ++a)
#pragma unroll
        for (int b = 0; b < 8; ++b)
#pragma unroll
            for (int c = 0; c < 4; ++c) acc[a][b][c] = 0.f;

    constexpr int NCH = KW / 64;
    uint4 pc[2], pd[2];
    {
        const uint4* cp = (const uint4*)rowC;
        const uint4* dp = (const uint4*)rowD;
        pc[0] = cp[0]; pc[1] = cp[1];
        pd[0] = dp[0]; pd[1] = dp[1];
        cp16(bdst0,      rowW);
        cp16(bdst0 + 16, rowW + 8);
        cp16(bdst0 + 32, rowW + 16);
        cp16(bdst0 + 48, rowW + 24);
        cp_commit();
    }

#pragma unroll 1
    for (int ch = 0; ch < NCH; ++ch) {
        {
            uint4 ao[2];
#pragma unroll
            for (int q = 0; q < 2; ++q) {
                ao[q].x = haddrelu2(pc[q].x, pd[q].x);
                ao[q].y = haddrelu2(pc[q].y, pd[q].y);
                ao[q].z = haddrelu2(pc[q].z, pd[q].z);
                ao[q].w = haddrelu2(pc[q].w, pd[q].w);
            }
            char* pa = smem + SM_A + fm * 144 + fq * 2;
            *(uint4*)pa        = ao[0];
            *(uint4*)(pa + 16) = ao[1];
        }
        cp_wait_all();
        __syncthreads();

        if (ch + 1 < NCH) {
            const uint4* cp = (const uint4*)(rowC + (ch + 1) * 64);
            const uint4* dp = (const uint4*)(rowD + (ch + 1) * 64);
            pc[0] = cp[0]; pc[1] = cp[1];
            pd[0] = dp[0]; pd[1] = dp[1];
            const __half* ws = rowW + (ch + 1) * 64;
            uint32_t bd = ((ch + 1) & 1) ? bdst1 : bdst0;
            cp16(bd,      ws);
            cp16(bd + 16, ws + 8);
            cp16(bd + 32, ws + 16);
            cp16(bd + 48, ws + 24);
            cp_commit();
        }

        const char* Bbuf = smem + SM_B0 + ((ch & 1) ? 36864 : 0);
#pragma unroll
        for (int ks = 0; ks < 4; ++ks) {
            const int koff = ks * 32 + tig * 4;
            uint32_t a[2][4];
#pragma unroll
            for (int mt = 0; mt < 2; ++mt) {
                int r = warp_m * 32 + mt * 16 + gid;
                const char* base = smem + SM_A + r * 144;
                a[mt][0] = *(const uint32_t*)(base + koff);
                a[mt][1] = *(const uint32_t*)(base + 8 * 144 + koff);
                a[mt][2] = *(const uint32_t*)(base + koff + 16);
                a[mt][3] = *(const uint32_t*)(base + 8 * 144 + koff + 16);
            }
#pragma unroll
            for (int j = 0; j < 8; ++j) {
                int n = warp_n * 64 + j * 8 + gid;
                const char* bb = Bbuf + n * 144;
                uint32_t b0 = *(const uint32_t*)(bb + koff);
                uint32_t b1 = *(const uint32_t*)(bb + koff + 16);
                mma_f16(acc[0][j], a[0][0], a[0][1], a[0][2], a[0][3], b0, b1);
                mma_f16(acc[1][j], a[1][0], a[1][1], a[1][2], a[1][3], b0, b1);
            }
        }
        __syncthreads();
    }

    // epilogue: 4 passes of 64 cols (warp_n == p stages its columns)
    float* stage = (float*)(smem + SM_STG);
#pragma unroll 1
    for (int p = 0; p < 4; ++p) {
        if (warp_n == p) {
#pragma unroll
            for (int mt = 0; mt < 2; ++mt)
#pragma unroll
                for (int j = 0; j < 8; ++j) {
                    int r0 = warp_m * 32 + mt * 16 + gid;
                    int cw = j * 8 + tig * 2;
                    float* st = stage + r0 * 66 + cw;
                    st[0] = acc[mt][j][0];
                    st[1] = acc[mt][j][1];
                    st[66 * 8] = acc[mt][j][2];
                    st[66 * 8 + 1] = acc[mt][j][3];
                }
        }
        __syncthreads();
        {
            int colw = tid & 63;            // 64 cols
            int grp = tid >> 6;             // 8 groups x 16 rows
            int gcol = p * 64 + colw;
            float bias = b2[gcol];
            int prev = -1;
            float mx = 0.f;
#pragma unroll 4
            for (int r = grp * 16; r < grp * 16 + 16; ++r) {
                int d = sdst[r];
                float v = fmaxf(stage[r * 66 + colw] + bias, 0.f);
                if (d == prev) {
                    mx = fmaxf(mx, v);
                } else {
                    if (prev >= 0)
                        atomicMax((int*)&AGG[(size_t)prev * NOUT + gcol], __float_as_int(mx));
                    prev = d;
                    mx = v;
                }
            }
            atomicMax((int*)&AGG[(size_t)prev * NOUT + gcol], __float_as_int(mx));
        }
        __syncthreads();
    }
}

// ---------------- dense head ----------------
__global__ void k_head(const float* __restrict__ W3, const float* __restrict__ b3,
                       const float* __restrict__ W4, const float* __restrict__ b4,
                       float* __restrict__ out) {
    __shared__ float sh[128];
    __shared__ float red[2];
    int n = blockIdx.x;
    int t = threadIdx.x;   // 64 threads
    sh[t]      = g_H2[n * 128 + t];
    sh[t + 64] = g_H2[n * 128 + 64 + t];
    __syncthreads();
    float s = b3[t];
#pragma unroll 8
    for (int k = 0; k < 128; k++) s += sh[k] * W3[k * 64 + t];
    s = fmaxf(s, 0.f);
    float p = s * W4[t];
#pragma unroll
    for (int off = 16; off > 0; off >>= 1) p += __shfl_down_sync(0xffffffffu, p, off);
    if ((t & 31) == 0) red[t >> 5] = p;
    __syncthreads();
    if (t == 0) {
        float z = red[0] + red[1] + b4[0];
        out[n] = 1.f / (1.f + expf(-z));
    }
}

// ---------------- launch ----------------
extern "C" void kernel_launch(void* const* d_in, const int* in_sizes, int n_in,
                              void* d_out, int out_size) {
    const float* x   = (const float*)d_in[0];
    const int*   ei  = (const int*)d_in[1];
    const int*   src = ei;
    const int*   dst = ei + N_EDGES;
    const float* W1a = (const float*)d_in[2];
    const float* b1a = (const float*)d_in[3];
    const float* W2a = (const float*)d_in[4];
    const float* b2a = (const float*)d_in[5];
    const float* W1b = (const float*)d_in[6];
    const float* b1b = (const float*)d_in[7];
    const float* W2b = (const float*)d_in[8];
    const float* b2b = (const float*)d_in[9];
    const float* W3  = (const float*)d_in[10];
    const float* b3  = (const float*)d_in[11];
    const float* W4  = (const float*)d_in[12];
    const float* b4  = (const float*)d_in[13];
    float* out = (float*)d_out;

    void *pC1, *pD1, *pH1, *pC2, *pD2, *pH2, *pWT1, *pWT2, *pWTD1, *pWTD2;
    cudaGetSymbolAddress(&pC1, g_C1);
    cudaGetSymbolAddress(&pD1, g_D1);
    cudaGetSymbolAddress(&pH1, g_H1);
    cudaGetSymbolAddress(&pC2, g_C2);
    cudaGetSymbolAddress(&pD2, g_D2);
    cudaGetSymbolAddress(&pH2, g_H2);
    cudaGetSymbolAddress(&pWT1, g_WT1);
    cudaGetSymbolAddress(&pWT2, g_WT2);
    cudaGetSymbolAddress(&pWTD1, g_WTD1);
    cudaGetSymbolAddress(&pWTD2, g_WTD2);

    cudaFuncSetAttribute(k_edge_wide<512, 256>, cudaFuncAttributeMaxDynamicSharedMemorySize, WEDGE_SMEM);
    cudaFuncSetAttribute(k_edge_mma<256, 128>, cudaFuncAttributeMaxDynamicSharedMemorySize, EDGE_SMEM);
    cudaFuncSetAttribute(k_node_mma<128, 512>, cudaFuncAttributeMaxDynamicSharedMemorySize, NODE_SMEM);
    cudaFuncSetAttribute(k_node_mma<256, 256>, cudaFuncAttributeMaxDynamicSharedMemorySize, NODE_SMEM);

    // init + counting sort (parallel scan)
    k_zero<<<512, 256>>>();
    k_hist<<<(N_EDGES + 255) / 256, 256>>>(dst);
    k_scan1<<<20, 512>>>();
    k_scan2<<<1, 32>>>();
    k_scan3<<<19, 512>>>();
    k_scatter<<<(N_EDGES + 255) / 256, 256>>>(src, dst);

    // weight prep
    k_prep<512, 256><<<(512 * 256 + 255) / 256, 256>>>(W2a, (__half*)pWT1);
    k_prep<256, 128><<<(256 * 128 + 255) / 256, 256>>>(W2b, (__half*)pWT2);
    k_prep_dual<128, 512><<<(512 * 128 + 255) / 256, 256>>>(W1a, (__half*)pWTD1);
    k_prep_dual<256, 256><<<(256 * 256 + 255) / 256, 256>>>(W1b, (__half*)pWTD2);

    // layer 1
    {
        dim3 g((N_NODES + 127) / 128, 1024 / 128);
        k_node_mma<128, 512><<<g, 256, NODE_SMEM>>>(x, (const __half*)pWTD1, b1a,
                                                    (__half*)pC1, (__half*)pD1);
    }
    k_edge_wide<512, 256><<<N_EDGES / 128, 512, WEDGE_SMEM>>>(
        (const __half*)pC1, (const __half*)pD1,
        (const __half*)pWT1, b2a, (float*)pH1);

    // layer 2
    {
        dim3 g((N_NODES + 127) / 128, 512 / 128);
        k_node_mma<256, 256><<<g, 256, NODE_SMEM>>>((const float*)pH1, (const __half*)pWTD2, b1b,
                                                    (__half*)pC2, (__half*)pD2);
    }
    {
        dim3 g(N_EDGES / 128, 128 / 128);
        k_edge_mma<256, 128><<<g, 256, EDGE_SMEM>>>(
            (const __half*)pC2, (const __half*)pD2,
            (const __half*)pWT2, b2b, (float*)pH2);
    }

    // head
    k_head<<<N_NODES, 64>>>(W3, b3, W4, b4, out);
}

// round 11
// speedup vs baseline: 1.0919x; 1.0092x over previous
#include <cuda_runtime.h>
#include <cuda_fp16.h>
#include <stdint.h>
#include <math.h>

#define N_NODES 10000
#define N_EDGES 320000

// ---------------- scratch (static device allocations) ----------------
__device__ __half g_C1[N_NODES * 512];   // fp16: x@(W1top-W1bot) + b1
__device__ __half g_D1[N_NODES * 512];   // fp16: x@W1bot
__device__ float  g_H1[N_NODES * 256];
__device__ __half g_C2[N_NODES * 256];
__device__ __half g_D2[N_NODES * 256];
__device__ float  g_H2[N_NODES * 128];
__device__ int    g_hist[N_NODES + 1];
__device__ int    g_bsum[32];
__device__ int    g_cursor[N_NODES];
__device__ int    g_src_s[N_EDGES];
__device__ int    g_dst_s[N_EDGES];
__device__ __half g_WT1[256 * 512];
__device__ __half g_WT2[128 * 256];
__device__ __half g_WTD1[1024 * 128];
__device__ __half g_WTD2[512 * 256];

// ---------------- helpers ----------------
__device__ __forceinline__ uint32_t smem_u32(const void* p) {
    uint32_t a;
    asm("{ .reg .u64 t; cvta.to.shared.u64 t, %1; cvt.u32.u64 %0, t; }" : "=r"(a) : "l"(p));
    return a;
}
__device__ __forceinline__ void mma_f16(float* c,
    uint32_t a0, uint32_t a1, uint32_t a2, uint32_t a3,
    uint32_t b0, uint32_t b1) {
    asm volatile(
        "mma.sync.aligned.m16n8k16.row.col.f32.f16.f16.f32 "
        "{%0,%1,%2,%3}, {%4,%5,%6,%7}, {%8,%9}, {%0,%1,%2,%3};"
        : "+f"(c[0]), "+f"(c[1]), "+f"(c[2]), "+f"(c[3])
        : "r"(a0), "r"(a1), "r"(a2), "r"(a3), "r"(b0), "r"(b1));
}
__device__ __forceinline__ uint32_t haddrelu2(uint32_t a, uint32_t b) {
    __half2 av = *reinterpret_cast<__half2*>(&a);
    __half2 bv = *reinterpret_cast<__half2*>(&b);
    __half2 r = __hmax2(__hadd2(av, bv), __float2half2_rn(0.f));
    return *reinterpret_cast<uint32_t*>(&r);
}
__device__ __forceinline__ void cp16(uint32_t dst, const void* src) {
    asm volatile("cp.async.ca.shared.global [%0], [%1], 16;" :: "r"(dst), "l"(src) : "memory");
}
__device__ __forceinline__ void cp_commit() {
    asm volatile("cp.async.commit_group;" ::: "memory");
}
__device__ __forceinline__ void cp_wait_all() {
    asm volatile("cp.async.wait_group 0;" ::: "memory");
}

// ---------------- init (zero only; must precede atomics in k_setup) ----------------
__global__ void k_zero() {
    int stride = gridDim.x * blockDim.x;
    int i0 = blockIdx.x * blockDim.x + threadIdx.x;
    float4 z4 = make_float4(0.f, 0.f, 0.f, 0.f);
    for (int j = i0; j < N_NODES * 64; j += stride) ((float4*)g_H1)[j] = z4;
    for (int j = i0; j < N_NODES * 32; j += stride) ((float4*)g_H2)[j] = z4;
    for (int j = i0; j <= N_NODES;     j += stride) g_hist[j] = 0;
    for (int j = i0; j < N_NODES;      j += stride) g_cursor[j] = 0;
}

// ---------------- fused setup: histogram + all weight preps ----------------
// ranges: [0,320000) hist | [320000,451072) WT1 | [451072,483840) WT2
//         [483840,549376) WTD1 | [549376,614912) WTD2
__global__ void k_setup(const int* __restrict__ dst,
                        const float* __restrict__ W2a, const float* __restrict__ W2b,
                        const float* __restrict__ W1a, const float* __restrict__ W1b) {
    int i = blockIdx.x * blockDim.x + threadIdx.x;
    if (i < 320000) {
        atomicAdd(&g_hist[dst[i] + 1], 1);
    } else if (i < 451072) {
        int i2 = i - 320000;                 // WT1: [256,512] K-major from W2a [512,256]
        int n = i2 >> 9, k = i2 & 511;
        g_WT1[i2] = __float2half_rn(W2a[k * 256 + n]);
    } else if (i < 483840) {
        int i2 = i - 451072;                 // WT2: [128,256] from W2b [256,128]
        int n = i2 >> 8, k = i2 & 255;
        g_WT2[i2] = __float2half_rn(W2b[k * 128 + n]);
    } else if (i < 549376) {
        int i2 = i - 483840;                 // WTD1: dual [1024,128] from W1a [256,512]
        int n = i2 >> 7, k = i2 & 127;
        float top = W1a[k * 512 + n];
        float bot = W1a[(128 + k) * 512 + n];
        g_WTD1[n * 128 + k] = __float2half_rn(top - bot);
        g_WTD1[(512 + n) * 128 + k] = __float2half_rn(bot);
    } else if (i < 614912) {
        int i2 = i - 549376;                 // WTD2: dual [512,256] from W1b [512,256]
        int n = i2 >> 8, k = i2 & 255;
        float top = W1b[k * 256 + n];
        float bot = W1b[(256 + k) * 256 + n];
        g_WTD2[n * 256 + k] = __float2half_rn(top - bot);
        g_WTD2[(256 + n) * 256 + k] = __float2half_rn(bot);
    }
}

// ---------------- counting-sort scan (2 kernels) + scatter ----------------
__global__ void k_scan1() {   // grid 20 x 512: per-block inclusive scan
    __shared__ int s[512];
    int b = blockIdx.x, t = threadIdx.x;
    int i = b * 512 + t;
    int v = (i < N_NODES + 1) ? g_hist[i] : 0;
    s[t] = v;
    __syncthreads();
    for (int off = 1; off < 512; off <<= 1) {
        int u = (t >= off) ? s[t - off] : 0;
        __syncthreads();
        s[t] += u;
        __syncthreads();
    }
    if (i < N_NODES + 1) g_hist[i] = s[t];
    if (t == 511) g_bsum[b] = s[511];
}
__global__ void k_scan23() {  // grid 20 x 512: each block adds its exclusive bsum prefix
    __shared__ int soff;
    int b = blockIdx.x, t = threadIdx.x;
    if (t < 32) {
        int v = (t < b) ? g_bsum[t] : 0;
#pragma unroll
        for (int off = 16; off > 0; off >>= 1)
            v += __shfl_down_sync(0xffffffffu, v, off);
        if (t == 0) soff = v;
    }
    __syncthreads();
    int i = b * 512 + t;
    if (i < N_NODES + 1) g_hist[i] += soff;
}
__global__ void k_scatter(const int* __restrict__ src, const int* __restrict__ dst) {
    int e = blockIdx.x * blockDim.x + threadIdx.x;
    if (e < N_EDGES) {
        int d = dst[e];
        int pos = g_hist[d] + atomicAdd(&g_cursor[d], 1);
        g_src_s[pos] = src[e];
        g_dst_s[pos] = d;
    }
}

// ---------------- node fp16 MMA GEMM: [C | D] = fp16(X) @ WTdual^T ----------------
#define NODE_SMEM 36864

template <int K, int NOUT>
__global__ void __launch_bounds__(256, 2) k_node_mma(
    const float* __restrict__ X, const __half* __restrict__ WT,
    const float* __restrict__ b1, __half* __restrict__ C, __half* __restrict__ D)
{
    extern __shared__ char smem[];
    const int tid = threadIdx.x;
    const int wid = tid >> 5, lid = tid & 31;
    const int warp_m = wid & 3, warp_n = wid >> 2;
    const int gid = lid >> 2, tig = lid & 3;

    const int m0 = blockIdx.x * 128;
    const int n0 = blockIdx.y * 128;

    const int fm = tid >> 1;
    const int fk = (tid & 1) * 32;
    const int gm = m0 + fm;
    const bool valid = gm < N_NODES;
    const float* rowX = X + (size_t)(valid ? gm : 0) * K + fk;
    const __half* rowW = WT + (size_t)(n0 + fm) * K + fk;

    float acc[2][8][4];
#pragma unroll
    for (int a = 0; a < 2; ++a)
#pragma unroll
        for (int b = 0; b < 8; ++b)
#pragma unroll
            for (int c = 0; c < 4; ++c) acc[a][b][c] = 0.f;

    constexpr int NCH = K / 64;
#pragma unroll 1
    for (int ch = 0; ch < NCH; ++ch) {
        {
            const uint4* wp = (const uint4*)(rowW + ch * 64);
            uint4 w0 = wp[0], w1 = wp[1], w2 = wp[2], w3 = wp[3];
            char* pb = smem + 18432 + fm * 144 + fk * 2;
            *(uint4*)pb        = w0;
            *(uint4*)(pb + 16) = w1;
            *(uint4*)(pb + 32) = w2;
            *(uint4*)(pb + 48) = w3;
        }
        {
            char* pa = smem + fm * 144 + fk * 2;
#pragma unroll
            for (int q = 0; q < 4; ++q) {
                float4 x0 = make_float4(0.f, 0.f, 0.f, 0.f);
                float4 x1 = make_float4(0.f, 0.f, 0.f, 0.f);
                if (valid) {
                    x0 = *(const float4*)(rowX + ch * 64 + q * 8);
                    x1 = *(const float4*)(rowX + ch * 64 + q * 8 + 4);
                }
                __half2 h0 = __floats2half2_rn(x0.x, x0.y);
                __half2 h1 = __floats2half2_rn(x0.z, x0.w);
                __half2 h2 = __floats2half2_rn(x1.x, x1.y);
                __half2 h3 = __floats2half2_rn(x1.z, x1.w);
                *(uint4*)(pa + q * 16) = make_uint4(
                    *(uint32_t*)&h0, *(uint32_t*)&h1, *(uint32_t*)&h2, *(uint32_t*)&h3);
            }
        }
        __syncthreads();
#pragma unroll
        for (int ks = 0; ks < 4; ++ks) {
            const int koff = ks * 32 + tig * 4;
            uint32_t a[2][4];
#pragma unroll
            for (int mt = 0; mt < 2; ++mt) {
                int r = warp_m * 32 + mt * 16 + gid;
                const char* base = smem + r * 144;
                a[mt][0] = *(const uint32_t*)(base + koff);
                a[mt][1] = *(const uint32_t*)(base + 8 * 144 + koff);
                a[mt][2] = *(const uint32_t*)(base + koff + 16);
                a[mt][3] = *(const uint32_t*)(base + 8 * 144 + koff + 16);
            }
#pragma unroll
            for (int j = 0; j < 8; ++j) {
                int n = warp_n * 64 + j * 8 + gid;
                const char* bb = smem + 18432 + n * 144;
                uint32_t b0 = *(const uint32_t*)(bb + koff);
                uint32_t b1v = *(const uint32_t*)(bb + koff + 16);
                mma_f16(acc[0][j], a[0][0], a[0][1], a[0][2], a[0][3], b0, b1v);
                mma_f16(acc[1][j], a[1][0], a[1][1], a[1][2], a[1][3], b0, b1v);
            }
        }
        __syncthreads();
    }

    const bool isC = (n0 < NOUT);
    __half* OUT = isC ? C : D;
    const int cb = isC ? n0 : n0 - NOUT;
#pragma unroll
    for (int mt = 0; mt < 2; ++mt)
#pragma unroll
        for (int j = 0; j < 8; ++j) {
            int r = m0 + warp_m * 32 + mt * 16 + gid;
            int c = cb + warp_n * 64 + j * 8 + tig * 2;
            float bb0 = 0.f, bb1 = 0.f;
            if (isC) { bb0 = __ldg(b1 + c); bb1 = __ldg(b1 + c + 1); }
            if (r < N_NODES) {
                __half2 h = __floats2half2_rn(acc[mt][j][0] + bb0, acc[mt][j][1] + bb1);
                *(__half2*)&OUT[(size_t)r * NOUT + c] = h;
            }
            if (r + 8 < N_NODES) {
                __half2 h = __floats2half2_rn(acc[mt][j][2] + bb0, acc[mt][j][3] + bb1);
                *(__half2*)&OUT[(size_t)(r + 8) * NOUT + c] = h;
            }
        }
}

// ---------------- layer-2 edge GEMM (R8 config: 256 thr, tile 128x128) ----------------
#define SM_SDST 0
#define SM_SSRC 512
#define SM_A    1024
#define SM_B0   19456
#define SM_B1   37888
#define SM_STG  1024
#define EDGE_SMEM 56320

template <int KW, int NOUT>
__global__ void __launch_bounds__(256, 2) k_edge_mma(
    const __half* __restrict__ C, const __half* __restrict__ D,
    const __half* __restrict__ WT, const float* __restrict__ b2, float* __restrict__ AGG)
{
    extern __shared__ char smem[];
    const uint32_t sb = smem_u32(smem);
    const int tid = threadIdx.x;
    const int wid = tid >> 5, lid = tid & 31;
    const int warp_m = wid & 3, warp_n = wid >> 2;
    const int gid = lid >> 2, tig = lid & 3;

    int* sdst = (int*)(smem + SM_SDST);
    int* ssrc = (int*)(smem + SM_SSRC);

    const int e0 = blockIdx.x * 128;
    const int n0 = blockIdx.y * 128;
    if (tid < 128) {
        sdst[tid] = g_dst_s[e0 + tid];
        ssrc[tid] = g_src_s[e0 + tid];
    }
    __syncthreads();

    const int fm = tid >> 1;
    const int fk = (tid & 1) * 32;
    const __half* rowC = C + (size_t)sdst[fm] * KW + fk;
    const __half* rowD = D + (size_t)ssrc[fm] * KW + fk;
    const __half* rowW = WT + (size_t)(n0 + fm) * KW + fk;
    const uint32_t bdst0 = sb + SM_B0 + fm * 144 + fk * 2;
    const uint32_t bdst1 = sb + SM_B1 + fm * 144 + fk * 2;

    float acc[2][8][4];
#pragma unroll
    for (int a = 0; a < 2; ++a)
#pragma unroll
        for (int b = 0; b < 8; ++b)
#pragma unroll
            for (int c = 0; c < 4; ++c) acc[a][b][c] = 0.f;

    constexpr int NCH = KW / 64;
    uint4 pc[4], pd[4];
    {
        const uint4* cp = (const uint4*)rowC;
        const uint4* dp = (const uint4*)rowD;
#pragma unroll
        for (int q = 0; q < 4; ++q) { pc[q] = cp[q]; pd[q] = dp[q]; }
        cp16(bdst0,      rowW);
        cp16(bdst0 + 16, rowW + 8);
        cp16(bdst0 + 32, rowW + 16);
        cp16(bdst0 + 48, rowW + 24);
        cp_commit();
    }

#pragma unroll 1
    for (int ch = 0; ch < NCH; ++ch) {
        {
            uint4 ao[4];
#pragma unroll
            for (int q = 0; q < 4; ++q) {
                ao[q].x = haddrelu2(pc[q].x, pd[q].x);
                ao[q].y = haddrelu2(pc[q].y, pd[q].y);
                ao[q].z = haddrelu2(pc[q].z, pd[q].z);
                ao[q].w = haddrelu2(pc[q].w, pd[q].w);
            }
            char* pa = smem + SM_A + fm * 144 + fk * 2;
            *(uint4*)pa        = ao[0];
            *(uint4*)(pa + 16) = ao[1];
            *(uint4*)(pa + 32) = ao[2];
            *(uint4*)(pa + 48) = ao[3];
        }
        cp_wait_all();
        __syncthreads();

        if (ch + 1 < NCH) {
            const uint4* cp = (const uint4*)(rowC + (ch + 1) * 64);
            const uint4* dp = (const uint4*)(rowD + (ch + 1) * 64);
#pragma unroll
            for (int q = 0; q < 4; ++q) { pc[q] = cp[q]; pd[q] = dp[q]; }
            const __half* ws = rowW + (ch + 1) * 64;
            uint32_t bd = ((ch + 1) & 1) ? bdst1 : bdst0;
            cp16(bd,      ws);
            cp16(bd + 16, ws + 8);
            cp16(bd + 32, ws + 16);
            cp16(bd + 48, ws + 24);
            cp_commit();
        }

        const char* Bbuf = smem + ((ch & 1) ? SM_B1 : SM_B0);
#pragma unroll
        for (int ks = 0; ks < 4; ++ks) {
            const int koff = ks * 32 + tig * 4;
            uint32_t a[2][4];
#pragma unroll
            for (int mt = 0; mt < 2; ++mt) {
                int r = warp_m * 32 + mt * 16 + gid;
                const char* base = smem + SM_A + r * 144;
                a[mt][0] = *(const uint32_t*)(base + koff);
                a[mt][1] = *(const uint32_t*)(base + 8 * 144 + koff);
                a[mt][2] = *(const uint32_t*)(base + koff + 16);
                a[mt][3] = *(const uint32_t*)(base + 8 * 144 + koff + 16);
            }
#pragma unroll
            for (int j = 0; j < 8; ++j) {
                int n = warp_n * 64 + j * 8 + gid;
                const char* bb = Bbuf + n * 144;
                uint32_t b0 = *(const uint32_t*)(bb + koff);
                uint32_t b1 = *(const uint32_t*)(bb + koff + 16);
                mma_f16(acc[0][j], a[0][0], a[0][1], a[0][2], a[0][3], b0, b1);
                mma_f16(acc[1][j], a[1][0], a[1][1], a[1][2], a[1][3], b0, b1);
            }
        }
        __syncthreads();
    }

    float* stage = (float*)(smem + SM_STG);
#pragma unroll 1
    for (int p = 0; p < 2; ++p) {
        if (warp_n == p) {
#pragma unroll
            for (int mt = 0; mt < 2; ++mt)
#pragma unroll
                for (int j = 0; j < 8; ++j) {
                    int r0 = warp_m * 32 + mt * 16 + gid;
                    int cw = j * 8 + tig * 2;
                    float* st = stage + r0 * 66 + cw;
                    st[0] = acc[mt][j][0];
                    st[1] = acc[mt][j][1];
                    st[66 * 8] = acc[mt][j][2];
                    st[66 * 8 + 1] = acc[mt][j][3];
                }
        }
        __syncthreads();
        {
            int colw = tid & 63;
            int grp = tid >> 6;
            int gcol = n0 + p * 64 + colw;
            float bias = b2[gcol];
            int prev = -1;
            float mx = 0.f;
#pragma unroll 4
            for (int r = grp * 32; r < grp * 32 + 32; ++r) {
                int d = sdst[r];
                float v = fmaxf(stage[r * 66 + colw] + bias, 0.f);
                if (d == prev) {
                    mx = fmaxf(mx, v);
                } else {
                    if (prev >= 0)
                        atomicMax((int*)&AGG[(size_t)prev * NOUT + gcol], __float_as_int(mx));
                    prev = d;
                    mx = v;
                }
            }
            atomicMax((int*)&AGG[(size_t)prev * NOUT + gcol], __float_as_int(mx));
        }
        __syncthreads();
    }
}

// ---------------- layer-1 edge GEMM: 512 thr, tile 128 edges x 256 cols ----------------
#define WEDGE_SMEM 93184

template <int KW, int NOUT>
__global__ void __launch_bounds__(512, 1) k_edge_wide(
    const __half* __restrict__ C, const __half* __restrict__ D,
    const __half* __restrict__ WT, const float* __restrict__ b2, float* __restrict__ AGG)
{
    extern __shared__ char smem[];
    const uint32_t sb = smem_u32(smem);
    const int tid = threadIdx.x;
    const int wid = tid >> 5, lid = tid & 31;
    const int warp_m = wid & 3, warp_n = wid >> 2;   // 4 x 4
    const int gid = lid >> 2, tig = lid & 3;

    int* sdst = (int*)(smem + SM_SDST);
    int* ssrc = (int*)(smem + SM_SSRC);

    const int e0 = blockIdx.x * 128;
    if (tid < 128) {
        sdst[tid] = g_dst_s[e0 + tid];
        ssrc[tid] = g_src_s[e0 + tid];
    }
    __syncthreads();

    const int fm = tid >> 2;
    const int fq = (tid & 3) * 16;
    const int wm = tid >> 1;
    const int wq = (tid & 1) * 32;
    const __half* rowC = C + (size_t)sdst[fm] * KW + fq;
    const __half* rowD = D + (size_t)ssrc[fm] * KW + fq;
    const __half* rowW = WT + (size_t)wm * KW + wq;
    const uint32_t bdst0 = sb + SM_B0 + wm * 144 + wq * 2;
    const uint32_t bdst1 = sb + SM_B0 + 36864 + wm * 144 + wq * 2;

    float acc[2][8][4];
#pragma unroll
    for (int a = 0; a < 2; ++a)
#pragma unroll
        for (int b = 0; b < 8; ++b)
#pragma unroll
            for (int c = 0; c < 4; ++c) acc[a][b][c] = 0.f;

    constexpr int NCH = KW / 64;
    uint4 pc[2], pd[2];
    {
        const uint4* cp = (const uint4*)rowC;
        const uint4* dp = (const uint4*)rowD;
        pc[0] = cp[0]; pc[1] = cp[1];
        pd[0] = dp[0]; pd[1] = dp[1];
        cp16(bdst0,      rowW);
        cp16(bdst0 + 16, rowW + 8);
        cp16(bdst0 + 32, rowW + 16);
        cp16(bdst0 + 48, rowW + 24);
        cp_commit();
    }

#pragma unroll 1
    for (int ch = 0; ch < NCH; ++ch) {
        {
            uint4 ao[2];
#pragma unroll
            for (int q = 0; q < 2; ++q) {
                ao[q].x = haddrelu2(pc[q].x, pd[q].x);
                ao[q].y = haddrelu2(pc[q].y, pd[q].y);
                ao[q].z = haddrelu2(pc[q].z, pd[q].z);
                ao[q].w = haddrelu2(pc[q].w, pd[q].w);
            }
            char* pa = smem + SM_A + fm * 144 + fq * 2;
            *(uint4*)pa        = ao[0];
            *(uint4*)(pa + 16) = ao[1];
        }
        cp_wait_all();
        __syncthreads();

        if (ch + 1 < NCH) {
            const uint4* cp = (const uint4*)(rowC + (ch + 1) * 64);
            const uint4* dp = (const uint4*)(rowD + (ch + 1) * 64);
            pc[0] = cp[0]; pc[1] = cp[1];
            pd[0] = dp[0]; pd[1] = dp[1];
            const __half* ws = rowW + (ch + 1) * 64;
            uint32_t bd = ((ch + 1) & 1) ? bdst1 : bdst0;
            cp16(bd,      ws);
            cp16(bd + 16, ws + 8);
            cp16(bd + 32, ws + 16);
            cp16(bd + 48, ws + 24);
            cp_commit();
        }

        const char* Bbuf = smem + SM_B0 + ((ch & 1) ? 36864 : 0);
#pragma unroll
        for (int ks = 0; ks < 4; ++ks) {
            const int koff = ks * 32 + tig * 4;
            uint32_t a[2][4];
#pragma unroll
            for (int mt = 0; mt < 2; ++mt) {
                int r = warp_m * 32 + mt * 16 + gid;
                const char* base = smem + SM_A + r * 144;
                a[mt][0] = *(const uint32_t*)(base + koff);
                a[mt][1] = *(const uint32_t*)(base + 8 * 144 + koff);
                a[mt][2] = *(const uint32_t*)(base + koff + 16);
                a[mt][3] = *(const uint32_t*)(base + 8 * 144 + koff + 16);
            }
#pragma unroll
            for (int j = 0; j < 8; ++j) {
                int n = warp_n * 64 + j * 8 + gid;
                const char* bb = Bbuf + n * 144;
                uint32_t b0 = *(const uint32_t*)(bb + koff);
                uint32_t b1 = *(const uint32_t*)(bb + koff + 16);
                mma_f16(acc[0][j], a[0][0], a[0][1], a[0][2], a[0][3], b0, b1);
                mma_f16(acc[1][j], a[1][0], a[1][1], a[1][2], a[1][3], b0, b1);
            }
        }
        __syncthreads();
    }

    float* stage = (float*)(smem + SM_STG);
#pragma unroll 1
    for (int p = 0; p < 4; ++p) {
        if (warp_n == p) {
#pragma unroll
            for (int mt = 0; mt < 2; ++mt)
#pragma unroll
                for (int j = 0; j < 8; ++j) {
                    int r0 = warp_m * 32 + mt * 16 + gid;
                    int cw = j * 8 + tig * 2;
                    float* st = stage + r0 * 66 + cw;
                    st[0] = acc[mt][j][0];
                    st[1] = acc[mt][j][1];
                    st[66 * 8] = acc[mt][j][2];
                    st[66 * 8 + 1] = acc[mt][j][3];
                }
        }
        __syncthreads();
        {
            int colw = tid & 63;
            int grp = tid >> 6;
            int gcol = p * 64 + colw;
            float bias = b2[gcol];
            int prev = -1;
            float mx = 0.f;
#pragma unroll 4
            for (int r = grp * 16; r < grp * 16 + 16; ++r) {
                int d = sdst[r];
                float v = fmaxf(stage[r * 66 + colw] + bias, 0.f);
                if (d == prev) {
                    mx = fmaxf(mx, v);
                } else {
                    if (prev >= 0)
                        atomicMax((int*)&AGG[(size_t)prev * NOUT + gcol], __float_as_int(mx));
                    prev = d;
                    mx = v;
                }
            }
            atomicMax((int*)&AGG[(size_t)prev * NOUT + gcol], __float_as_int(mx));
        }
        __syncthreads();
    }
}

// ---------------- dense head ----------------
__global__ void k_head(const float* __restrict__ W3, const float* __restrict__ b3,
                       const float* __restrict__ W4, const float* __restrict__ b4,
                       float* __restrict__ out) {
    __shared__ float sh[128];
    __shared__ float red[2];
    int n = blockIdx.x;
    int t = threadIdx.x;   // 64 threads
    sh[t]      = g_H2[n * 128 + t];
    sh[t + 64] = g_H2[n * 128 + 64 + t];
    __syncthreads();
    float s = b3[t];
#pragma unroll 8
    for (int k = 0; k < 128; k++) s += sh[k] * W3[k * 64 + t];
    s = fmaxf(s, 0.f);
    float p = s * W4[t];
#pragma unroll
    for (int off = 16; off > 0; off >>= 1) p += __shfl_down_sync(0xffffffffu, p, off);
    if ((t & 31) == 0) red[t >> 5] = p;
    __syncthreads();
    if (t == 0) {
        float z = red[0] + red[1] + b4[0];
        out[n] = 1.f / (1.f + expf(-z));
    }
}

// ---------------- launch ----------------
extern "C" void kernel_launch(void* const* d_in, const int* in_sizes, int n_in,
                              void* d_out, int out_size) {
    const float* x   = (const float*)d_in[0];
    const int*   ei  = (const int*)d_in[1];
    const int*   src = ei;
    const int*   dst = ei + N_EDGES;
    const float* W1a = (const float*)d_in[2];
    const float* b1a = (const float*)d_in[3];
    const float* W2a = (const float*)d_in[4];
    const float* b2a = (const float*)d_in[5];
    const float* W1b = (const float*)d_in[6];
    const float* b1b = (const float*)d_in[7];
    const float* W2b = (const float*)d_in[8];
    const float* b2b = (const float*)d_in[9];
    const float* W3  = (const float*)d_in[10];
    const float* b3  = (const float*)d_in[11];
    const float* W4  = (const float*)d_in[12];
    const float* b4  = (const float*)d_in[13];
    float* out = (float*)d_out;

    void *pC1, *pD1, *pH1, *pC2, *pD2, *pH2, *pWT1, *pWT2, *pWTD1, *pWTD2;
    cudaGetSymbolAddress(&pC1, g_C1);
    cudaGetSymbolAddress(&pD1, g_D1);
    cudaGetSymbolAddress(&pH1, g_H1);
    cudaGetSymbolAddress(&pC2, g_C2);
    cudaGetSymbolAddress(&pD2, g_D2);
    cudaGetSymbolAddress(&pH2, g_H2);
    cudaGetSymbolAddress(&pWT1, g_WT1);
    cudaGetSymbolAddress(&pWT2, g_WT2);
    cudaGetSymbolAddress(&pWTD1, g_WTD1);
    cudaGetSymbolAddress(&pWTD2, g_WTD2);

    cudaFuncSetAttribute(k_edge_wide<512, 256>, cudaFuncAttributeMaxDynamicSharedMemorySize, WEDGE_SMEM);
    cudaFuncSetAttribute(k_edge_mma<256, 128>, cudaFuncAttributeMaxDynamicSharedMemorySize, EDGE_SMEM);
    cudaFuncSetAttribute(k_node_mma<128, 512>, cudaFuncAttributeMaxDynamicSharedMemorySize, NODE_SMEM);
    cudaFuncSetAttribute(k_node_mma<256, 256>, cudaFuncAttributeMaxDynamicSharedMemorySize, NODE_SMEM);

    // init + fused setup (hist + weight preps) + scan + scatter
    k_zero<<<512, 256>>>();
    k_setup<<<(614912 + 255) / 256, 256>>>(dst, W2a, W2b, W1a, W1b);
    k_scan1<<<20, 512>>>();
    k_scan23<<<20, 512>>>();
    k_scatter<<<(N_EDGES + 255) / 256, 256>>>(src, dst);

    // layer 1
    {
        dim3 g((N_NODES + 127) / 128, 1024 / 128);
        k_node_mma<128, 512><<<g, 256, NODE_SMEM>>>(x, (const __half*)pWTD1, b1a,
                                                    (__half*)pC1, (__half*)pD1);
    }
    k_edge_wide<512, 256><<<N_EDGES / 128, 512, WEDGE_SMEM>>>(
        (const __half*)pC1, (const __half*)pD1,
        (const __half*)pWT1, b2a, (float*)pH1);

    // layer 2
    {
        dim3 g((N_NODES + 127) / 128, 512 / 128);
        k_node_mma<256, 256><<<g, 256, NODE_SMEM>>>((const float*)pH1, (const __half*)pWTD2, b1b,
                                                    (__half*)pC2, (__half*)pD2);
    }
    {
        dim3 g(N_EDGES / 128, 128 / 128);
        k_edge_mma<256, 128><<<g, 256, EDGE_SMEM>>>(
            (const __half*)pC2, (const __half*)pD2,
            (const __half*)pWT2, b2b, (float*)pH2);
    }

    // head
    k_head<<<N_NODES, 64>>>(W3, b3, W4, b4, out);
}

// round 12
// speedup vs baseline: 1.1062x; 1.0131x over previous
#include <cuda_runtime.h>
#include <cuda_fp16.h>
#include <stdint.h>
#include <math.h>

#define N_NODES 10000
#define N_EDGES 320000

// ---------------- scratch (static device allocations) ----------------
__device__ __half g_C1[N_NODES * 512];   // fp16: x@(W1top-W1bot) + b1
__device__ __half g_D1[N_NODES * 512];   // fp16: x@W1bot
__device__ float  g_H1[N_NODES * 256];
__device__ __half g_C2[N_NODES * 256];
__device__ __half g_D2[N_NODES * 256];
__device__ float  g_H2[N_NODES * 128];
__device__ int    g_hist[N_NODES + 1];
__device__ int    g_bsum[32];
__device__ int    g_cursor[N_NODES];
__device__ int    g_src_s[N_EDGES];
__device__ int    g_dst_s[N_EDGES];
__device__ __half g_WT1[256 * 512];
__device__ __half g_WT2[128 * 256];
__device__ __half g_WTD1[1024 * 128];
__device__ __half g_WTD2[512 * 256];

// ---------------- helpers ----------------
__device__ __forceinline__ uint32_t smem_u32(const void* p) {
    uint32_t a;
    asm("{ .reg .u64 t; cvta.to.shared.u64 t, %1; cvt.u32.u64 %0, t; }" : "=r"(a) : "l"(p));
    return a;
}
__device__ __forceinline__ void mma_f16(float* c,
    uint32_t a0, uint32_t a1, uint32_t a2, uint32_t a3,
    uint32_t b0, uint32_t b1) {
    asm volatile(
        "mma.sync.aligned.m16n8k16.row.col.f32.f16.f16.f32 "
        "{%0,%1,%2,%3}, {%4,%5,%6,%7}, {%8,%9}, {%0,%1,%2,%3};"
        : "+f"(c[0]), "+f"(c[1]), "+f"(c[2]), "+f"(c[3])
        : "r"(a0), "r"(a1), "r"(a2), "r"(a3), "r"(b0), "r"(b1));
}
__device__ __forceinline__ uint32_t haddrelu2(uint32_t a, uint32_t b) {
    __half2 av = *reinterpret_cast<__half2*>(&a);
    __half2 bv = *reinterpret_cast<__half2*>(&b);
    __half2 r = __hmax2(__hadd2(av, bv), __float2half2_rn(0.f));
    return *reinterpret_cast<uint32_t*>(&r);
}
__device__ __forceinline__ void cp16(uint32_t dst, const void* src) {
    asm volatile("cp.async.ca.shared.global [%0], [%1], 16;" :: "r"(dst), "l"(src) : "memory");
}
__device__ __forceinline__ void cp_commit() {
    asm volatile("cp.async.commit_group;" ::: "memory");
}
__device__ __forceinline__ void cp_wait_all() {
    asm volatile("cp.async.wait_group 0;" ::: "memory");
}

// ---------------- init (zero only; must precede atomics in k_setup) ----------------
__global__ void k_zero() {
    int stride = gridDim.x * blockDim.x;
    int i0 = blockIdx.x * blockDim.x + threadIdx.x;
    float4 z4 = make_float4(0.f, 0.f, 0.f, 0.f);
    for (int j = i0; j < N_NODES * 64; j += stride) ((float4*)g_H1)[j] = z4;
    for (int j = i0; j < N_NODES * 32; j += stride) ((float4*)g_H2)[j] = z4;
    for (int j = i0; j <= N_NODES;     j += stride) g_hist[j] = 0;
    for (int j = i0; j < N_NODES;      j += stride) g_cursor[j] = 0;
}

// ---------------- fused setup: histogram + all weight preps ----------------
__global__ void k_setup(const int* __restrict__ dst,
                        const float* __restrict__ W2a, const float* __restrict__ W2b,
                        const float* __restrict__ W1a, const float* __restrict__ W1b) {
    int i = blockIdx.x * blockDim.x + threadIdx.x;
    if (i < 320000) {
        atomicAdd(&g_hist[dst[i] + 1], 1);
    } else if (i < 451072) {
        int i2 = i - 320000;                 // WT1: [256,512] K-major from W2a [512,256]
        int n = i2 >> 9, k = i2 & 511;
        g_WT1[i2] = __float2half_rn(W2a[k * 256 + n]);
    } else if (i < 483840) {
        int i2 = i - 451072;                 // WT2: [128,256] from W2b [256,128]
        int n = i2 >> 8, k = i2 & 255;
        g_WT2[i2] = __float2half_rn(W2b[k * 128 + n]);
    } else if (i < 549376) {
        int i2 = i - 483840;                 // WTD1: dual [1024,128] from W1a [256,512]
        int n = i2 >> 7, k = i2 & 127;
        float top = W1a[k * 512 + n];
        float bot = W1a[(128 + k) * 512 + n];
        g_WTD1[n * 128 + k] = __float2half_rn(top - bot);
        g_WTD1[(512 + n) * 128 + k] = __float2half_rn(bot);
    } else if (i < 614912) {
        int i2 = i - 549376;                 // WTD2: dual [512,256] from W1b [512,256]
        int n = i2 >> 8, k = i2 & 255;
        float top = W1b[k * 256 + n];
        float bot = W1b[(256 + k) * 256 + n];
        g_WTD2[n * 256 + k] = __float2half_rn(top - bot);
        g_WTD2[(256 + n) * 256 + k] = __float2half_rn(bot);
    }
}

// ---------------- counting-sort scan + scatter ----------------
__global__ void k_scan1() {
    __shared__ int s[512];
    int b = blockIdx.x, t = threadIdx.x;
    int i = b * 512 + t;
    int v = (i < N_NODES + 1) ? g_hist[i] : 0;
    s[t] = v;
    __syncthreads();
    for (int off = 1; off < 512; off <<= 1) {
        int u = (t >= off) ? s[t - off] : 0;
        __syncthreads();
        s[t] += u;
        __syncthreads();
    }
    if (i < N_NODES + 1) g_hist[i] = s[t];
    if (t == 511) g_bsum[b] = s[511];
}
__global__ void k_scan23() {
    __shared__ int soff;
    int b = blockIdx.x, t = threadIdx.x;
    if (t < 32) {
        int v = (t < b) ? g_bsum[t] : 0;
#pragma unroll
        for (int off = 16; off > 0; off >>= 1)
            v += __shfl_down_sync(0xffffffffu, v, off);
        if (t == 0) soff = v;
    }
    __syncthreads();
    int i = b * 512 + t;
    if (i < N_NODES + 1) g_hist[i] += soff;
}
__global__ void k_scatter(const int* __restrict__ src, const int* __restrict__ dst) {
    int e = blockIdx.x * blockDim.x + threadIdx.x;
    if (e < N_EDGES) {
        int d = dst[e];
        int pos = g_hist[d] + atomicAdd(&g_cursor[d], 1);
        g_src_s[pos] = src[e];
        g_dst_s[pos] = d;
    }
}

// ---------------- node fp16 MMA GEMM: [C | D] = fp16(X) @ WTdual^T ----------------
#define NODE_SMEM 36864

template <int K, int NOUT>
__global__ void __launch_bounds__(256, 2) k_node_mma(
    const float* __restrict__ X, const __half* __restrict__ WT,
    const float* __restrict__ b1, __half* __restrict__ C, __half* __restrict__ D)
{
    extern __shared__ char smem[];
    const int tid = threadIdx.x;
    const int wid = tid >> 5, lid = tid & 31;
    const int warp_m = wid & 3, warp_n = wid >> 2;
    const int gid = lid >> 2, tig = lid & 3;

    const int m0 = blockIdx.x * 128;
    const int n0 = blockIdx.y * 128;

    const int fm = tid >> 1;
    const int fk = (tid & 1) * 32;
    const int gm = m0 + fm;
    const bool valid = gm < N_NODES;
    const float* rowX = X + (size_t)(valid ? gm : 0) * K + fk;
    const __half* rowW = WT + (size_t)(n0 + fm) * K + fk;

    float acc[2][8][4];
#pragma unroll
    for (int a = 0; a < 2; ++a)
#pragma unroll
        for (int b = 0; b < 8; ++b)
#pragma unroll
            for (int c = 0; c < 4; ++c) acc[a][b][c] = 0.f;

    constexpr int NCH = K / 64;
#pragma unroll 1
    for (int ch = 0; ch < NCH; ++ch) {
        {
            const uint4* wp = (const uint4*)(rowW + ch * 64);
            uint4 w0 = wp[0], w1 = wp[1], w2 = wp[2], w3 = wp[3];
            char* pb = smem + 18432 + fm * 144 + fk * 2;
            *(uint4*)pb        = w0;
            *(uint4*)(pb + 16) = w1;
            *(uint4*)(pb + 32) = w2;
            *(uint4*)(pb + 48) = w3;
        }
        {
            char* pa = smem + fm * 144 + fk * 2;
#pragma unroll
            for (int q = 0; q < 4; ++q) {
                float4 x0 = make_float4(0.f, 0.f, 0.f, 0.f);
                float4 x1 = make_float4(0.f, 0.f, 0.f, 0.f);
                if (valid) {
                    x0 = *(const float4*)(rowX + ch * 64 + q * 8);
                    x1 = *(const float4*)(rowX + ch * 64 + q * 8 + 4);
                }
                __half2 h0 = __floats2half2_rn(x0.x, x0.y);
                __half2 h1 = __floats2half2_rn(x0.z, x0.w);
                __half2 h2 = __floats2half2_rn(x1.x, x1.y);
                __half2 h3 = __floats2half2_rn(x1.z, x1.w);
                *(uint4*)(pa + q * 16) = make_uint4(
                    *(uint32_t*)&h0, *(uint32_t*)&h1, *(uint32_t*)&h2, *(uint32_t*)&h3);
            }
        }
        __syncthreads();
#pragma unroll
        for (int ks = 0; ks < 4; ++ks) {
            const int koff = ks * 32 + tig * 4;
            uint32_t a[2][4];
#pragma unroll
            for (int mt = 0; mt < 2; ++mt) {
                int r = warp_m * 32 + mt * 16 + gid;
                const char* base = smem + r * 144;
                a[mt][0] = *(const uint32_t*)(base + koff);
                a[mt][1] = *(const uint32_t*)(base + 8 * 144 + koff);
                a[mt][2] = *(const uint32_t*)(base + koff + 16);
                a[mt][3] = *(const uint32_t*)(base + 8 * 144 + koff + 16);
            }
#pragma unroll
            for (int j = 0; j < 8; ++j) {
                int n = warp_n * 64 + j * 8 + gid;
                const char* bb = smem + 18432 + n * 144;
                uint32_t b0 = *(const uint32_t*)(bb + koff);
                uint32_t b1v = *(const uint32_t*)(bb + koff + 16);
                mma_f16(acc[0][j], a[0][0], a[0][1], a[0][2], a[0][3], b0, b1v);
                mma_f16(acc[1][j], a[1][0], a[1][1], a[1][2], a[1][3], b0, b1v);
            }
        }
        __syncthreads();
    }

    const bool isC = (n0 < NOUT);
    __half* OUT = isC ? C : D;
    const int cb = isC ? n0 : n0 - NOUT;
#pragma unroll
    for (int mt = 0; mt < 2; ++mt)
#pragma unroll
        for (int j = 0; j < 8; ++j) {
            int r = m0 + warp_m * 32 + mt * 16 + gid;
            int c = cb + warp_n * 64 + j * 8 + tig * 2;
            float bb0 = 0.f, bb1 = 0.f;
            if (isC) { bb0 = __ldg(b1 + c); bb1 = __ldg(b1 + c + 1); }
            if (r < N_NODES) {
                __half2 h = __floats2half2_rn(acc[mt][j][0] + bb0, acc[mt][j][1] + bb1);
                *(__half2*)&OUT[(size_t)r * NOUT + c] = h;
            }
            if (r + 8 < N_NODES) {
                __half2 h = __floats2half2_rn(acc[mt][j][2] + bb0, acc[mt][j][3] + bb1);
                *(__half2*)&OUT[(size_t)(r + 8) * NOUT + c] = h;
            }
        }
}

// ---------------- layer-2 edge GEMM: 256 thr, tile 128x128, A+B double-buffered ----------
// SMEM: sdst@0, ssrc@512, A0@1024, A1@19456, B0@37888, B1@56320 (each 18432); stage@1024
#define SM_SDST 0
#define SM_SSRC 512
#define SM_A0   1024
#define SM_A1   19456
#define SM_B0   37888
#define SM_B1   56320
#define SM_STG  1024
#define EDGE_SMEM 74752

template <int KW, int NOUT>
__global__ void __launch_bounds__(256, 2) k_edge_mma(
    const __half* __restrict__ C, const __half* __restrict__ D,
    const __half* __restrict__ WT, const float* __restrict__ b2, float* __restrict__ AGG)
{
    extern __shared__ char smem[];
    const uint32_t sb = smem_u32(smem);
    const int tid = threadIdx.x;
    const int wid = tid >> 5, lid = tid & 31;
    const int warp_m = wid & 3, warp_n = wid >> 2;
    const int gid = lid >> 2, tig = lid & 3;

    int* sdst = (int*)(smem + SM_SDST);
    int* ssrc = (int*)(smem + SM_SSRC);

    const int e0 = blockIdx.x * 128;
    const int n0 = blockIdx.y * 128;
    if (tid < 128) {
        sdst[tid] = g_dst_s[e0 + tid];
        ssrc[tid] = g_src_s[e0 + tid];
    }
    __syncthreads();

    const int fm = tid >> 1;
    const int fk = (tid & 1) * 32;
    const __half* rowC = C + (size_t)sdst[fm] * KW + fk;
    const __half* rowD = D + (size_t)ssrc[fm] * KW + fk;
    const __half* rowW = WT + (size_t)(n0 + fm) * KW + fk;
    const uint32_t bdst0 = sb + SM_B0 + fm * 144 + fk * 2;
    const uint32_t bdst1 = sb + SM_B1 + fm * 144 + fk * 2;

    float acc[2][8][4];
#pragma unroll
    for (int a = 0; a < 2; ++a)
#pragma unroll
        for (int b = 0; b < 8; ++b)
#pragma unroll
            for (int c = 0; c < 4; ++c) acc[a][b][c] = 0.f;

    constexpr int NCH = KW / 64;
    uint4 pc[4], pd[4];
    {   // prologue: gathers for ch0 + async B0
        const uint4* cp = (const uint4*)rowC;
        const uint4* dp = (const uint4*)rowD;
#pragma unroll
        for (int q = 0; q < 4; ++q) { pc[q] = cp[q]; pd[q] = dp[q]; }
        cp16(bdst0,      rowW);
        cp16(bdst0 + 16, rowW + 8);
        cp16(bdst0 + 32, rowW + 16);
        cp16(bdst0 + 48, rowW + 24);
        cp_commit();
    }

#pragma unroll 1
    for (int ch = 0; ch < NCH; ++ch) {
        // step1: A[ch] -> Abuf[ch&1]
        {
            uint4 ao[4];
#pragma unroll
            for (int q = 0; q < 4; ++q) {
                ao[q].x = haddrelu2(pc[q].x, pd[q].x);
                ao[q].y = haddrelu2(pc[q].y, pd[q].y);
                ao[q].z = haddrelu2(pc[q].z, pd[q].z);
                ao[q].w = haddrelu2(pc[q].w, pd[q].w);
            }
            char* pa = smem + ((ch & 1) ? SM_A1 : SM_A0) + fm * 144 + fk * 2;
            *(uint4*)pa        = ao[0];
            *(uint4*)(pa + 16) = ao[1];
            *(uint4*)(pa + 32) = ao[2];
            *(uint4*)(pa + 48) = ao[3];
        }
        // step2: B[ch] landed + A[ch] visible
        cp_wait_all();
        __syncthreads();
        // step3: issue next-chunk gathers + async B (overlaps MMA below)
        if (ch + 1 < NCH) {
            const uint4* cp = (const uint4*)(rowC + (ch + 1) * 64);
            const uint4* dp = (const uint4*)(rowD + (ch + 1) * 64);
#pragma unroll
            for (int q = 0; q < 4; ++q) { pc[q] = cp[q]; pd[q] = dp[q]; }
            const __half* ws = rowW + (ch + 1) * 64;
            uint32_t bd = ((ch + 1) & 1) ? bdst1 : bdst0;
            cp16(bd,      ws);
            cp16(bd + 16, ws + 8);
            cp16(bd + 32, ws + 16);
            cp16(bd + 48, ws + 24);
            cp_commit();
        }
        // step4: MMA from buf[ch&1]
        const char* Abuf = smem + ((ch & 1) ? SM_A1 : SM_A0);
        const char* Bbuf = smem + ((ch & 1) ? SM_B1 : SM_B0);
#pragma unroll
        for (int ks = 0; ks < 4; ++ks) {
            const int koff = ks * 32 + tig * 4;
            uint32_t a[2][4];
#pragma unroll
            for (int mt = 0; mt < 2; ++mt) {
                int r = warp_m * 32 + mt * 16 + gid;
                const char* base = Abuf + r * 144;
                a[mt][0] = *(const uint32_t*)(base + koff);
                a[mt][1] = *(const uint32_t*)(base + 8 * 144 + koff);
                a[mt][2] = *(const uint32_t*)(base + koff + 16);
                a[mt][3] = *(const uint32_t*)(base + 8 * 144 + koff + 16);
            }
#pragma unroll
            for (int j = 0; j < 8; ++j) {
                int n = warp_n * 64 + j * 8 + gid;
                const char* bb = Bbuf + n * 144;
                uint32_t b0 = *(const uint32_t*)(bb + koff);
                uint32_t b1 = *(const uint32_t*)(bb + koff + 16);
                mma_f16(acc[0][j], a[0][0], a[0][1], a[0][2], a[0][3], b0, b1);
                mma_f16(acc[1][j], a[1][0], a[1][1], a[1][2], a[1][3], b0, b1);
            }
        }
    }
    __syncthreads();   // protect stage region (overlaps A buffers)

    float* stage = (float*)(smem + SM_STG);
#pragma unroll 1
    for (int p = 0; p < 2; ++p) {
        if (warp_n == p) {
#pragma unroll
            for (int mt = 0; mt < 2; ++mt)
#pragma unroll
                for (int j = 0; j < 8; ++j) {
                    int r0 = warp_m * 32 + mt * 16 + gid;
                    int cw = j * 8 + tig * 2;
                    float* st = stage + r0 * 66 + cw;
                    st[0] = acc[mt][j][0];
                    st[1] = acc[mt][j][1];
                    st[66 * 8] = acc[mt][j][2];
                    st[66 * 8 + 1] = acc[mt][j][3];
                }
        }
        __syncthreads();
        {
            int colw = tid & 63;
            int grp = tid >> 6;
            int gcol = n0 + p * 64 + colw;
            float bias = b2[gcol];
            int prev = -1;
            float mx = 0.f;
#pragma unroll 4
            for (int r = grp * 32; r < grp * 32 + 32; ++r) {
                int d = sdst[r];
                float v = fmaxf(stage[r * 66 + colw] + bias, 0.f);
                if (d == prev) {
                    mx = fmaxf(mx, v);
                } else {
                    if (prev >= 0)
                        atomicMax((int*)&AGG[(size_t)prev * NOUT + gcol], __float_as_int(mx));
                    prev = d;
                    mx = v;
                }
            }
            atomicMax((int*)&AGG[(size_t)prev * NOUT + gcol], __float_as_int(mx));
        }
        __syncthreads();
    }
}

// ---------------- layer-1 edge GEMM: 512 thr, tile 128x256, A+B double-buffered -------
// SMEM: sdst@0, ssrc@512, A0@1024, A1@19456 (18432 each), B0@37888, B1@74752 (36864 each)
#define WSM_A0 1024
#define WSM_A1 19456
#define WSM_B0 37888
#define WSM_B1 74752
#define WEDGE_SMEM 111616

template <int KW, int NOUT>
__global__ void __launch_bounds__(512, 1) k_edge_wide(
    const __half* __restrict__ C, const __half* __restrict__ D,
    const __half* __restrict__ WT, const float* __restrict__ b2, float* __restrict__ AGG)
{
    extern __shared__ char smem[];
    const uint32_t sb = smem_u32(smem);
    const int tid = threadIdx.x;
    const int wid = tid >> 5, lid = tid & 31;
    const int warp_m = wid & 3, warp_n = wid >> 2;   // 4 x 4
    const int gid = lid >> 2, tig = lid & 3;

    int* sdst = (int*)(smem + SM_SDST);
    int* ssrc = (int*)(smem + SM_SSRC);

    const int e0 = blockIdx.x * 128;
    if (tid < 128) {
        sdst[tid] = g_dst_s[e0 + tid];
        ssrc[tid] = g_src_s[e0 + tid];
    }
    __syncthreads();

    const int fm = tid >> 2;
    const int fq = (tid & 3) * 16;
    const int wm = tid >> 1;
    const int wq = (tid & 1) * 32;
    const __half* rowC = C + (size_t)sdst[fm] * KW + fq;
    const __half* rowD = D + (size_t)ssrc[fm] * KW + fq;
    const __half* rowW = WT + (size_t)wm * KW + wq;
    const uint32_t bdst0 = sb + WSM_B0 + wm * 144 + wq * 2;
    const uint32_t bdst1 = sb + WSM_B1 + wm * 144 + wq * 2;

    float acc[2][8][4];
#pragma unroll
    for (int a = 0; a < 2; ++a)
#pragma unroll
        for (int b = 0; b < 8; ++b)
#pragma unroll
            for (int c = 0; c < 4; ++c) acc[a][b][c] = 0.f;

    constexpr int NCH = KW / 64;
    uint4 pc[2], pd[2];
    {
        const uint4* cp = (const uint4*)rowC;
        const uint4* dp = (const uint4*)rowD;
        pc[0] = cp[0]; pc[1] = cp[1];
        pd[0] = dp[0]; pd[1] = dp[1];
        cp16(bdst0,      rowW);
        cp16(bdst0 + 16, rowW + 8);
        cp16(bdst0 + 32, rowW + 16);
        cp16(bdst0 + 48, rowW + 24);
        cp_commit();
    }

#pragma unroll 1
    for (int ch = 0; ch < NCH; ++ch) {
        // step1: A[ch] -> Abuf[ch&1]
        {
            uint4 ao[2];
#pragma unroll
            for (int q = 0; q < 2; ++q) {
                ao[q].x = haddrelu2(pc[q].x, pd[q].x);
                ao[q].y = haddrelu2(pc[q].y, pd[q].y);
                ao[q].z = haddrelu2(pc[q].z, pd[q].z);
                ao[q].w = haddrelu2(pc[q].w, pd[q].w);
            }
            char* pa = smem + ((ch & 1) ? WSM_A1 : WSM_A0) + fm * 144 + fq * 2;
            *(uint4*)pa        = ao[0];
            *(uint4*)(pa + 16) = ao[1];
        }
        cp_wait_all();
        __syncthreads();
        // step3: next-chunk prefetch (overlaps MMA)
        if (ch + 1 < NCH) {
            const uint4* cp = (const uint4*)(rowC + (ch + 1) * 64);
            const uint4* dp = (const uint4*)(rowD + (ch + 1) * 64);
            pc[0] = cp[0]; pc[1] = cp[1];
            pd[0] = dp[0]; pd[1] = dp[1];
            const __half* ws = rowW + (ch + 1) * 64;
            uint32_t bd = ((ch + 1) & 1) ? bdst1 : bdst0;
            cp16(bd,      ws);
            cp16(bd + 16, ws + 8);
            cp16(bd + 32, ws + 16);
            cp16(bd + 48, ws + 24);
            cp_commit();
        }
        // step4: MMA from buf[ch&1]
        const char* Abuf = smem + ((ch & 1) ? WSM_A1 : WSM_A0);
        const char* Bbuf = smem + ((ch & 1) ? WSM_B1 : WSM_B0);
#pragma unroll
        for (int ks = 0; ks < 4; ++ks) {
            const int koff = ks * 32 + tig * 4;
            uint32_t a[2][4];
#pragma unroll
            for (int mt = 0; mt < 2; ++mt) {
                int r = warp_m * 32 + mt * 16 + gid;
                const char* base = Abuf + r * 144;
                a[mt][0] = *(const uint32_t*)(base + koff);
                a[mt][1] = *(const uint32_t*)(base + 8 * 144 + koff);
                a[mt][2] = *(const uint32_t*)(base + koff + 16);
                a[mt][3] = *(const uint32_t*)(base + 8 * 144 + koff + 16);
            }
#pragma unroll
            for (int j = 0; j < 8; ++j) {
                int n = warp_n * 64 + j * 8 + gid;
                const char* bb = Bbuf + n * 144;
                uint32_t b0 = *(const uint32_t*)(bb + koff);
                uint32_t b1 = *(const uint32_t*)(bb + koff + 16);
                mma_f16(acc[0][j], a[0][0], a[0][1], a[0][2], a[0][3], b0, b1);
                mma_f16(acc[1][j], a[1][0], a[1][1], a[1][2], a[1][3], b0, b1);
            }
        }
    }
    __syncthreads();   // protect stage region (overlaps A buffers)

    float* stage = (float*)(smem + SM_STG);
#pragma unroll 1
    for (int p = 0; p < 4; ++p) {
        if (warp_n == p) {
#pragma unroll
            for (int mt = 0; mt < 2; ++mt)
#pragma unroll
                for (int j = 0; j < 8; ++j) {
                    int r0 = warp_m * 32 + mt * 16 + gid;
                    int cw = j * 8 + tig * 2;
                    float* st = stage + r0 * 66 + cw;
                    st[0] = acc[mt][j][0];
                    st[1] = acc[mt][j][1];
                    st[66 * 8] = acc[mt][j][2];
                    st[66 * 8 + 1] = acc[mt][j][3];
                }
        }
        __syncthreads();
        {
            int colw = tid & 63;
            int grp = tid >> 6;
            int gcol = p * 64 + colw;
            float bias = b2[gcol];
            int prev = -1;
            float mx = 0.f;
#pragma unroll 4
            for (int r = grp * 16; r < grp * 16 + 16; ++r) {
                int d = sdst[r];
                float v = fmaxf(stage[r * 66 + colw] + bias, 0.f);
                if (d == prev) {
                    mx = fmaxf(mx, v);
                } else {
                    if (prev >= 0)
                        atomicMax((int*)&AGG[(size_t)prev * NOUT + gcol], __float_as_int(mx));
                    prev = d;
                    mx = v;
                }
            }
            atomicMax((int*)&AGG[(size_t)prev * NOUT + gcol], __float_as_int(mx));
        }
        __syncthreads();
    }
}

// ---------------- dense head ----------------
__global__ void k_head(const float* __restrict__ W3, const float* __restrict__ b3,
                       const float* __restrict__ W4, const float* __restrict__ b4,
                       float* __restrict__ out) {
    __shared__ float sh[128];
    __shared__ float red[2];
    int n = blockIdx.x;
    int t = threadIdx.x;   // 64 threads
    sh[t]      = g_H2[n * 128 + t];
    sh[t + 64] = g_H2[n * 128 + 64 + t];
    __syncthreads();
    float s = b3[t];
#pragma unroll 8
    for (int k = 0; k < 128; k++) s += sh[k] * W3[k * 64 + t];
    s = fmaxf(s, 0.f);
    float p = s * W4[t];
#pragma unroll
    for (int off = 16; off > 0; off >>= 1) p += __shfl_down_sync(0xffffffffu, p, off);
    if ((t & 31) == 0) red[t >> 5] = p;
    __syncthreads();
    if (t == 0) {
        float z = red[0] + red[1] + b4[0];
        out[n] = 1.f / (1.f + expf(-z));
    }
}

// ---------------- launch ----------------
extern "C" void kernel_launch(void* const* d_in, const int* in_sizes, int n_in,
                              void* d_out, int out_size) {
    const float* x   = (const float*)d_in[0];
    const int*   ei  = (const int*)d_in[1];
    const int*   src = ei;
    const int*   dst = ei + N_EDGES;
    const float* W1a = (const float*)d_in[2];
    const float* b1a = (const float*)d_in[3];
    const float* W2a = (const float*)d_in[4];
    const float* b2a = (const float*)d_in[5];
    const float* W1b = (const float*)d_in[6];
    const float* b1b = (const float*)d_in[7];
    const float* W2b = (const float*)d_in[8];
    const float* b2b = (const float*)d_in[9];
    const float* W3  = (const float*)d_in[10];
    const float* b3  = (const float*)d_in[11];
    const float* W4  = (const float*)d_in[12];
    const float* b4  = (const float*)d_in[13];
    float* out = (float*)d_out;

    void *pC1, *pD1, *pH1, *pC2, *pD2, *pH2, *pWT1, *pWT2, *pWTD1, *pWTD2;
    cudaGetSymbolAddress(&pC1, g_C1);
    cudaGetSymbolAddress(&pD1, g_D1);
    cudaGetSymbolAddress(&pH1, g_H1);
    cudaGetSymbolAddress(&pC2, g_C2);
    cudaGetSymbolAddress(&pD2, g_D2);
    cudaGetSymbolAddress(&pH2, g_H2);
    cudaGetSymbolAddress(&pWT1, g_WT1);
    cudaGetSymbolAddress(&pWT2, g_WT2);
    cudaGetSymbolAddress(&pWTD1, g_WTD1);
    cudaGetSymbolAddress(&pWTD2, g_WTD2);

    cudaFuncSetAttribute(k_edge_wide<512, 256>, cudaFuncAttributeMaxDynamicSharedMemorySize, WEDGE_SMEM);
    cudaFuncSetAttribute(k_edge_mma<256, 128>, cudaFuncAttributeMaxDynamicSharedMemorySize, EDGE_SMEM);
    cudaFuncSetAttribute(k_node_mma<128, 512>, cudaFuncAttributeMaxDynamicSharedMemorySize, NODE_SMEM);
    cudaFuncSetAttribute(k_node_mma<256, 256>, cudaFuncAttributeMaxDynamicSharedMemorySize, NODE_SMEM);

    // init + fused setup + scan + scatter
    k_zero<<<512, 256>>>();
    k_setup<<<(614912 + 255) / 256, 256>>>(dst, W2a, W2b, W1a, W1b);
    k_scan1<<<20, 512>>>();
    k_scan23<<<20, 512>>>();
    k_scatter<<<(N_EDGES + 255) / 256, 256>>>(src, dst);

    // layer 1
    {
        dim3 g((N_NODES + 127) / 128, 1024 / 128);
        k_node_mma<128, 512><<<g, 256, NODE_SMEM>>>(x, (const __half*)pWTD1, b1a,
                                                    (__half*)pC1, (__half*)pD1);
    }
    k_edge_wide<512, 256><<<N_EDGES / 128, 512, WEDGE_SMEM>>>(
        (const __half*)pC1, (const __half*)pD1,
        (const __half*)pWT1, b2a, (float*)pH1);

    // layer 2
    {
        dim3 g((N_NODES + 127) / 128, 512 / 128);
        k_node_mma<256, 256><<<g, 256, NODE_SMEM>>>((const float*)pH1, (const __half*)pWTD2, b1b,
                                                    (__half*)pC2, (__half*)pD2);
    }
    {
        dim3 g(N_EDGES / 128, 128 / 128);
        k_edge_mma<256, 128><<<g, 256, EDGE_SMEM>>>(
            (const __half*)pC2, (const __half*)pD2,
            (const __half*)pWT2, b2b, (float*)pH2);
    }

    // head
    k_head<<<N_NODES, 64>>>(W3, b3, W4, b4, out);
}

// round 13
// speedup vs baseline: 1.1883x; 1.0742x over previous
#include <cuda_runtime.h>
#include <cuda_fp16.h>
#include <stdint.h>
#include <math.h>

#define N_NODES 10000
#define N_EDGES 320000

// ---------------- scratch (static device allocations) ----------------
__device__ __half g_C1[N_NODES * 512];   // fp16: x@(W1top-W1bot) + b1
__device__ __half g_D1[N_NODES * 512];   // fp16: x@W1bot
__device__ float  g_H1[N_NODES * 256];
__device__ __half g_C2[N_NODES * 256];
__device__ __half g_D2[N_NODES * 256];
__device__ float  g_H2[N_NODES * 128];
__device__ int    g_hist[N_NODES + 1];
__device__ int    g_bsum[32];
__device__ int    g_cursor[N_NODES];
__device__ int    g_src_s[N_EDGES];
__device__ int    g_dst_s[N_EDGES];
__device__ __half g_WT1[256 * 512];
__device__ __half g_WT2[128 * 256];
__device__ __half g_WTD1[1024 * 128];
__device__ __half g_WTD2[512 * 256];

// ---------------- helpers ----------------
__device__ __forceinline__ uint32_t smem_u32(const void* p) {
    uint32_t a;
    asm("{ .reg .u64 t; cvta.to.shared.u64 t, %1; cvt.u32.u64 %0, t; }" : "=r"(a) : "l"(p));
    return a;
}
__device__ __forceinline__ void mma_f16(float* c,
    uint32_t a0, uint32_t a1, uint32_t a2, uint32_t a3,
    uint32_t b0, uint32_t b1) {
    asm volatile(
        "mma.sync.aligned.m16n8k16.row.col.f32.f16.f16.f32 "
        "{%0,%1,%2,%3}, {%4,%5,%6,%7}, {%8,%9}, {%0,%1,%2,%3};"
        : "+f"(c[0]), "+f"(c[1]), "+f"(c[2]), "+f"(c[3])
        : "r"(a0), "r"(a1), "r"(a2), "r"(a3), "r"(b0), "r"(b1));
}
__device__ __forceinline__ void ldsm4(uint32_t& r0, uint32_t& r1, uint32_t& r2, uint32_t& r3,
                                      uint32_t addr) {
    asm volatile("ldmatrix.sync.aligned.m8n8.x4.shared.b16 {%0,%1,%2,%3}, [%4];"
        : "=r"(r0), "=r"(r1), "=r"(r2), "=r"(r3) : "r"(addr));
}
__device__ __forceinline__ uint32_t haddrelu2(uint32_t a, uint32_t b) {
    __half2 av = *reinterpret_cast<__half2*>(&a);
    __half2 bv = *reinterpret_cast<__half2*>(&b);
    __half2 r = __hmax2(__hadd2(av, bv), __float2half2_rn(0.f));
    return *reinterpret_cast<uint32_t*>(&r);
}
__device__ __forceinline__ void cp16(uint32_t dst, const void* src) {
    asm volatile("cp.async.ca.shared.global [%0], [%1], 16;" :: "r"(dst), "l"(src) : "memory");
}
__device__ __forceinline__ void cp_commit() {
    asm volatile("cp.async.commit_group;" ::: "memory");
}
__device__ __forceinline__ void cp_wait_all() {
    asm volatile("cp.async.wait_group 0;" ::: "memory");
}

// lane offsets for LDSM fragment addressing (144B row stride tiles)
// A (m16k16 tile): row = lane&15, k-half = lane>>4
#define A_LANE_OFF(lid) ((uint32_t)(((lid) & 15) * 144 + ((lid) >> 4) * 16))
// B (two n8k16 tiles): n-octet = (lane>>4)&1, row = lane&7, k-half = (lane>>3)&1
#define B_LANE_OFF(lid) ((uint32_t)(((((lid) >> 4) & 1) * 8 + ((lid) & 7)) * 144 + (((lid) >> 3) & 1) * 16))

// ---------------- init (zero only; must precede atomics in k_setup) ----------------
__global__ void k_zero() {
    int stride = gridDim.x * blockDim.x;
    int i0 = blockIdx.x * blockDim.x + threadIdx.x;
    float4 z4 = make_float4(0.f, 0.f, 0.f, 0.f);
    for (int j = i0; j < N_NODES * 64; j += stride) ((float4*)g_H1)[j] = z4;
    for (int j = i0; j < N_NODES * 32; j += stride) ((float4*)g_H2)[j] = z4;
    for (int j = i0; j <= N_NODES;     j += stride) g_hist[j] = 0;
    for (int j = i0; j < N_NODES;      j += stride) g_cursor[j] = 0;
}

// ---------------- fused setup: histogram + all weight preps ----------------
__global__ void k_setup(const int* __restrict__ dst,
                        const float* __restrict__ W2a, const float* __restrict__ W2b,
                        const float* __restrict__ W1a, const float* __restrict__ W1b) {
    int i = blockIdx.x * blockDim.x + threadIdx.x;
    if (i < 320000) {
        atomicAdd(&g_hist[dst[i] + 1], 1);
    } else if (i < 451072) {
        int i2 = i - 320000;                 // WT1: [256,512] K-major from W2a [512,256]
        int n = i2 >> 9, k = i2 & 511;
        g_WT1[i2] = __float2half_rn(W2a[k * 256 + n]);
    } else if (i < 483840) {
        int i2 = i - 451072;                 // WT2: [128,256] from W2b [256,128]
        int n = i2 >> 8, k = i2 & 255;
        g_WT2[i2] = __float2half_rn(W2b[k * 128 + n]);
    } else if (i < 549376) {
        int i2 = i - 483840;                 // WTD1: dual [1024,128] from W1a [256,512]
        int n = i2 >> 7, k = i2 & 127;
        float top = W1a[k * 512 + n];
        float bot = W1a[(128 + k) * 512 + n];
        g_WTD1[n * 128 + k] = __float2half_rn(top - bot);
        g_WTD1[(512 + n) * 128 + k] = __float2half_rn(bot);
    } else if (i < 614912) {
        int i2 = i - 549376;                 // WTD2: dual [512,256] from W1b [512,256]
        int n = i2 >> 8, k = i2 & 255;
        float top = W1b[k * 256 + n];
        float bot = W1b[(256 + k) * 256 + n];
        g_WTD2[n * 256 + k] = __float2half_rn(top - bot);
        g_WTD2[(256 + n) * 256 + k] = __float2half_rn(bot);
    }
}

// ---------------- counting-sort scan + scatter ----------------
__global__ void k_scan1() {
    __shared__ int s[512];
    int b = blockIdx.x, t = threadIdx.x;
    int i = b * 512 + t;
    int v = (i < N_NODES + 1) ? g_hist[i] : 0;
    s[t] = v;
    __syncthreads();
    for (int off = 1; off < 512; off <<= 1) {
        int u = (t >= off) ? s[t - off] : 0;
        __syncthreads();
        s[t] += u;
        __syncthreads();
    }
    if (i < N_NODES + 1) g_hist[i] = s[t];
    if (t == 511) g_bsum[b] = s[511];
}
__global__ void k_scan23() {
    __shared__ int soff;
    int b = blockIdx.x, t = threadIdx.x;
    if (t < 32) {
        int v = (t < b) ? g_bsum[t] : 0;
#pragma unroll
        for (int off = 16; off > 0; off >>= 1)
            v += __shfl_down_sync(0xffffffffu, v, off);
        if (t == 0) soff = v;
    }
    __syncthreads();
    int i = b * 512 + t;
    if (i < N_NODES + 1) g_hist[i] += soff;
}
__global__ void k_scatter(const int* __restrict__ src, const int* __restrict__ dst) {
    int e = blockIdx.x * blockDim.x + threadIdx.x;
    if (e < N_EDGES) {
        int d = dst[e];
        int pos = g_hist[d] + atomicAdd(&g_cursor[d], 1);
        g_src_s[pos] = src[e];
        g_dst_s[pos] = d;
    }
}

// ---------------- node fp16 MMA GEMM: [C | D] = fp16(X) @ WTdual^T ----------------
#define NODE_SMEM 36864

template <int K, int NOUT>
__global__ void __launch_bounds__(256, 2) k_node_mma(
    const float* __restrict__ X, const __half* __restrict__ WT,
    const float* __restrict__ b1, __half* __restrict__ C, __half* __restrict__ D)
{
    extern __shared__ char smem[];
    const uint32_t sb = smem_u32(smem);
    const int tid = threadIdx.x;
    const int wid = tid >> 5, lid = tid & 31;
    const int warp_m = wid & 3, warp_n = wid >> 2;
    const int gid = lid >> 2, tig = lid & 3;

    const int m0 = blockIdx.x * 128;
    const int n0 = blockIdx.y * 128;

    const int fm = tid >> 1;
    const int fk = (tid & 1) * 32;
    const int gm = m0 + fm;
    const bool valid = gm < N_NODES;
    const float* rowX = X + (size_t)(valid ? gm : 0) * K + fk;
    const __half* rowW = WT + (size_t)(n0 + fm) * K + fk;

    const uint32_t aA = sb + (uint32_t)(warp_m * 32) * 144 + A_LANE_OFF(lid);
    const uint32_t aB = sb + 18432 + (uint32_t)(warp_n * 64) * 144 + B_LANE_OFF(lid);

    float acc[2][8][4];
#pragma unroll
    for (int a = 0; a < 2; ++a)
#pragma unroll
        for (int b = 0; b < 8; ++b)
#pragma unroll
            for (int c = 0; c < 4; ++c) acc[a][b][c] = 0.f;

    constexpr int NCH = K / 64;
#pragma unroll 1
    for (int ch = 0; ch < NCH; ++ch) {
        {
            const uint4* wp = (const uint4*)(rowW + ch * 64);
            uint4 w0 = wp[0], w1 = wp[1], w2 = wp[2], w3 = wp[3];
            char* pb = smem + 18432 + fm * 144 + fk * 2;
            *(uint4*)pb        = w0;
            *(uint4*)(pb + 16) = w1;
            *(uint4*)(pb + 32) = w2;
            *(uint4*)(pb + 48) = w3;
        }
        {
            char* pa = smem + fm * 144 + fk * 2;
#pragma unroll
            for (int q = 0; q < 4; ++q) {
                float4 x0 = make_float4(0.f, 0.f, 0.f, 0.f);
                float4 x1 = make_float4(0.f, 0.f, 0.f, 0.f);
                if (valid) {
                    x0 = *(const float4*)(rowX + ch * 64 + q * 8);
                    x1 = *(const float4*)(rowX + ch * 64 + q * 8 + 4);
                }
                __half2 h0 = __floats2half2_rn(x0.x, x0.y);
                __half2 h1 = __floats2half2_rn(x0.z, x0.w);
                __half2 h2 = __floats2half2_rn(x1.x, x1.y);
                __half2 h3 = __floats2half2_rn(x1.z, x1.w);
                *(uint4*)(pa + q * 16) = make_uint4(
                    *(uint32_t*)&h0, *(uint32_t*)&h1, *(uint32_t*)&h2, *(uint32_t*)&h3);
            }
        }
        __syncthreads();
#pragma unroll
        for (int ks = 0; ks < 4; ++ks) {
            uint32_t a[2][4];
            ldsm4(a[0][0], a[0][1], a[0][2], a[0][3], aA + ks * 32);
            ldsm4(a[1][0], a[1][1], a[1][2], a[1][3], aA + 16 * 144 + ks * 32);
#pragma unroll
            for (int p = 0; p < 4; ++p) {
                uint32_t b0, b1v, b2v, b3v;
                ldsm4(b0, b1v, b2v, b3v, aB + (uint32_t)(p * 16) * 144 + ks * 32);
                mma_f16(acc[0][p * 2],     a[0][0], a[0][1], a[0][2], a[0][3], b0, b1v);
                mma_f16(acc[1][p * 2],     a[1][0], a[1][1], a[1][2], a[1][3], b0, b1v);
                mma_f16(acc[0][p * 2 + 1], a[0][0], a[0][1], a[0][2], a[0][3], b2v, b3v);
                mma_f16(acc[1][p * 2 + 1], a[1][0], a[1][1], a[1][2], a[1][3], b2v, b3v);
            }
        }
        __syncthreads();
    }

    const bool isC = (n0 < NOUT);
    __half* OUT = isC ? C : D;
    const int cb = isC ? n0 : n0 - NOUT;
#pragma unroll
    for (int mt = 0; mt < 2; ++mt)
#pragma unroll
        for (int j = 0; j < 8; ++j) {
            int r = m0 + warp_m * 32 + mt * 16 + gid;
            int c = cb + warp_n * 64 + j * 8 + tig * 2;
            float bb0 = 0.f, bb1 = 0.f;
            if (isC) { bb0 = __ldg(b1 + c); bb1 = __ldg(b1 + c + 1); }
            if (r < N_NODES) {
                __half2 h = __floats2half2_rn(acc[mt][j][0] + bb0, acc[mt][j][1] + bb1);
                *(__half2*)&OUT[(size_t)r * NOUT + c] = h;
            }
            if (r + 8 < N_NODES) {
                __half2 h = __floats2half2_rn(acc[mt][j][2] + bb0, acc[mt][j][3] + bb1);
                *(__half2*)&OUT[(size_t)(r + 8) * NOUT + c] = h;
            }
        }
}

// ---------------- layer-2 edge GEMM: 256 thr, tile 128x128, A+B double-buffered ----------
#define SM_SDST 0
#define SM_SSRC 512
#define SM_A0   1024
#define SM_A1   19456
#define SM_B0   37888
#define SM_B1   56320
#define SM_STG  1024
#define EDGE_SMEM 74752

template <int KW, int NOUT>
__global__ void __launch_bounds__(256, 2) k_edge_mma(
    const __half* __restrict__ C, const __half* __restrict__ D,
    const __half* __restrict__ WT, const float* __restrict__ b2, float* __restrict__ AGG)
{
    extern __shared__ char smem[];
    const uint32_t sb = smem_u32(smem);
    const int tid = threadIdx.x;
    const int wid = tid >> 5, lid = tid & 31;
    const int warp_m = wid & 3, warp_n = wid >> 2;
    const int gid = lid >> 2, tig = lid & 3;

    int* sdst = (int*)(smem + SM_SDST);
    int* ssrc = (int*)(smem + SM_SSRC);

    const int e0 = blockIdx.x * 128;
    const int n0 = blockIdx.y * 128;
    if (tid < 128) {
        sdst[tid] = g_dst_s[e0 + tid];
        ssrc[tid] = g_src_s[e0 + tid];
    }
    __syncthreads();

    const int fm = tid >> 1;
    const int fk = (tid & 1) * 32;
    const __half* rowC = C + (size_t)sdst[fm] * KW + fk;
    const __half* rowD = D + (size_t)ssrc[fm] * KW + fk;
    const __half* rowW = WT + (size_t)(n0 + fm) * KW + fk;
    const uint32_t bdst0 = sb + SM_B0 + fm * 144 + fk * 2;
    const uint32_t bdst1 = sb + SM_B1 + fm * 144 + fk * 2;

    const uint32_t aOffA = (uint32_t)(warp_m * 32) * 144 + A_LANE_OFF(lid);
    const uint32_t aOffB = (uint32_t)(warp_n * 64) * 144 + B_LANE_OFF(lid);

    float acc[2][8][4];
#pragma unroll
    for (int a = 0; a < 2; ++a)
#pragma unroll
        for (int b = 0; b < 8; ++b)
#pragma unroll
            for (int c = 0; c < 4; ++c) acc[a][b][c] = 0.f;

    constexpr int NCH = KW / 64;
    uint4 pc[4], pd[4];
    {
        const uint4* cp = (const uint4*)rowC;
        const uint4* dp = (const uint4*)rowD;
#pragma unroll
        for (int q = 0; q < 4; ++q) { pc[q] = cp[q]; pd[q] = dp[q]; }
        cp16(bdst0,      rowW);
        cp16(bdst0 + 16, rowW + 8);
        cp16(bdst0 + 32, rowW + 16);
        cp16(bdst0 + 48, rowW + 24);
        cp_commit();
    }

#pragma unroll 1
    for (int ch = 0; ch < NCH; ++ch) {
        {
            uint4 ao[4];
#pragma unroll
            for (int q = 0; q < 4; ++q) {
                ao[q].x = haddrelu2(pc[q].x, pd[q].x);
                ao[q].y = haddrelu2(pc[q].y, pd[q].y);
                ao[q].z = haddrelu2(pc[q].z, pd[q].z);
                ao[q].w = haddrelu2(pc[q].w, pd[q].w);
            }
            char* pa = smem + ((ch & 1) ? SM_A1 : SM_A0) + fm * 144 + fk * 2;
            *(uint4*)pa        = ao[0];
            *(uint4*)(pa + 16) = ao[1];
            *(uint4*)(pa + 32) = ao[2];
            *(uint4*)(pa + 48) = ao[3];
        }
        cp_wait_all();
        __syncthreads();
        if (ch + 1 < NCH) {
            const uint4* cp = (const uint4*)(rowC + (ch + 1) * 64);
            const uint4* dp = (const uint4*)(rowD + (ch + 1) * 64);
#pragma unroll
            for (int q = 0; q < 4; ++q) { pc[q] = cp[q]; pd[q] = dp[q]; }
            const __half* ws = rowW + (ch + 1) * 64;
            uint32_t bd = ((ch + 1) & 1) ? bdst1 : bdst0;
            cp16(bd,      ws);
            cp16(bd + 16, ws + 8);
            cp16(bd + 32, ws + 16);
            cp16(bd + 48, ws + 24);
            cp_commit();
        }
        const uint32_t abase = sb + ((ch & 1) ? SM_A1 : SM_A0) + aOffA;
        const uint32_t bbase = sb + ((ch & 1) ? SM_B1 : SM_B0) + aOffB;
#pragma unroll
        for (int ks = 0; ks < 4; ++ks) {
            uint32_t a[2][4];
            ldsm4(a[0][0], a[0][1], a[0][2], a[0][3], abase + ks * 32);
            ldsm4(a[1][0], a[1][1], a[1][2], a[1][3], abase + 16 * 144 + ks * 32);
#pragma unroll
            for (int p = 0; p < 4; ++p) {
                uint32_t b0, b1v, b2v, b3v;
                ldsm4(b0, b1v, b2v, b3v, bbase + (uint32_t)(p * 16) * 144 + ks * 32);
                mma_f16(acc[0][p * 2],     a[0][0], a[0][1], a[0][2], a[0][3], b0, b1v);
                mma_f16(acc[1][p * 2],     a[1][0], a[1][1], a[1][2], a[1][3], b0, b1v);
                mma_f16(acc[0][p * 2 + 1], a[0][0], a[0][1], a[0][2], a[0][3], b2v, b3v);
                mma_f16(acc[1][p * 2 + 1], a[1][0], a[1][1], a[1][2], a[1][3], b2v, b3v);
            }
        }
    }
    __syncthreads();   // protect stage region (overlaps A buffers)

    float* stage = (float*)(smem + SM_STG);
#pragma unroll 1
    for (int p = 0; p < 2; ++p) {
        if (warp_n == p) {
#pragma unroll
            for (int mt = 0; mt < 2; ++mt)
#pragma unroll
                for (int j = 0; j < 8; ++j) {
                    int r0 = warp_m * 32 + mt * 16 + gid;
                    int cw = j * 8 + tig * 2;
                    float* st = stage + r0 * 66 + cw;
                    st[0] = acc[mt][j][0];
                    st[1] = acc[mt][j][1];
                    st[66 * 8] = acc[mt][j][2];
                    st[66 * 8 + 1] = acc[mt][j][3];
                }
        }
        __syncthreads();
        {
            int colw = tid & 63;
            int grp = tid >> 6;
            int gcol = n0 + p * 64 + colw;
            float bias = b2[gcol];
            int prev = -1;
            float mx = 0.f;
#pragma unroll 4
            for (int r = grp * 32; r < grp * 32 + 32; ++r) {
                int d = sdst[r];
                float v = fmaxf(stage[r * 66 + colw] + bias, 0.f);
                if (d == prev) {
                    mx = fmaxf(mx, v);
                } else {
                    if (prev >= 0)
                        atomicMax((int*)&AGG[(size_t)prev * NOUT + gcol], __float_as_int(mx));
                    prev = d;
                    mx = v;
                }
            }
            atomicMax((int*)&AGG[(size_t)prev * NOUT + gcol], __float_as_int(mx));
        }
        __syncthreads();
    }
}

// ---------------- layer-1 edge GEMM: 512 thr, tile 128x256, A+B double-buffered -------
#define WSM_A0 1024
#define WSM_A1 19456
#define WSM_B0 37888
#define WSM_B1 74752
#define WEDGE_SMEM 111616

template <int KW, int NOUT>
__global__ void __launch_bounds__(512, 1) k_edge_wide(
    const __half* __restrict__ C, const __half* __restrict__ D,
    const __half* __restrict__ WT, const float* __restrict__ b2, float* __restrict__ AGG)
{
    extern __shared__ char smem[];
    const uint32_t sb = smem_u32(smem);
    const int tid = threadIdx.x;
    const int wid = tid >> 5, lid = tid & 31;
    const int warp_m = wid & 3, warp_n = wid >> 2;   // 4 x 4
    const int gid = lid >> 2, tig = lid & 3;

    int* sdst = (int*)(smem + SM_SDST);
    int* ssrc = (int*)(smem + SM_SSRC);

    const int e0 = blockIdx.x * 128;
    if (tid < 128) {
        sdst[tid] = g_dst_s[e0 + tid];
        ssrc[tid] = g_src_s[e0 + tid];
    }
    __syncthreads();

    const int fm = tid >> 2;
    const int fq = (tid & 3) * 16;
    const int wm = tid >> 1;
    const int wq = (tid & 1) * 32;
    const __half* rowC = C + (size_t)sdst[fm] * KW + fq;
    const __half* rowD = D + (size_t)ssrc[fm] * KW + fq;
    const __half* rowW = WT + (size_t)wm * KW + wq;
    const uint32_t bdst0 = sb + WSM_B0 + wm * 144 + wq * 2;
    const uint32_t bdst1 = sb + WSM_B1 + wm * 144 + wq * 2;

    const uint32_t aOffA = (uint32_t)(warp_m * 32) * 144 + A_LANE_OFF(lid);
    const uint32_t aOffB = (uint32_t)(warp_n * 64) * 144 + B_LANE_OFF(lid);

    float acc[2][8][4];
#pragma unroll
    for (int a = 0; a < 2; ++a)
#pragma unroll
        for (int b = 0; b < 8; ++b)
#pragma unroll
            for (int c = 0; c < 4; ++c) acc[a][b][c] = 0.f;

    constexpr int NCH = KW / 64;
    uint4 pc[2], pd[2];
    {
        const uint4* cp = (const uint4*)rowC;
        const uint4* dp = (const uint4*)rowD;
        pc[0] = cp[0]; pc[1] = cp[1];
        pd[0] = dp[0]; pd[1] = dp[1];
        cp16(bdst0,      rowW);
        cp16(bdst0 + 16, rowW + 8);
        cp16(bdst0 + 32, rowW + 16);
        cp16(bdst0 + 48, rowW + 24);
        cp_commit();
    }

#pragma unroll 1
    for (int ch = 0; ch < NCH; ++ch) {
        {
            uint4 ao[2];
#pragma unroll
            for (int q = 0; q < 2; ++q) {
                ao[q].x = haddrelu2(pc[q].x, pd[q].x);
                ao[q].y = haddrelu2(pc[q].y, pd[q].y);
                ao[q].z = haddrelu2(pc[q].z, pd[q].z);
                ao[q].w = haddrelu2(pc[q].w, pd[q].w);
            }
            char* pa = smem + ((ch & 1) ? WSM_A1 : WSM_A0) + fm * 144 + fq * 2;
            *(uint4*)pa        = ao[0];
            *(uint4*)(pa + 16) = ao[1];
        }
        cp_wait_all();
        __syncthreads();
        if (ch + 1 < NCH) {
            const uint4* cp = (const uint4*)(rowC + (ch + 1) * 64);
            const uint4* dp = (const uint4*)(rowD + (ch + 1) * 64);
            pc[0] = cp[0]; pc[1] = cp[1];
            pd[0] = dp[0]; pd[1] = dp[1];
            const __half* ws = rowW + (ch + 1) * 64;
            uint32_t bd = ((ch + 1) & 1) ? bdst1 : bdst0;
            cp16(bd,      ws);
            cp16(bd + 16, ws + 8);
            cp16(bd + 32, ws + 16);
            cp16(bd + 48, ws + 24);
            cp_commit();
        }
        const uint32_t abase = sb + ((ch & 1) ? WSM_A1 : WSM_A0) + aOffA;
        const uint32_t bbase = sb + ((ch & 1) ? WSM_B1 : WSM_B0) + aOffB;
#pragma unroll
        for (int ks = 0; ks < 4; ++ks) {
            uint32_t a[2][4];
            ldsm4(a[0][0], a[0][1], a[0][2], a[0][3], abase + ks * 32);
            ldsm4(a[1][0], a[1][1], a[1][2], a[1][3], abase + 16 * 144 + ks * 32);
#pragma unroll
            for (int p = 0; p < 4; ++p) {
                uint32_t b0, b1v, b2v, b3v;
                ldsm4(b0, b1v, b2v, b3v, bbase + (uint32_t)(p * 16) * 144 + ks * 32);
                mma_f16(acc[0][p * 2],     a[0][0], a[0][1], a[0][2], a[0][3], b0, b1v);
                mma_f16(acc[1][p * 2],     a[1][0], a[1][1], a[1][2], a[1][3], b0, b1v);
                mma_f16(acc[0][p * 2 + 1], a[0][0], a[0][1], a[0][2], a[0][3], b2v, b3v);
                mma_f16(acc[1][p * 2 + 1], a[1][0], a[1][1], a[1][2], a[1][3], b2v, b3v);
            }
        }
    }
    __syncthreads();   // protect stage region (overlaps A buffers)

    float* stage = (float*)(smem + SM_STG);
#pragma unroll 1
    for (int p = 0; p < 4; ++p) {
        if (warp_n == p) {
#pragma unroll
            for (int mt = 0; mt < 2; ++mt)
#pragma unroll
                for (int j = 0; j < 8; ++j) {
                    int r0 = warp_m * 32 + mt * 16 + gid;
                    int cw = j * 8 + tig * 2;
                    float* st = stage + r0 * 66 + cw;
                    st[0] = acc[mt][j][0];
                    st[1] = acc[mt][j][1];
                    st[66 * 8] = acc[mt][j][2];
                    st[66 * 8 + 1] = acc[mt][j][3];
                }
        }
        __syncthreads();
        {
            int colw = tid & 63;
            int grp = tid >> 6;
            int gcol = p * 64 + colw;
            float bias = b2[gcol];
            int prev = -1;
            float mx = 0.f;
#pragma unroll 4
            for (int r = grp * 16; r < grp * 16 + 16; ++r) {
                int d = sdst[r];
                float v = fmaxf(stage[r * 66 + colw] + bias, 0.f);
                if (d == prev) {
                    mx = fmaxf(mx, v);
                } else {
                    if (prev >= 0)
                        atomicMax((int*)&AGG[(size_t)prev * NOUT + gcol], __float_as_int(mx));
                    prev = d;
                    mx = v;
                }
            }
            atomicMax((int*)&AGG[(size_t)prev * NOUT + gcol], __float_as_int(mx));
        }
        __syncthreads();
    }
}

// ---------------- dense head ----------------
__global__ void k_head(const float* __restrict__ W3, const float* __restrict__ b3,
                       const float* __restrict__ W4, const float* __restrict__ b4,
                       float* __restrict__ out) {
    __shared__ float sh[128];
    __shared__ float red[2];
    int n = blockIdx.x;
    int t = threadIdx.x;   // 64 threads
    sh[t]      = g_H2[n * 128 + t];
    sh[t + 64] = g_H2[n * 128 + 64 + t];
    __syncthreads();
    float s = b3[t];
#pragma unroll 8
    for (int k = 0; k < 128; k++) s += sh[k] * W3[k * 64 + t];
    s = fmaxf(s, 0.f);
    float p = s * W4[t];
#pragma unroll
    for (int off = 16; off > 0; off >>= 1) p += __shfl_down_sync(0xffffffffu, p, off);
    if ((t & 31) == 0) red[t >> 5] = p;
    __syncthreads();
    if (t == 0) {
        float z = red[0] + red[1] + b4[0];
        out[n] = 1.f / (1.f + expf(-z));
    }
}

// ---------------- launch ----------------
extern "C" void kernel_launch(void* const* d_in, const int* in_sizes, int n_in,
                              void* d_out, int out_size) {
    const float* x   = (const float*)d_in[0];
    const int*   ei  = (const int*)d_in[1];
    const int*   src = ei;
    const int*   dst = ei + N_EDGES;
    const float* W1a = (const float*)d_in[2];
    const float* b1a = (const float*)d_in[3];
    const float* W2a = (const float*)d_in[4];
    const float* b2a = (const float*)d_in[5];
    const float* W1b = (const float*)d_in[6];
    const float* b1b = (const float*)d_in[7];
    const float* W2b = (const float*)d_in[8];
    const float* b2b = (const float*)d_in[9];
    const float* W3  = (const float*)d_in[10];
    const float* b3  = (const float*)d_in[11];
    const float* W4  = (const float*)d_in[12];
    const float* b4  = (const float*)d_in[13];
    float* out = (float*)d_out;

    void *pC1, *pD1, *pH1, *pC2, *pD2, *pH2, *pWT1, *pWT2, *pWTD1, *pWTD2;
    cudaGetSymbolAddress(&pC1, g_C1);
    cudaGetSymbolAddress(&pD1, g_D1);
    cudaGetSymbolAddress(&pH1, g_H1);
    cudaGetSymbolAddress(&pC2, g_C2);
    cudaGetSymbolAddress(&pD2, g_D2);
    cudaGetSymbolAddress(&pH2, g_H2);
    cudaGetSymbolAddress(&pWT1, g_WT1);
    cudaGetSymbolAddress(&pWT2, g_WT2);
    cudaGetSymbolAddress(&pWTD1, g_WTD1);
    cudaGetSymbolAddress(&pWTD2, g_WTD2);

    cudaFuncSetAttribute(k_edge_wide<512, 256>, cudaFuncAttributeMaxDynamicSharedMemorySize, WEDGE_SMEM);
    cudaFuncSetAttribute(k_edge_mma<256, 128>, cudaFuncAttributeMaxDynamicSharedMemorySize, EDGE_SMEM);
    cudaFuncSetAttribute(k_node_mma<128, 512>, cudaFuncAttributeMaxDynamicSharedMemorySize, NODE_SMEM);
    cudaFuncSetAttribute(k_node_mma<256, 256>, cudaFuncAttributeMaxDynamicSharedMemorySize, NODE_SMEM);

    // init + fused setup + scan + scatter
    k_zero<<<512, 256>>>();
    k_setup<<<(614912 + 255) / 256, 256>>>(dst, W2a, W2b, W1a, W1b);
    k_scan1<<<20, 512>>>();
    k_scan23<<<20, 512>>>();
    k_scatter<<<(N_EDGES + 255) / 256, 256>>>(src, dst);

    // layer 1
    {
        dim3 g((N_NODES + 127) / 128, 1024 / 128);
        k_node_mma<128, 512><<<g, 256, NODE_SMEM>>>(x, (const __half*)pWTD1, b1a,
                                                    (__half*)pC1, (__half*)pD1);
    }
    k_edge_wide<512, 256><<<N_EDGES / 128, 512, WEDGE_SMEM>>>(
        (const __half*)pC1, (const __half*)pD1,
        (const __half*)pWT1, b2a, (float*)pH1);

    // layer 2
    {
        dim3 g((N_NODES + 127) / 128, 512 / 128);
        k_node_mma<256, 256><<<g, 256, NODE_SMEM>>>((const float*)pH1, (const __half*)pWTD2, b1b,
                                                    (__half*)pC2, (__half*)pD2);
    }
    {
        dim3 g(N_EDGES / 128, 128 / 128);
        k_edge_mma<256, 128><<<g, 256, EDGE_SMEM>>>(
            (const __half*)pC2, (const __half*)pD2,
            (const __half*)pWT2, b2b, (float*)pH2);
    }

    // head
    k_head<<<N_NODES, 64>>>(W3, b3, W4, b4, out);
}

// round 14
// speedup vs baseline: 1.2190x; 1.0258x over previous
#include <cuda_runtime.h>
#include <cuda_fp16.h>
#include <stdint.h>
#include <math.h>

#define N_NODES 10000
#define N_EDGES 320000

// ---------------- scratch (static device allocations) ----------------
__device__ __half g_C1[N_NODES * 512];   // fp16: x@(W1top-W1bot) + b1
__device__ __half g_D1[N_NODES * 512];   // fp16: x@W1bot
__device__ float  g_H1[N_NODES * 256];
__device__ __half g_C2[N_NODES * 256];
__device__ __half g_D2[N_NODES * 256];
__device__ float  g_H2[N_NODES * 128];
__device__ int    g_hist[N_NODES + 1];
__device__ int    g_bsum[32];
__device__ int    g_cursor[N_NODES];
__device__ int    g_src_s[N_EDGES];
__device__ int    g_dst_s[N_EDGES];
__device__ __half g_WT1[256 * 512];
__device__ __half g_WT2[128 * 256];
__device__ __half g_WTD1[1024 * 128];
__device__ __half g_WTD2[512 * 256];

// ---------------- helpers ----------------
__device__ __forceinline__ uint32_t smem_u32(const void* p) {
    uint32_t a;
    asm("{ .reg .u64 t; cvta.to.shared.u64 t, %1; cvt.u32.u64 %0, t; }" : "=r"(a) : "l"(p));
    return a;
}
__device__ __forceinline__ void mma_f16(float* c,
    uint32_t a0, uint32_t a1, uint32_t a2, uint32_t a3,
    uint32_t b0, uint32_t b1) {
    asm volatile(
        "mma.sync.aligned.m16n8k16.row.col.f32.f16.f16.f32 "
        "{%0,%1,%2,%3}, {%4,%5,%6,%7}, {%8,%9}, {%0,%1,%2,%3};"
        : "+f"(c[0]), "+f"(c[1]), "+f"(c[2]), "+f"(c[3])
        : "r"(a0), "r"(a1), "r"(a2), "r"(a3), "r"(b0), "r"(b1));
}
__device__ __forceinline__ void ldsm4(uint32_t& r0, uint32_t& r1, uint32_t& r2, uint32_t& r3,
                                      uint32_t addr) {
    asm volatile("ldmatrix.sync.aligned.m8n8.x4.shared.b16 {%0,%1,%2,%3}, [%4];"
        : "=r"(r0), "=r"(r1), "=r"(r2), "=r"(r3) : "r"(addr));
}
__device__ __forceinline__ uint32_t haddrelu2(uint32_t a, uint32_t b) {
    __half2 av = *reinterpret_cast<__half2*>(&a);
    __half2 bv = *reinterpret_cast<__half2*>(&b);
    __half2 r = __hmax2(__hadd2(av, bv), __float2half2_rn(0.f));
    return *reinterpret_cast<uint32_t*>(&r);
}
__device__ __forceinline__ void cp16(uint32_t dst, const void* src) {
    asm volatile("cp.async.ca.shared.global [%0], [%1], 16;" :: "r"(dst), "l"(src) : "memory");
}
__device__ __forceinline__ void cp_commit() {
    asm volatile("cp.async.commit_group;" ::: "memory");
}
__device__ __forceinline__ void cp_wait_all() {
    asm volatile("cp.async.wait_group 0;" ::: "memory");
}

// lane offsets for LDSM fragment addressing (144B row stride tiles)
#define A_LANE_OFF(lid) ((uint32_t)(((lid) & 15) * 144 + ((lid) >> 4) * 16))
#define B_LANE_OFF(lid) ((uint32_t)(((((lid) >> 4) & 1) * 8 + ((lid) & 7)) * 144 + (((lid) >> 3) & 1) * 16))

// ---------------- init (zero only; must precede atomics in k_setup) ----------------
__global__ void k_zero() {
    int stride = gridDim.x * blockDim.x;
    int i0 = blockIdx.x * blockDim.x + threadIdx.x;
    float4 z4 = make_float4(0.f, 0.f, 0.f, 0.f);
    for (int j = i0; j < N_NODES * 64; j += stride) ((float4*)g_H1)[j] = z4;
    for (int j = i0; j < N_NODES * 32; j += stride) ((float4*)g_H2)[j] = z4;
    for (int j = i0; j <= N_NODES;     j += stride) g_hist[j] = 0;
    for (int j = i0; j < N_NODES;      j += stride) g_cursor[j] = 0;
}

// ---------------- fused setup: histogram + all weight preps ----------------
__global__ void k_setup(const int* __restrict__ dst,
                        const float* __restrict__ W2a, const float* __restrict__ W2b,
                        const float* __restrict__ W1a, const float* __restrict__ W1b) {
    int i = blockIdx.x * blockDim.x + threadIdx.x;
    if (i < 320000) {
        atomicAdd(&g_hist[dst[i] + 1], 1);
    } else if (i < 451072) {
        int i2 = i - 320000;                 // WT1: [256,512] K-major from W2a [512,256]
        int n = i2 >> 9, k = i2 & 511;
        g_WT1[i2] = __float2half_rn(W2a[k * 256 + n]);
    } else if (i < 483840) {
        int i2 = i - 451072;                 // WT2: [128,256] from W2b [256,128]
        int n = i2 >> 8, k = i2 & 255;
        g_WT2[i2] = __float2half_rn(W2b[k * 128 + n]);
    } else if (i < 549376) {
        int i2 = i - 483840;                 // WTD1: dual [1024,128] from W1a [256,512]
        int n = i2 >> 7, k = i2 & 127;
        float top = W1a[k * 512 + n];
        float bot = W1a[(128 + k) * 512 + n];
        g_WTD1[n * 128 + k] = __float2half_rn(top - bot);
        g_WTD1[(512 + n) * 128 + k] = __float2half_rn(bot);
    } else if (i < 614912) {
        int i2 = i - 549376;                 // WTD2: dual [512,256] from W1b [512,256]
        int n = i2 >> 8, k = i2 & 255;
        float top = W1b[k * 256 + n];
        float bot = W1b[(256 + k) * 256 + n];
        g_WTD2[n * 256 + k] = __float2half_rn(top - bot);
        g_WTD2[(256 + n) * 256 + k] = __float2half_rn(bot);
    }
}

// ---------------- counting-sort scan + scatter (scan23 folded into scatter) ----------------
__global__ void k_scan1() {
    __shared__ int s[512];
    int b = blockIdx.x, t = threadIdx.x;
    int i = b * 512 + t;
    int v = (i < N_NODES + 1) ? g_hist[i] : 0;
    s[t] = v;
    __syncthreads();
    for (int off = 1; off < 512; off <<= 1) {
        int u = (t >= off) ? s[t - off] : 0;
        __syncthreads();
        s[t] += u;
        __syncthreads();
    }
    if (i < N_NODES + 1) g_hist[i] = s[t];
    if (t == 511) g_bsum[b] = s[511];
}
__global__ void k_scatter(const int* __restrict__ src, const int* __restrict__ dst) {
    __shared__ int lut[20];
    int t = threadIdx.x;
    if (t < 32) {
        int v = (t < 20) ? g_bsum[t] : 0;
        int inc = v;
#pragma unroll
        for (int off = 1; off < 32; off <<= 1) {
            int u = __shfl_up_sync(0xffffffffu, inc, off);
            if (t >= off) inc += u;
        }
        if (t < 20) lut[t] = inc - v;   // exclusive prefix
    }
    __syncthreads();
    int e = blockIdx.x * blockDim.x + t;
    if (e < N_EDGES) {
        int d = dst[e];
        int pos = g_hist[d] + lut[d >> 9] + atomicAdd(&g_cursor[d], 1);
        g_src_s[pos] = src[e];
        g_dst_s[pos] = d;
    }
}

// ---------------- node fp16 MMA GEMM: [C | D] = fp16(X) @ WTdual^T ----------------
#define NODE_SMEM 36864

template <int K, int NOUT>
__global__ void __launch_bounds__(256, 2) k_node_mma(
    const float* __restrict__ X, const __half* __restrict__ WT,
    const float* __restrict__ b1, __half* __restrict__ C, __half* __restrict__ D)
{
    extern __shared__ char smem[];
    const uint32_t sb = smem_u32(smem);
    const int tid = threadIdx.x;
    const int wid = tid >> 5, lid = tid & 31;
    const int warp_m = wid & 3, warp_n = wid >> 2;
    const int gid = lid >> 2, tig = lid & 3;

    const int m0 = blockIdx.x * 128;
    const int n0 = blockIdx.y * 128;

    const int fm = tid >> 1;
    const int fk = (tid & 1) * 32;
    const int gm = m0 + fm;
    const bool valid = gm < N_NODES;
    const float* rowX = X + (size_t)(valid ? gm : 0) * K + fk;
    const __half* rowW = WT + (size_t)(n0 + fm) * K + fk;

    const uint32_t aA = sb + (uint32_t)(warp_m * 32) * 144 + A_LANE_OFF(lid);
    const uint32_t aB = sb + 18432 + (uint32_t)(warp_n * 64) * 144 + B_LANE_OFF(lid);

    float acc[2][8][4];
#pragma unroll
    for (int a = 0; a < 2; ++a)
#pragma unroll
        for (int b = 0; b < 8; ++b)
#pragma unroll
            for (int c = 0; c < 4; ++c) acc[a][b][c] = 0.f;

    constexpr int NCH = K / 64;
#pragma unroll 1
    for (int ch = 0; ch < NCH; ++ch) {
        {
            const uint4* wp = (const uint4*)(rowW + ch * 64);
            uint4 w0 = wp[0], w1 = wp[1], w2 = wp[2], w3 = wp[3];
            char* pb = smem + 18432 + fm * 144 + fk * 2;
            *(uint4*)pb        = w0;
            *(uint4*)(pb + 16) = w1;
            *(uint4*)(pb + 32) = w2;
            *(uint4*)(pb + 48) = w3;
        }
        {
            char* pa = smem + fm * 144 + fk * 2;
#pragma unroll
            for (int q = 0; q < 4; ++q) {
                float4 x0 = make_float4(0.f, 0.f, 0.f, 0.f);
                float4 x1 = make_float4(0.f, 0.f, 0.f, 0.f);
                if (valid) {
                    x0 = *(const float4*)(rowX + ch * 64 + q * 8);
                    x1 = *(const float4*)(rowX + ch * 64 + q * 8 + 4);
                }
                __half2 h0 = __floats2half2_rn(x0.x, x0.y);
                __half2 h1 = __floats2half2_rn(x0.z, x0.w);
                __half2 h2 = __floats2half2_rn(x1.x, x1.y);
                __half2 h3 = __floats2half2_rn(x1.z, x1.w);
                *(uint4*)(pa + q * 16) = make_uint4(
                    *(uint32_t*)&h0, *(uint32_t*)&h1, *(uint32_t*)&h2, *(uint32_t*)&h3);
            }
        }
        __syncthreads();
#pragma unroll
        for (int ks = 0; ks < 4; ++ks) {
            uint32_t a[2][4];
            ldsm4(a[0][0], a[0][1], a[0][2], a[0][3], aA + ks * 32);
            ldsm4(a[1][0], a[1][1], a[1][2], a[1][3], aA + 16 * 144 + ks * 32);
#pragma unroll
            for (int p = 0; p < 4; ++p) {
                uint32_t b0, b1v, b2v, b3v;
                ldsm4(b0, b1v, b2v, b3v, aB + (uint32_t)(p * 16) * 144 + ks * 32);
                mma_f16(acc[0][p * 2],     a[0][0], a[0][1], a[0][2], a[0][3], b0, b1v);
                mma_f16(acc[1][p * 2],     a[1][0], a[1][1], a[1][2], a[1][3], b0, b1v);
                mma_f16(acc[0][p * 2 + 1], a[0][0], a[0][1], a[0][2], a[0][3], b2v, b3v);
                mma_f16(acc[1][p * 2 + 1], a[1][0], a[1][1], a[1][2], a[1][3], b2v, b3v);
            }
        }
        __syncthreads();
    }

    const bool isC = (n0 < NOUT);
    __half* OUT = isC ? C : D;
    const int cb = isC ? n0 : n0 - NOUT;
#pragma unroll
    for (int mt = 0; mt < 2; ++mt)
#pragma unroll
        for (int j = 0; j < 8; ++j) {
            int r = m0 + warp_m * 32 + mt * 16 + gid;
            int c = cb + warp_n * 64 + j * 8 + tig * 2;
            float bb0 = 0.f, bb1 = 0.f;
            if (isC) { bb0 = __ldg(b1 + c); bb1 = __ldg(b1 + c + 1); }
            if (r < N_NODES) {
                __half2 h = __floats2half2_rn(acc[mt][j][0] + bb0, acc[mt][j][1] + bb1);
                *(__half2*)&OUT[(size_t)r * NOUT + c] = h;
            }
            if (r + 8 < N_NODES) {
                __half2 h = __floats2half2_rn(acc[mt][j][2] + bb0, acc[mt][j][3] + bb1);
                *(__half2*)&OUT[(size_t)(r + 8) * NOUT + c] = h;
            }
        }
}

// ---------------- layer-2 edge GEMM: 256 thr, tile 128x128, A+B double-buffered ----------
#define SM_SDST 0
#define SM_SSRC 512
#define SM_A0   1024
#define SM_A1   19456
#define SM_B0   37888
#define SM_B1   56320
#define SM_STG  1024
#define EDGE_SMEM 74752

template <int KW, int NOUT>
__global__ void __launch_bounds__(256, 2) k_edge_mma(
    const __half* __restrict__ C, const __half* __restrict__ D,
    const __half* __restrict__ WT, const float* __restrict__ b2, float* __restrict__ AGG)
{
    extern __shared__ char smem[];
    const uint32_t sb = smem_u32(smem);
    const int tid = threadIdx.x;
    const int wid = tid >> 5, lid = tid & 31;
    const int warp_m = wid & 3, warp_n = wid >> 2;
    const int gid = lid >> 2, tig = lid & 3;

    int* sdst = (int*)(smem + SM_SDST);
    int* ssrc = (int*)(smem + SM_SSRC);

    const int e0 = blockIdx.x * 128;
    const int n0 = blockIdx.y * 128;
    if (tid < 128) {
        sdst[tid] = g_dst_s[e0 + tid];
        ssrc[tid] = g_src_s[e0 + tid];
    }
    __syncthreads();

    const int fm = tid >> 1;
    const int fk = (tid & 1) * 32;
    const __half* rowC = C + (size_t)sdst[fm] * KW + fk;
    const __half* rowD = D + (size_t)ssrc[fm] * KW + fk;
    const __half* rowW = WT + (size_t)(n0 + fm) * KW + fk;
    const uint32_t bdst0 = sb + SM_B0 + fm * 144 + fk * 2;
    const uint32_t bdst1 = sb + SM_B1 + fm * 144 + fk * 2;

    const uint32_t aOffA = (uint32_t)(warp_m * 32) * 144 + A_LANE_OFF(lid);
    const uint32_t aOffB = (uint32_t)(warp_n * 64) * 144 + B_LANE_OFF(lid);

    float acc[2][8][4];
#pragma unroll
    for (int a = 0; a < 2; ++a)
#pragma unroll
        for (int b = 0; b < 8; ++b)
#pragma unroll
            for (int c = 0; c < 4; ++c) acc[a][b][c] = 0.f;

    constexpr int NCH = KW / 64;
    uint4 pc[4], pd[4];
    {
        const uint4* cp = (const uint4*)rowC;
        const uint4* dp = (const uint4*)rowD;
#pragma unroll
        for (int q = 0; q < 4; ++q) { pc[q] = cp[q]; pd[q] = dp[q]; }
        cp16(bdst0,      rowW);
        cp16(bdst0 + 16, rowW + 8);
        cp16(bdst0 + 32, rowW + 16);
        cp16(bdst0 + 48, rowW + 24);
        cp_commit();
    }

#pragma unroll 1
    for (int ch = 0; ch < NCH; ++ch) {
        // consume prefetched gathers -> A fragments
        uint4 ao[4];
#pragma unroll
        for (int q = 0; q < 4; ++q) {
            ao[q].x = haddrelu2(pc[q].x, pd[q].x);
            ao[q].y = haddrelu2(pc[q].y, pd[q].y);
            ao[q].z = haddrelu2(pc[q].z, pd[q].z);
            ao[q].w = haddrelu2(pc[q].w, pd[q].w);
        }
        // issue next-chunk gathers EARLY (regs free, no SMEM dep)
        if (ch + 1 < NCH) {
            const uint4* cp = (const uint4*)(rowC + (ch + 1) * 64);
            const uint4* dp = (const uint4*)(rowD + (ch + 1) * 64);
#pragma unroll
            for (int q = 0; q < 4; ++q) { pc[q] = cp[q]; pd[q] = dp[q]; }
        }
        // store A tile
        {
            char* pa = smem + ((ch & 1) ? SM_A1 : SM_A0) + fm * 144 + fk * 2;
            *(uint4*)pa        = ao[0];
            *(uint4*)(pa + 16) = ao[1];
            *(uint4*)(pa + 32) = ao[2];
            *(uint4*)(pa + 48) = ao[3];
        }
        cp_wait_all();
        __syncthreads();
        // async B for next chunk (buffer freed by barrier)
        if (ch + 1 < NCH) {
            const __half* ws = rowW + (ch + 1) * 64;
            uint32_t bd = ((ch + 1) & 1) ? bdst1 : bdst0;
            cp16(bd,      ws);
            cp16(bd + 16, ws + 8);
            cp16(bd + 32, ws + 16);
            cp16(bd + 48, ws + 24);
            cp_commit();
        }
        const uint32_t abase = sb + ((ch & 1) ? SM_A1 : SM_A0) + aOffA;
        const uint32_t bbase = sb + ((ch & 1) ? SM_B1 : SM_B0) + aOffB;
#pragma unroll
        for (int ks = 0; ks < 4; ++ks) {
            uint32_t a[2][4];
            ldsm4(a[0][0], a[0][1], a[0][2], a[0][3], abase + ks * 32);
            ldsm4(a[1][0], a[1][1], a[1][2], a[1][3], abase + 16 * 144 + ks * 32);
#pragma unroll
            for (int p = 0; p < 4; ++p) {
                uint32_t b0, b1v, b2v, b3v;
                ldsm4(b0, b1v, b2v, b3v, bbase + (uint32_t)(p * 16) * 144 + ks * 32);
                mma_f16(acc[0][p * 2],     a[0][0], a[0][1], a[0][2], a[0][3], b0, b1v);
                mma_f16(acc[1][p * 2],     a[1][0], a[1][1], a[1][2], a[1][3], b0, b1v);
                mma_f16(acc[0][p * 2 + 1], a[0][0], a[0][1], a[0][2], a[0][3], b2v, b3v);
                mma_f16(acc[1][p * 2 + 1], a[1][0], a[1][1], a[1][2], a[1][3], b2v, b3v);
            }
        }
    }
    __syncthreads();   // protect stage region (overlaps A/B buffers)

    // ---- epilogue: single pass, all 128 cols staged (stride 130 floats)
    float* stage = (float*)(smem + SM_STG);
#pragma unroll
    for (int mt = 0; mt < 2; ++mt)
#pragma unroll
        for (int j = 0; j < 8; ++j) {
            int r0 = warp_m * 32 + mt * 16 + gid;
            int cw = warp_n * 64 + j * 8 + tig * 2;
            float* st = stage + r0 * 130 + cw;
            st[0] = acc[mt][j][0];
            st[1] = acc[mt][j][1];
            st[130 * 8] = acc[mt][j][2];
            st[130 * 8 + 1] = acc[mt][j][3];
        }
    __syncthreads();
    {
        int colw = tid & 127;          // 128 cols
        int grp = tid >> 7;            // 2 groups x 64 rows
        int gcol = n0 + colw;
        float bias = b2[gcol];
        int prev = -1;
        float mx = 0.f;
#pragma unroll 4
        for (int r = grp * 64; r < grp * 64 + 64; ++r) {
            int d = sdst[r];
            float v = fmaxf(stage[r * 130 + colw] + bias, 0.f);
            if (d == prev) {
                mx = fmaxf(mx, v);
            } else {
                if (prev >= 0)
                    atomicMax((int*)&AGG[(size_t)prev * NOUT + gcol], __float_as_int(mx));
                prev = d;
                mx = v;
            }
        }
        atomicMax((int*)&AGG[(size_t)prev * NOUT + gcol], __float_as_int(mx));
    }
}

// ---------------- layer-1 edge GEMM: 512 thr, tile 128x256, A+B double-buffered -------
#define WSM_A0 1024
#define WSM_A1 19456
#define WSM_B0 37888
#define WSM_B1 74752
#define WEDGE_SMEM 111616

template <int KW, int NOUT>
__global__ void __launch_bounds__(512, 1) k_edge_wide(
    const __half* __restrict__ C, const __half* __restrict__ D,
    const __half* __restrict__ WT, const float* __restrict__ b2, float* __restrict__ AGG)
{
    extern __shared__ char smem[];
    const uint32_t sb = smem_u32(smem);
    const int tid = threadIdx.x;
    const int wid = tid >> 5, lid = tid & 31;
    const int warp_m = wid & 3, warp_n = wid >> 2;   // 4 x 4
    const int gid = lid >> 2, tig = lid & 3;

    int* sdst = (int*)(smem + SM_SDST);
    int* ssrc = (int*)(smem + SM_SSRC);

    const int e0 = blockIdx.x * 128;
    if (tid < 128) {
        sdst[tid] = g_dst_s[e0 + tid];
        ssrc[tid] = g_src_s[e0 + tid];
    }
    __syncthreads();

    const int fm = tid >> 2;
    const int fq = (tid & 3) * 16;
    const int wm = tid >> 1;
    const int wq = (tid & 1) * 32;
    const __half* rowC = C + (size_t)sdst[fm] * KW + fq;
    const __half* rowD = D + (size_t)ssrc[fm] * KW + fq;
    const __half* rowW = WT + (size_t)wm * KW + wq;
    const uint32_t bdst0 = sb + WSM_B0 + wm * 144 + wq * 2;
    const uint32_t bdst1 = sb + WSM_B1 + wm * 144 + wq * 2;

    const uint32_t aOffA = (uint32_t)(warp_m * 32) * 144 + A_LANE_OFF(lid);
    const uint32_t aOffB = (uint32_t)(warp_n * 64) * 144 + B_LANE_OFF(lid);

    float acc[2][8][4];
#pragma unroll
    for (int a = 0; a < 2; ++a)
#pragma unroll
        for (int b = 0; b < 8; ++b)
#pragma unroll
            for (int c = 0; c < 4; ++c) acc[a][b][c] = 0.f;

    constexpr int NCH = KW / 64;
    uint4 pc[2], pd[2];
    {
        const uint4* cp = (const uint4*)rowC;
        const uint4* dp = (const uint4*)rowD;
        pc[0] = cp[0]; pc[1] = cp[1];
        pd[0] = dp[0]; pd[1] = dp[1];
        cp16(bdst0,      rowW);
        cp16(bdst0 + 16, rowW + 8);
        cp16(bdst0 + 32, rowW + 16);
        cp16(bdst0 + 48, rowW + 24);
        cp_commit();
    }

#pragma unroll 1
    for (int ch = 0; ch < NCH; ++ch) {
        uint4 ao[2];
#pragma unroll
        for (int q = 0; q < 2; ++q) {
            ao[q].x = haddrelu2(pc[q].x, pd[q].x);
            ao[q].y = haddrelu2(pc[q].y, pd[q].y);
            ao[q].z = haddrelu2(pc[q].z, pd[q].z);
            ao[q].w = haddrelu2(pc[q].w, pd[q].w);
        }
        if (ch + 1 < NCH) {   // early gather issue
            const uint4* cp = (const uint4*)(rowC + (ch + 1) * 64);
            const uint4* dp = (const uint4*)(rowD + (ch + 1) * 64);
            pc[0] = cp[0]; pc[1] = cp[1];
            pd[0] = dp[0]; pd[1] = dp[1];
        }
        {
            char* pa = smem + ((ch & 1) ? WSM_A1 : WSM_A0) + fm * 144 + fq * 2;
            *(uint4*)pa        = ao[0];
            *(uint4*)(pa + 16) = ao[1];
        }
        cp_wait_all();
        __syncthreads();
        if (ch + 1 < NCH) {
            const __half* ws = rowW + (ch + 1) * 64;
            uint32_t bd = ((ch + 1) & 1) ? bdst1 : bdst0;
            cp16(bd,      ws);
            cp16(bd + 16, ws + 8);
            cp16(bd + 32, ws + 16);
            cp16(bd + 48, ws + 24);
            cp_commit();
        }
        const uint32_t abase = sb + ((ch & 1) ? WSM_A1 : WSM_A0) + aOffA;
        const uint32_t bbase = sb + ((ch & 1) ? WSM_B1 : WSM_B0) + aOffB;
#pragma unroll
        for (int ks = 0; ks < 4; ++ks) {
            uint32_t a[2][4];
            ldsm4(a[0][0], a[0][1], a[0][2], a[0][3], abase + ks * 32);
            ldsm4(a[1][0], a[1][1], a[1][2], a[1][3], abase + 16 * 144 + ks * 32);
#pragma unroll
            for (int p = 0; p < 4; ++p) {
                uint32_t b0, b1v, b2v, b3v;
                ldsm4(b0, b1v, b2v, b3v, bbase + (uint32_t)(p * 16) * 144 + ks * 32);
                mma_f16(acc[0][p * 2],     a[0][0], a[0][1], a[0][2], a[0][3], b0, b1v);
                mma_f16(acc[1][p * 2],     a[1][0], a[1][1], a[1][2], a[1][3], b0, b1v);
                mma_f16(acc[0][p * 2 + 1], a[0][0], a[0][1], a[0][2], a[0][3], b2v, b3v);
                mma_f16(acc[1][p * 2 + 1], a[1][0], a[1][1], a[1][2], a[1][3], b2v, b3v);
            }
        }
    }
    __syncthreads();   // protect stage region

    // ---- epilogue: 2 passes of 128 cols (stride 130 floats)
    float* stage = (float*)(smem + SM_STG);
#pragma unroll 1
    for (int p = 0; p < 2; ++p) {
        if ((warp_n >> 1) == p) {
#pragma unroll
            for (int mt = 0; mt < 2; ++mt)
#pragma unroll
                for (int j = 0; j < 8; ++j) {
                    int r0 = warp_m * 32 + mt * 16 + gid;
                    int cw = (warp_n & 1) * 64 + j * 8 + tig * 2;
                    float* st = stage + r0 * 130 + cw;
                    st[0] = acc[mt][j][0];
                    st[1] = acc[mt][j][1];
                    st[130 * 8] = acc[mt][j][2];
                    st[130 * 8 + 1] = acc[mt][j][3];
                }
        }
        __syncthreads();
        {
            int colw = tid & 127;          // 128 cols
            int grp = tid >> 7;            // 4 groups x 32 rows
            int gcol = p * 128 + colw;
            float bias = b2[gcol];
            int prev = -1;
            float mx = 0.f;
#pragma unroll 4
            for (int r = grp * 32; r < grp * 32 + 32; ++r) {
                int d = sdst[r];
                float v = fmaxf(stage[r * 130 + colw] + bias, 0.f);
                if (d == prev) {
                    mx = fmaxf(mx, v);
                } else {
                    if (prev >= 0)
                        atomicMax((int*)&AGG[(size_t)prev * NOUT + gcol], __float_as_int(mx));
                    prev = d;
                    mx = v;
                }
            }
            atomicMax((int*)&AGG[(size_t)prev * NOUT + gcol], __float_as_int(mx));
        }
        __syncthreads();
    }
}

// ---------------- dense head ----------------
__global__ void k_head(const float* __restrict__ W3, const float* __restrict__ b3,
                       const float* __restrict__ W4, const float* __restrict__ b4,
                       float* __restrict__ out) {
    __shared__ float sh[128];
    __shared__ float red[2];
    int n = blockIdx.x;
    int t = threadIdx.x;   // 64 threads
    sh[t]      = g_H2[n * 128 + t];
    sh[t + 64] = g_H2[n * 128 + 64 + t];
    __syncthreads();
    float s = b3[t];
#pragma unroll 8
    for (int k = 0; k < 128; k++) s += sh[k] * W3[k * 64 + t];
    s = fmaxf(s, 0.f);
    float p = s * W4[t];
#pragma unroll
    for (int off = 16; off > 0; off >>= 1) p += __shfl_down_sync(0xffffffffu, p, off);
    if ((t & 31) == 0) red[t >> 5] = p;
    __syncthreads();
    if (t == 0) {
        float z = red[0] + red[1] + b4[0];
        out[n] = 1.f / (1.f + expf(-z));
    }
}

// ---------------- launch ----------------
extern "C" void kernel_launch(void* const* d_in, const int* in_sizes, int n_in,
                              void* d_out, int out_size) {
    const float* x   = (const float*)d_in[0];
    const int*   ei  = (const int*)d_in[1];
    const int*   src = ei;
    const int*   dst = ei + N_EDGES;
    const float* W1a = (const float*)d_in[2];
    const float* b1a = (const float*)d_in[3];
    const float* W2a = (const float*)d_in[4];
    const float* b2a = (const float*)d_in[5];
    const float* W1b = (const float*)d_in[6];
    const float* b1b = (const float*)d_in[7];
    const float* W2b = (const float*)d_in[8];
    const float* b2b = (const float*)d_in[9];
    const float* W3  = (const float*)d_in[10];
    const float* b3  = (const float*)d_in[11];
    const float* W4  = (const float*)d_in[12];
    const float* b4  = (const float*)d_in[13];
    float* out = (float*)d_out;

    void *pC1, *pD1, *pH1, *pC2, *pD2, *pH2, *pWT1, *pWT2, *pWTD1, *pWTD2;
    cudaGetSymbolAddress(&pC1, g_C1);
    cudaGetSymbolAddress(&pD1, g_D1);
    cudaGetSymbolAddress(&pH1, g_H1);
    cudaGetSymbolAddress(&pC2, g_C2);
    cudaGetSymbolAddress(&pD2, g_D2);
    cudaGetSymbolAddress(&pH2, g_H2);
    cudaGetSymbolAddress(&pWT1, g_WT1);
    cudaGetSymbolAddress(&pWT2, g_WT2);
    cudaGetSymbolAddress(&pWTD1, g_WTD1);
    cudaGetSymbolAddress(&pWTD2, g_WTD2);

    cudaFuncSetAttribute(k_edge_wide<512, 256>, cudaFuncAttributeMaxDynamicSharedMemorySize, WEDGE_SMEM);
    cudaFuncSetAttribute(k_edge_mma<256, 128>, cudaFuncAttributeMaxDynamicSharedMemorySize, EDGE_SMEM);
    cudaFuncSetAttribute(k_node_mma<128, 512>, cudaFuncAttributeMaxDynamicSharedMemorySize, NODE_SMEM);
    cudaFuncSetAttribute(k_node_mma<256, 256>, cudaFuncAttributeMaxDynamicSharedMemorySize, NODE_SMEM);

    // init + fused setup + scan + scatter
    k_zero<<<512, 256>>>();
    k_setup<<<(614912 + 255) / 256, 256>>>(dst, W2a, W2b, W1a, W1b);
    k_scan1<<<20, 512>>>();
    k_scatter<<<(N_EDGES + 255) / 256, 256>>>(src, dst);

    // layer 1
    {
        dim3 g((N_NODES + 127) / 128, 1024 / 128);
        k_node_mma<128, 512><<<g, 256, NODE_SMEM>>>(x, (const __half*)pWTD1, b1a,
                                                    (__half*)pC1, (__half*)pD1);
    }
    k_edge_wide<512, 256><<<N_EDGES / 128, 512, WEDGE_SMEM>>>(
        (const __half*)pC1, (const __half*)pD1,
        (const __half*)pWT1, b2a, (float*)pH1);

    // layer 2
    {
        dim3 g((N_NODES + 127) / 128, 512 / 128);
        k_node_mma<256, 256><<<g, 256, NODE_SMEM>>>((const float*)pH1, (const __half*)pWTD2, b1b,
                                                    (__half*)pC2, (__half*)pD2);
    }
    {
        dim3 g(N_EDGES / 128, 128 / 128);
        k_edge_mma<256, 128><<<g, 256, EDGE_SMEM>>>(
            (const __half*)pC2, (const __half*)pD2,
            (const __half*)pWT2, b2b, (float*)pH2);
    }

    // head
    k_head<<<N_NODES, 64>>>(W3, b3, W4, b4, out);
}

// round 15
// speedup vs baseline: 1.2395x; 1.0168x over previous
#include <cuda_runtime.h>
#include <cuda_fp16.h>
#include <stdint.h>
#include <math.h>

#define N_NODES 10000
#define N_EDGES 320000

// ---------------- scratch (static device allocations) ----------------
__device__ __half g_C1[N_NODES * 512];   // fp16: x@(W1top-W1bot) + b1
__device__ __half g_D1[N_NODES * 512];   // fp16: x@W1bot
__device__ float  g_H1[N_NODES * 256];
__device__ __half g_C2[N_NODES * 256];
__device__ __half g_D2[N_NODES * 256];
__device__ float  g_H2[N_NODES * 128];
__device__ int    g_hist[N_NODES + 1];
__device__ int    g_bsum[32];
__device__ int    g_cursor[N_NODES];
__device__ int    g_src_s[N_EDGES];
__device__ int    g_dst_s[N_EDGES];
__device__ __half g_WT1[256 * 512];
__device__ __half g_WT2[128 * 256];
__device__ __half g_WTD1[1024 * 128];
__device__ __half g_WTD2[512 * 256];

// ---------------- one-time stream/event creation (static init, pre-checkpoint) ----
struct GraphFork {
    cudaStream_t s;
    cudaEvent_t e0, e1;
    GraphFork() {
        cudaStreamCreateWithFlags(&s, cudaStreamNonBlocking);
        cudaEventCreateWithFlags(&e0, cudaEventDisableTiming);
        cudaEventCreateWithFlags(&e1, cudaEventDisableTiming);
    }
};
static GraphFork g_fork;

// ---------------- helpers ----------------
__device__ __forceinline__ uint32_t smem_u32(const void* p) {
    uint32_t a;
    asm("{ .reg .u64 t; cvta.to.shared.u64 t, %1; cvt.u32.u64 %0, t; }" : "=r"(a) : "l"(p));
    return a;
}
__device__ __forceinline__ void mma_f16(float* c,
    uint32_t a0, uint32_t a1, uint32_t a2, uint32_t a3,
    uint32_t b0, uint32_t b1) {
    asm volatile(
        "mma.sync.aligned.m16n8k16.row.col.f32.f16.f16.f32 "
        "{%0,%1,%2,%3}, {%4,%5,%6,%7}, {%8,%9}, {%0,%1,%2,%3};"
        : "+f"(c[0]), "+f"(c[1]), "+f"(c[2]), "+f"(c[3])
        : "r"(a0), "r"(a1), "r"(a2), "r"(a3), "r"(b0), "r"(b1));
}
__device__ __forceinline__ void ldsm4(uint32_t& r0, uint32_t& r1, uint32_t& r2, uint32_t& r3,
                                      uint32_t addr) {
    asm volatile("ldmatrix.sync.aligned.m8n8.x4.shared.b16 {%0,%1,%2,%3}, [%4];"
        : "=r"(r0), "=r"(r1), "=r"(r2), "=r"(r3) : "r"(addr));
}
__device__ __forceinline__ uint32_t haddrelu2(uint32_t a, uint32_t b) {
    __half2 av = *reinterpret_cast<__half2*>(&a);
    __half2 bv = *reinterpret_cast<__half2*>(&b);
    __half2 r = __hmax2(__hadd2(av, bv), __float2half2_rn(0.f));
    return *reinterpret_cast<uint32_t*>(&r);
}
__device__ __forceinline__ void cp16(uint32_t dst, const void* src) {
    asm volatile("cp.async.ca.shared.global [%0], [%1], 16;" :: "r"(dst), "l"(src) : "memory");
}
__device__ __forceinline__ void cp_commit() {
    asm volatile("cp.async.commit_group;" ::: "memory");
}
__device__ __forceinline__ void cp_wait_all() {
    asm volatile("cp.async.wait_group 0;" ::: "memory");
}

// lane offsets for LDSM fragment addressing (144B row stride tiles)
#define A_LANE_OFF(lid) ((uint32_t)(((lid) & 15) * 144 + ((lid) >> 4) * 16))
#define B_LANE_OFF(lid) ((uint32_t)(((((lid) >> 4) & 1) * 8 + ((lid) & 7)) * 144 + (((lid) >> 3) & 1) * 16))

// ---------------- init: hist/cursor/H1/H2 (branch A head) ----------------
__global__ void k_zero() {
    int stride = gridDim.x * blockDim.x;
    int i0 = blockIdx.x * blockDim.x + threadIdx.x;
    float4 z4 = make_float4(0.f, 0.f, 0.f, 0.f);
    for (int j = i0; j < N_NODES * 64; j += stride) ((float4*)g_H1)[j] = z4;
    for (int j = i0; j < N_NODES * 32; j += stride) ((float4*)g_H2)[j] = z4;
    for (int j = i0; j <= N_NODES;     j += stride) g_hist[j] = 0;
    for (int j = i0; j < N_NODES;      j += stride) g_cursor[j] = 0;
}

// ---------------- histogram (branch A) ----------------
__global__ void k_hist(const int* __restrict__ dst) {
    int e = blockIdx.x * blockDim.x + threadIdx.x;
    if (e < N_EDGES) atomicAdd(&g_hist[dst[e] + 1], 1);
}

// ---------------- weight preps (branch B) ----------------
// ranges: [0,131072) WT1 | [131072,163840) WT2 | [163840,229376) WTD1 | [229376,294912) WTD2
__global__ void k_prep(const float* __restrict__ W2a, const float* __restrict__ W2b,
                       const float* __restrict__ W1a, const float* __restrict__ W1b) {
    int i = blockIdx.x * blockDim.x + threadIdx.x;
    if (i < 131072) {
        int n = i >> 9, k = i & 511;       // WT1: [256,512] from W2a [512,256]
        g_WT1[i] = __float2half_rn(W2a[k * 256 + n]);
    } else if (i < 163840) {
        int i2 = i - 131072;               // WT2: [128,256] from W2b [256,128]
        int n = i2 >> 8, k = i2 & 255;
        g_WT2[i2] = __float2half_rn(W2b[k * 128 + n]);
    } else if (i < 229376) {
        int i2 = i - 163840;               // WTD1: dual [1024,128] from W1a [256,512]
        int n = i2 >> 7, k = i2 & 127;
        float top = W1a[k * 512 + n];
        float bot = W1a[(128 + k) * 512 + n];
        g_WTD1[n * 128 + k] = __float2half_rn(top - bot);
        g_WTD1[(512 + n) * 128 + k] = __float2half_rn(bot);
    } else if (i < 294912) {
        int i2 = i - 229376;               // WTD2: dual [512,256] from W1b [512,256]
        int n = i2 >> 8, k = i2 & 255;
        float top = W1b[k * 256 + n];
        float bot = W1b[(256 + k) * 256 + n];
        g_WTD2[n * 256 + k] = __float2half_rn(top - bot);
        g_WTD2[(256 + n) * 256 + k] = __float2half_rn(bot);
    }
}

// ---------------- counting-sort scan + scatter (branch A) ----------------
__global__ void k_scan1() {
    __shared__ int s[512];
    int b = blockIdx.x, t = threadIdx.x;
    int i = b * 512 + t;
    int v = (i < N_NODES + 1) ? g_hist[i] : 0;
    s[t] = v;
    __syncthreads();
    for (int off = 1; off < 512; off <<= 1) {
        int u = (t >= off) ? s[t - off] : 0;
        __syncthreads();
        s[t] += u;
        __syncthreads();
    }
    if (i < N_NODES + 1) g_hist[i] = s[t];
    if (t == 511) g_bsum[b] = s[511];
}
__global__ void k_scatter(const int* __restrict__ src, const int* __restrict__ dst) {
    __shared__ int lut[20];
    int t = threadIdx.x;
    if (t < 32) {
        int v = (t < 20) ? g_bsum[t] : 0;
        int inc = v;
#pragma unroll
        for (int off = 1; off < 32; off <<= 1) {
            int u = __shfl_up_sync(0xffffffffu, inc, off);
            if (t >= off) inc += u;
        }
        if (t < 20) lut[t] = inc - v;   // exclusive prefix
    }
    __syncthreads();
    int e = blockIdx.x * blockDim.x + t;
    if (e < N_EDGES) {
        int d = dst[e];
        int pos = g_hist[d] + lut[d >> 9] + atomicAdd(&g_cursor[d], 1);
        g_src_s[pos] = src[e];
        g_dst_s[pos] = d;
    }
}

// ---------------- node fp16 MMA GEMM: [C | D] = fp16(X) @ WTdual^T ----------------
#define NODE_SMEM 36864

template <int K, int NOUT>
__global__ void __launch_bounds__(256, 2) k_node_mma(
    const float* __restrict__ X, const __half* __restrict__ WT,
    const float* __restrict__ b1, __half* __restrict__ C, __half* __restrict__ D)
{
    extern __shared__ char smem[];
    const uint32_t sb = smem_u32(smem);
    const int tid = threadIdx.x;
    const int wid = tid >> 5, lid = tid & 31;
    const int warp_m = wid & 3, warp_n = wid >> 2;
    const int gid = lid >> 2, tig = lid & 3;

    const int m0 = blockIdx.x * 128;
    const int n0 = blockIdx.y * 128;

    const int fm = tid >> 1;
    const int fk = (tid & 1) * 32;
    const int gm = m0 + fm;
    const bool valid = gm < N_NODES;
    const float* rowX = X + (size_t)(valid ? gm : 0) * K + fk;
    const __half* rowW = WT + (size_t)(n0 + fm) * K + fk;

    const uint32_t aA = sb + (uint32_t)(warp_m * 32) * 144 + A_LANE_OFF(lid);
    const uint32_t aB = sb + 18432 + (uint32_t)(warp_n * 64) * 144 + B_LANE_OFF(lid);

    float acc[2][8][4];
#pragma unroll
    for (int a = 0; a < 2; ++a)
#pragma unroll
        for (int b = 0; b < 8; ++b)
#pragma unroll
            for (int c = 0; c < 4; ++c) acc[a][b][c] = 0.f;

    constexpr int NCH = K / 64;
#pragma unroll 1
    for (int ch = 0; ch < NCH; ++ch) {
        {
            const uint4* wp = (const uint4*)(rowW + ch * 64);
            uint4 w0 = wp[0], w1 = wp[1], w2 = wp[2], w3 = wp[3];
            char* pb = smem + 18432 + fm * 144 + fk * 2;
            *(uint4*)pb        = w0;
            *(uint4*)(pb + 16) = w1;
            *(uint4*)(pb + 32) = w2;
            *(uint4*)(pb + 48) = w3;
        }
        {
            char* pa = smem + fm * 144 + fk * 2;
#pragma unroll
            for (int q = 0; q < 4; ++q) {
                float4 x0 = make_float4(0.f, 0.f, 0.f, 0.f);
                float4 x1 = make_float4(0.f, 0.f, 0.f, 0.f);
                if (valid) {
                    x0 = *(const float4*)(rowX + ch * 64 + q * 8);
                    x1 = *(const float4*)(rowX + ch * 64 + q * 8 + 4);
                }
                __half2 h0 = __floats2half2_rn(x0.x, x0.y);
                __half2 h1 = __floats2half2_rn(x0.z, x0.w);
                __half2 h2 = __floats2half2_rn(x1.x, x1.y);
                __half2 h3 = __floats2half2_rn(x1.z, x1.w);
                *(uint4*)(pa + q * 16) = make_uint4(
                    *(uint32_t*)&h0, *(uint32_t*)&h1, *(uint32_t*)&h2, *(uint32_t*)&h3);
            }
        }
        __syncthreads();
#pragma unroll
        for (int ks = 0; ks < 4; ++ks) {
            uint32_t a[2][4];
            ldsm4(a[0][0], a[0][1], a[0][2], a[0][3], aA + ks * 32);
            ldsm4(a[1][0], a[1][1], a[1][2], a[1][3], aA + 16 * 144 + ks * 32);
#pragma unroll
            for (int p = 0; p < 4; ++p) {
                uint32_t b0, b1v, b2v, b3v;
                ldsm4(b0, b1v, b2v, b3v, aB + (uint32_t)(p * 16) * 144 + ks * 32);
                mma_f16(acc[0][p * 2],     a[0][0], a[0][1], a[0][2], a[0][3], b0, b1v);
                mma_f16(acc[1][p * 2],     a[1][0], a[1][1], a[1][2], a[1][3], b0, b1v);
                mma_f16(acc[0][p * 2 + 1], a[0][0], a[0][1], a[0][2], a[0][3], b2v, b3v);
                mma_f16(acc[1][p * 2 + 1], a[1][0], a[1][1], a[1][2], a[1][3], b2v, b3v);
            }
        }
        __syncthreads();
    }

    const bool isC = (n0 < NOUT);
    __half* OUT = isC ? C : D;
    const int cb = isC ? n0 : n0 - NOUT;
#pragma unroll
    for (int mt = 0; mt < 2; ++mt)
#pragma unroll
        for (int j = 0; j < 8; ++j) {
            int r = m0 + warp_m * 32 + mt * 16 + gid;
            int c = cb + warp_n * 64 + j * 8 + tig * 2;
            float bb0 = 0.f, bb1 = 0.f;
            if (isC) { bb0 = __ldg(b1 + c); bb1 = __ldg(b1 + c + 1); }
            if (r < N_NODES) {
                __half2 h = __floats2half2_rn(acc[mt][j][0] + bb0, acc[mt][j][1] + bb1);
                *(__half2*)&OUT[(size_t)r * NOUT + c] = h;
            }
            if (r + 8 < N_NODES) {
                __half2 h = __floats2half2_rn(acc[mt][j][2] + bb0, acc[mt][j][3] + bb1);
                *(__half2*)&OUT[(size_t)(r + 8) * NOUT + c] = h;
            }
        }
}

// ---------------- layer-2 edge GEMM: 256 thr, tile 128x128, A+B double-buffered ----------
#define SM_SDST 0
#define SM_SSRC 512
#define SM_A0   1024
#define SM_A1   19456
#define SM_B0   37888
#define SM_B1   56320
#define SM_STG  1024
#define EDGE_SMEM 74752

template <int KW, int NOUT>
__global__ void __launch_bounds__(256, 2) k_edge_mma(
    const __half* __restrict__ C, const __half* __restrict__ D,
    const __half* __restrict__ WT, const float* __restrict__ b2, float* __restrict__ AGG)
{
    extern __shared__ char smem[];
    const uint32_t sb = smem_u32(smem);
    const int tid = threadIdx.x;
    const int wid = tid >> 5, lid = tid & 31;
    const int warp_m = wid & 3, warp_n = wid >> 2;
    const int gid = lid >> 2, tig = lid & 3;

    int* sdst = (int*)(smem + SM_SDST);
    int* ssrc = (int*)(smem + SM_SSRC);

    const int e0 = blockIdx.x * 128;
    const int n0 = blockIdx.y * 128;
    if (tid < 128) {
        sdst[tid] = g_dst_s[e0 + tid];
        ssrc[tid] = g_src_s[e0 + tid];
    }
    __syncthreads();

    const int fm = tid >> 1;
    const int fk = (tid & 1) * 32;
    const __half* rowC = C + (size_t)sdst[fm] * KW + fk;
    const __half* rowD = D + (size_t)ssrc[fm] * KW + fk;
    const __half* rowW = WT + (size_t)(n0 + fm) * KW + fk;
    const uint32_t bdst0 = sb + SM_B0 + fm * 144 + fk * 2;
    const uint32_t bdst1 = sb + SM_B1 + fm * 144 + fk * 2;

    const uint32_t aOffA = (uint32_t)(warp_m * 32) * 144 + A_LANE_OFF(lid);
    const uint32_t aOffB = (uint32_t)(warp_n * 64) * 144 + B_LANE_OFF(lid);

    float acc[2][8][4];
#pragma unroll
    for (int a = 0; a < 2; ++a)
#pragma unroll
        for (int b = 0; b < 8; ++b)
#pragma unroll
            for (int c = 0; c < 4; ++c) acc[a][b][c] = 0.f;

    constexpr int NCH = KW / 64;
    uint4 pc[4], pd[4];
    {
        const uint4* cp = (const uint4*)rowC;
        const uint4* dp = (const uint4*)rowD;
#pragma unroll
        for (int q = 0; q < 4; ++q) { pc[q] = cp[q]; pd[q] = dp[q]; }
        cp16(bdst0,      rowW);
        cp16(bdst0 + 16, rowW + 8);
        cp16(bdst0 + 32, rowW + 16);
        cp16(bdst0 + 48, rowW + 24);
        cp_commit();
    }

#pragma unroll 1
    for (int ch = 0; ch < NCH; ++ch) {
        uint4 ao[4];
#pragma unroll
        for (int q = 0; q < 4; ++q) {
            ao[q].x = haddrelu2(pc[q].x, pd[q].x);
            ao[q].y = haddrelu2(pc[q].y, pd[q].y);
            ao[q].z = haddrelu2(pc[q].z, pd[q].z);
            ao[q].w = haddrelu2(pc[q].w, pd[q].w);
        }
        if (ch + 1 < NCH) {   // early gather issue
            const uint4* cp = (const uint4*)(rowC + (ch + 1) * 64);
            const uint4* dp = (const uint4*)(rowD + (ch + 1) * 64);
#pragma unroll
            for (int q = 0; q < 4; ++q) { pc[q] = cp[q]; pd[q] = dp[q]; }
        }
        {
            char* pa = smem + ((ch & 1) ? SM_A1 : SM_A0) + fm * 144 + fk * 2;
            *(uint4*)pa        = ao[0];
            *(uint4*)(pa + 16) = ao[1];
            *(uint4*)(pa + 32) = ao[2];
            *(uint4*)(pa + 48) = ao[3];
        }
        cp_wait_all();
        __syncthreads();
        if (ch + 1 < NCH) {
            const __half* ws = rowW + (ch + 1) * 64;
            uint32_t bd = ((ch + 1) & 1) ? bdst1 : bdst0;
            cp16(bd,      ws);
            cp16(bd + 16, ws + 8);
            cp16(bd + 32, ws + 16);
            cp16(bd + 48, ws + 24);
            cp_commit();
        }
        const uint32_t abase = sb + ((ch & 1) ? SM_A1 : SM_A0) + aOffA;
        const uint32_t bbase = sb + ((ch & 1) ? SM_B1 : SM_B0) + aOffB;
#pragma unroll
        for (int ks = 0; ks < 4; ++ks) {
            uint32_t a[2][4];
            ldsm4(a[0][0], a[0][1], a[0][2], a[0][3], abase + ks * 32);
            ldsm4(a[1][0], a[1][1], a[1][2], a[1][3], abase + 16 * 144 + ks * 32);
#pragma unroll
            for (int p = 0; p < 4; ++p) {
                uint32_t b0, b1v, b2v, b3v;
                ldsm4(b0, b1v, b2v, b3v, bbase + (uint32_t)(p * 16) * 144 + ks * 32);
                mma_f16(acc[0][p * 2],     a[0][0], a[0][1], a[0][2], a[0][3], b0, b1v);
                mma_f16(acc[1][p * 2],     a[1][0], a[1][1], a[1][2], a[1][3], b0, b1v);
                mma_f16(acc[0][p * 2 + 1], a[0][0], a[0][1], a[0][2], a[0][3], b2v, b3v);
                mma_f16(acc[1][p * 2 + 1], a[1][0], a[1][1], a[1][2], a[1][3], b2v, b3v);
            }
        }
    }
    __syncthreads();   // protect stage region (overlaps A/B buffers)

    // ---- epilogue: single pass, all 128 cols staged (stride 130 floats)
    float* stage = (float*)(smem + SM_STG);
#pragma unroll
    for (int mt = 0; mt < 2; ++mt)
#pragma unroll
        for (int j = 0; j < 8; ++j) {
            int r0 = warp_m * 32 + mt * 16 + gid;
            int cw = warp_n * 64 + j * 8 + tig * 2;
            float* st = stage + r0 * 130 + cw;
            st[0] = acc[mt][j][0];
            st[1] = acc[mt][j][1];
            st[130 * 8] = acc[mt][j][2];
            st[130 * 8 + 1] = acc[mt][j][3];
        }
    __syncthreads();
    {
        int colw = tid & 127;
        int grp = tid >> 7;
        int gcol = n0 + colw;
        float bias = b2[gcol];
        int prev = -1;
        float mx = 0.f;
#pragma unroll 4
        for (int r = grp * 64; r < grp * 64 + 64; ++r) {
            int d = sdst[r];
            float v = fmaxf(stage[r * 130 + colw] + bias, 0.f);
            if (d == prev) {
                mx = fmaxf(mx, v);
            } else {
                if (prev >= 0)
                    atomicMax((int*)&AGG[(size_t)prev * NOUT + gcol], __float_as_int(mx));
                prev = d;
                mx = v;
            }
        }
        atomicMax((int*)&AGG[(size_t)prev * NOUT + gcol], __float_as_int(mx));
    }
}

// ---------------- layer-1 edge GEMM: 512 thr, tile 128x256, A+B double-buffered -------
#define WSM_A0 1024
#define WSM_A1 19456
#define WSM_B0 37888
#define WSM_B1 74752
#define WEDGE_SMEM 111616

template <int KW, int NOUT>
__global__ void __launch_bounds__(512, 1) k_edge_wide(
    const __half* __restrict__ C, const __half* __restrict__ D,
    const __half* __restrict__ WT, const float* __restrict__ b2, float* __restrict__ AGG)
{
    extern __shared__ char smem[];
    const uint32_t sb = smem_u32(smem);
    const int tid = threadIdx.x;
    const int wid = tid >> 5, lid = tid & 31;
    const int warp_m = wid & 3, warp_n = wid >> 2;   // 4 x 4
    const int gid = lid >> 2, tig = lid & 3;

    int* sdst = (int*)(smem + SM_SDST);
    int* ssrc = (int*)(smem + SM_SSRC);

    const int e0 = blockIdx.x * 128;
    if (tid < 128) {
        sdst[tid] = g_dst_s[e0 + tid];
        ssrc[tid] = g_src_s[e0 + tid];
    }
    __syncthreads();

    const int fm = tid >> 2;
    const int fq = (tid & 3) * 16;
    const int wm = tid >> 1;
    const int wq = (tid & 1) * 32;
    const __half* rowC = C + (size_t)sdst[fm] * KW + fq;
    const __half* rowD = D + (size_t)ssrc[fm] * KW + fq;
    const __half* rowW = WT + (size_t)wm * KW + wq;
    const uint32_t bdst0 = sb + WSM_B0 + wm * 144 + wq * 2;
    const uint32_t bdst1 = sb + WSM_B1 + wm * 144 + wq * 2;

    const uint32_t aOffA = (uint32_t)(warp_m * 32) * 144 + A_LANE_OFF(lid);
    const uint32_t aOffB = (uint32_t)(warp_n * 64) * 144 + B_LANE_OFF(lid);

    float acc[2][8][4];
#pragma unroll
    for (int a = 0; a < 2; ++a)
#pragma unroll
        for (int b = 0; b < 8; ++b)
#pragma unroll
            for (int c = 0; c < 4; ++c) acc[a][b][c] = 0.f;

    constexpr int NCH = KW / 64;
    uint4 pc[2], pd[2];
    {
        const uint4* cp = (const uint4*)rowC;
        const uint4* dp = (const uint4*)rowD;
        pc[0] = cp[0]; pc[1] = cp[1];
        pd[0] = dp[0]; pd[1] = dp[1];
        cp16(bdst0,      rowW);
        cp16(bdst0 + 16, rowW + 8);
        cp16(bdst0 + 32, rowW + 16);
        cp16(bdst0 + 48, rowW + 24);
        cp_commit();
    }

#pragma unroll 1
    for (int ch = 0; ch < NCH; ++ch) {
        uint4 ao[2];
#pragma unroll
        for (int q = 0; q < 2; ++q) {
            ao[q].x = haddrelu2(pc[q].x, pd[q].x);
            ao[q].y = haddrelu2(pc[q].y, pd[q].y);
            ao[q].z = haddrelu2(pc[q].z, pd[q].z);
            ao[q].w = haddrelu2(pc[q].w, pd[q].w);
        }
        if (ch + 1 < NCH) {   // early gather issue
            const uint4* cp = (const uint4*)(rowC + (ch + 1) * 64);
            const uint4* dp = (const uint4*)(rowD + (ch + 1) * 64);
            pc[0] = cp[0]; pc[1] = cp[1];
            pd[0] = dp[0]; pd[1] = dp[1];
        }
        {
            char* pa = smem + ((ch & 1) ? WSM_A1 : WSM_A0) + fm * 144 + fq * 2;
            *(uint4*)pa        = ao[0];
            *(uint4*)(pa + 16) = ao[1];
        }
        cp_wait_all();
        __syncthreads();
        if (ch + 1 < NCH) {
            const __half* ws = rowW + (ch + 1) * 64;
            uint32_t bd = ((ch + 1) & 1) ? bdst1 : bdst0;
            cp16(bd,      ws);
            cp16(bd + 16, ws + 8);
            cp16(bd + 32, ws + 16);
            cp16(bd + 48, ws + 24);
            cp_commit();
        }
        const uint32_t abase = sb + ((ch & 1) ? WSM_A1 : WSM_A0) + aOffA;
        const uint32_t bbase = sb + ((ch & 1) ? WSM_B1 : WSM_B0) + aOffB;
#pragma unroll
        for (int ks = 0; ks < 4; ++ks) {
            uint32_t a[2][4];
            ldsm4(a[0][0], a[0][1], a[0][2], a[0][3], abase + ks * 32);
            ldsm4(a[1][0], a[1][1], a[1][2], a[1][3], abase + 16 * 144 + ks * 32);
#pragma unroll
            for (int p = 0; p < 4; ++p) {
                uint32_t b0, b1v, b2v, b3v;
                ldsm4(b0, b1v, b2v, b3v, bbase + (uint32_t)(p * 16) * 144 + ks * 32);
                mma_f16(acc[0][p * 2],     a[0][0], a[0][1], a[0][2], a[0][3], b0, b1v);
                mma_f16(acc[1][p * 2],     a[1][0], a[1][1], a[1][2], a[1][3], b0, b1v);
                mma_f16(acc[0][p * 2 + 1], a[0][0], a[0][1], a[0][2], a[0][3], b2v, b3v);
                mma_f16(acc[1][p * 2 + 1], a[1][0], a[1][1], a[1][2], a[1][3], b2v, b3v);
            }
        }
    }
    __syncthreads();   // protect stage region

    // ---- epilogue: 2 passes of 128 cols (stride 130 floats)
    float* stage = (float*)(smem + SM_STG);
#pragma unroll 1
    for (int p = 0; p < 2; ++p) {
        if ((warp_n >> 1) == p) {
#pragma unroll
            for (int mt = 0; mt < 2; ++mt)
#pragma unroll
                for (int j = 0; j < 8; ++j) {
                    int r0 = warp_m * 32 + mt * 16 + gid;
                    int cw = (warp_n & 1) * 64 + j * 8 + tig * 2;
                    float* st = stage + r0 * 130 + cw;
                    st[0] = acc[mt][j][0];
                    st[1] = acc[mt][j][1];
                    st[130 * 8] = acc[mt][j][2];
                    st[130 * 8 + 1] = acc[mt][j][3];
                }
        }
        __syncthreads();
        {
            int colw = tid & 127;
            int grp = tid >> 7;
            int gcol = p * 128 + colw;
            float bias = b2[gcol];
            int prev = -1;
            float mx = 0.f;
#pragma unroll 4
            for (int r = grp * 32; r < grp * 32 + 32; ++r) {
                int d = sdst[r];
                float v = fmaxf(stage[r * 130 + colw] + bias, 0.f);
                if (d == prev) {
                    mx = fmaxf(mx, v);
                } else {
                    if (prev >= 0)
                        atomicMax((int*)&AGG[(size_t)prev * NOUT + gcol], __float_as_int(mx));
                    prev = d;
                    mx = v;
                }
            }
            atomicMax((int*)&AGG[(size_t)prev * NOUT + gcol], __float_as_int(mx));
        }
        __syncthreads();
    }
}

// ---------------- dense head ----------------
__global__ void k_head(const float* __restrict__ W3, const float* __restrict__ b3,
                       const float* __restrict__ W4, const float* __restrict__ b4,
                       float* __restrict__ out) {
    __shared__ float sh[128];
    __shared__ float red[2];
    int n = blockIdx.x;
    int t = threadIdx.x;   // 64 threads
    sh[t]      = g_H2[n * 128 + t];
    sh[t + 64] = g_H2[n * 128 + 64 + t];
    __syncthreads();
    float s = b3[t];
#pragma unroll 8
    for (int k = 0; k < 128; k++) s += sh[k] * W3[k * 64 + t];
    s = fmaxf(s, 0.f);
    float p = s * W4[t];
#pragma unroll
    for (int off = 16; off > 0; off >>= 1) p += __shfl_down_sync(0xffffffffu, p, off);
    if ((t & 31) == 0) red[t >> 5] = p;
    __syncthreads();
    if (t == 0) {
        float z = red[0] + red[1] + b4[0];
        out[n] = 1.f / (1.f + expf(-z));
    }
}

// ---------------- launch ----------------
extern "C" void kernel_launch(void* const* d_in, const int* in_sizes, int n_in,
                              void* d_out, int out_size) {
    const float* x   = (const float*)d_in[0];
    const int*   ei  = (const int*)d_in[1];
    const int*   src = ei;
    const int*   dst = ei + N_EDGES;
    const float* W1a = (const float*)d_in[2];
    const float* b1a = (const float*)d_in[3];
    const float* W2a = (const float*)d_in[4];
    const float* b2a = (const float*)d_in[5];
    const float* W1b = (const float*)d_in[6];
    const float* b1b = (const float*)d_in[7];
    const float* W2b = (const float*)d_in[8];
    const float* b2b = (const float*)d_in[9];
    const float* W3  = (const float*)d_in[10];
    const float* b3  = (const float*)d_in[11];
    const float* W4  = (const float*)d_in[12];
    const float* b4  = (const float*)d_in[13];
    float* out = (float*)d_out;

    void *pC1, *pD1, *pH1, *pC2, *pD2, *pH2, *pWT1, *pWT2, *pWTD1, *pWTD2;
    cudaGetSymbolAddress(&pC1, g_C1);
    cudaGetSymbolAddress(&pD1, g_D1);
    cudaGetSymbolAddress(&pH1, g_H1);
    cudaGetSymbolAddress(&pC2, g_C2);
    cudaGetSymbolAddress(&pD2, g_D2);
    cudaGetSymbolAddress(&pH2, g_H2);
    cudaGetSymbolAddress(&pWT1, g_WT1);
    cudaGetSymbolAddress(&pWT2, g_WT2);
    cudaGetSymbolAddress(&pWTD1, g_WTD1);
    cudaGetSymbolAddress(&pWTD2, g_WTD2);

    cudaFuncSetAttribute(k_edge_wide<512, 256>, cudaFuncAttributeMaxDynamicSharedMemorySize, WEDGE_SMEM);
    cudaFuncSetAttribute(k_edge_mma<256, 128>, cudaFuncAttributeMaxDynamicSharedMemorySize, EDGE_SMEM);
    cudaFuncSetAttribute(k_node_mma<128, 512>, cudaFuncAttributeMaxDynamicSharedMemorySize, NODE_SMEM);
    cudaFuncSetAttribute(k_node_mma<256, 256>, cudaFuncAttributeMaxDynamicSharedMemorySize, NODE_SMEM);

    // ---- fork: branch A (sort chain) on side stream, branch B (weights+node L1) on main
    cudaEventRecord(g_fork.e0, 0);
    cudaStreamWaitEvent(g_fork.s, g_fork.e0, 0);

    // branch A: zero + histogram + scan + scatter
    k_zero<<<512, 256, 0, g_fork.s>>>();
    k_hist<<<(N_EDGES + 255) / 256, 256, 0, g_fork.s>>>(dst);
    k_scan1<<<20, 512, 0, g_fork.s>>>();
    k_scatter<<<(N_EDGES + 255) / 256, 256, 0, g_fork.s>>>(src, dst);
    cudaEventRecord(g_fork.e1, g_fork.s);

    // branch B: weight prep + node GEMM layer 1
    k_prep<<<(294912 + 255) / 256, 256>>>(W2a, W2b, W1a, W1b);
    {
        dim3 g((N_NODES + 127) / 128, 1024 / 128);
        k_node_mma<128, 512><<<g, 256, NODE_SMEM>>>(x, (const __half*)pWTD1, b1a,
                                                    (__half*)pC1, (__half*)pD1);
    }

    // join: edge layer 1 needs both branches
    cudaStreamWaitEvent(0, g_fork.e1, 0);
    k_edge_wide<512, 256><<<N_EDGES / 128, 512, WEDGE_SMEM>>>(
        (const __half*)pC1, (const __half*)pD1,
        (const __half*)pWT1, b2a, (float*)pH1);

    // layer 2
    {
        dim3 g((N_NODES + 127) / 128, 512 / 128);
        k_node_mma<256, 256><<<g, 256, NODE_SMEM>>>((const float*)pH1, (const __half*)pWTD2, b1b,
                                                    (__half*)pC2, (__half*)pD2);
    }
    {
        dim3 g(N_EDGES / 128, 128 / 128);
        k_edge_mma<256, 128><<<g, 256, EDGE_SMEM>>>(
            (const __half*)pC2, (const __half*)pD2,
            (const __half*)pWT2, b2b, (float*)pH2);
    }

    // head
    k_head<<<N_NODES, 64>>>(W3, b3, W4, b4, out);
}